// round 3
// baseline (speedup 1.0000x reference)
#include <cuda_runtime.h>
#include <math.h>

// ---------------------------------------------------------------------------
// CLIP ViT-B/16 forward. B=32, C=3, IMG=224, P=16 -> 196 patches + cls = 197
// D=768, DEPTH=12, H=12, DH=64, MLP=3072, PROJ=512, NCLS=1000
// ---------------------------------------------------------------------------

#define BB      32
#define NTOK    197
#define NPAT    196
#define DD      768
#define DEPTH   12
#define NH      12
#define DH      64
#define MLPD    3072
#define PROJD   512
#define NCLS    1000
#define MROWS   (BB*NTOK)          // 6304
#define PROWS   (BB*NPAT)          // 6272

// scratch (device globals: allocated at module load, not in kernel_launch)
__device__ float g_x   [MROWS*DD];      // residual stream
__device__ float g_h   [MROWS*DD];      // LN output
__device__ float g_qkv [MROWS*3*DD];    // qkv
__device__ float g_o   [MROWS*DD];      // attention out / patch-embed out
__device__ float g_mlp [MROWS*MLPD];    // mlp hidden
__device__ float g_pat [PROWS*DD];      // im2col patches
__device__ float g_cls [BB*DD];
__device__ float g_z   [BB*PROJD];

// ---------------------------------------------------------------------------
// im2col: gather 16x16x3 patches -> (6272, 768), k = c*256 + r*16 + col
// ---------------------------------------------------------------------------
__global__ void im2col_kernel(const float* __restrict__ x) {
    int idx = blockIdx.x * 256 + threadIdx.x;
    if (idx >= PROWS * DD) return;
    int k = idx % DD;
    int m = idx / DD;
    int b = m / NPAT, p = m % NPAT;
    int ph = p / 14, pw = p % 14;
    int c = k >> 8, r = (k >> 4) & 15, col = k & 15;
    g_pat[idx] = x[(((long)(b*3 + c)*224 + ph*16 + r)*224) + pw*16 + col];
}

// ---------------------------------------------------------------------------
// assemble tokens: y[b,0,:] = cls + pos[0]; y[b,n,:] = pe[b,n-1,:] + pos[n]
// ---------------------------------------------------------------------------
__global__ void assemble_kernel(const float* __restrict__ pe,
                                const float* __restrict__ cls_tok,
                                const float* __restrict__ pos) {
    int idx = blockIdx.x * 256 + threadIdx.x;
    if (idx >= MROWS * DD) return;
    int d = idx % DD;
    int bn = idx / DD;
    int b = bn / NTOK, n = bn % NTOK;
    float v;
    if (n == 0) v = cls_tok[d] + pos[d];
    else        v = pe[((long)b*NPAT + (n-1))*DD + d] + pos[(long)n*DD + d];
    g_h[idx] = v;
}

// ---------------------------------------------------------------------------
// LayerNorm over 768: one block per row, 256 threads * 3 elems
// ---------------------------------------------------------------------------
__global__ void ln_kernel(const float* __restrict__ in, float* __restrict__ out,
                          const float* __restrict__ gam, const float* __restrict__ bet,
                          long in_stride, long out_stride) {
    __shared__ float red[8];
    int row = blockIdx.x, tid = threadIdx.x;
    const float* xr = in + (long)row * in_stride;
    float v0 = xr[tid], v1 = xr[tid + 256], v2 = xr[tid + 512];
    float s = v0 + v1 + v2;
    #pragma unroll
    for (int o = 16; o; o >>= 1) s += __shfl_xor_sync(0xffffffffu, s, o);
    if ((tid & 31) == 0) red[tid >> 5] = s;
    __syncthreads();
    float tot = red[0]+red[1]+red[2]+red[3]+red[4]+red[5]+red[6]+red[7];
    float mean = tot * (1.0f / 768.0f);
    float d0 = v0 - mean, d1 = v1 - mean, d2 = v2 - mean;
    float q = d0*d0 + d1*d1 + d2*d2;
    __syncthreads();
    #pragma unroll
    for (int o = 16; o; o >>= 1) q += __shfl_xor_sync(0xffffffffu, q, o);
    if ((tid & 31) == 0) red[tid >> 5] = q;
    __syncthreads();
    float var = (red[0]+red[1]+red[2]+red[3]+red[4]+red[5]+red[6]+red[7]) * (1.0f/768.0f);
    float rs = rsqrtf(var + 1e-5f);
    float* orow = out + (long)row * out_stride;
    orow[tid      ] = d0 * rs * gam[tid      ] + bet[tid      ];
    orow[tid + 256] = d1 * rs * gam[tid + 256] + bet[tid + 256];
    orow[tid + 512] = d2 * rs * gam[tid + 512] + bet[tid + 512];
}

// ---------------------------------------------------------------------------
// Generic NT SGEMM: C[M,N] = A[M,K] @ W[N,K]^T (+bias) (+residual) (gelu?)
// 64x64 tile, BK=16, 256 threads, 4x4 per thread
// ---------------------------------------------------------------------------
__device__ __forceinline__ float gelu_f(float v) {
    return 0.5f * v * (1.0f + erff(v * 0.70710678118654752f));
}

template<bool GELU, bool RES>
__global__ void gemm_nt(const float* __restrict__ A, const float* __restrict__ W,
                        const float* __restrict__ bias, const float* __restrict__ Rs,
                        float* __restrict__ C, int M, int N, int K) {
    __shared__ float As[16][64];
    __shared__ float Bs[16][64];
    int tid = threadIdx.x;
    int tx = tid & 15, ty = tid >> 4;
    int m0 = blockIdx.y * 64, n0 = blockIdx.x * 64;
    int lr = tid >> 2;            // 0..63
    int lc = (tid & 3) << 2;      // 0,4,8,12
    float acc[4][4] = {};
    const float* Aptr = A + (long)(m0 + lr) * K + lc;
    const float* Wptr = W + (long)(n0 + lr) * K + lc;
    bool am = (m0 + lr) < M;
    bool wn = (n0 + lr) < N;
    for (int k0 = 0; k0 < K; k0 += 16) {
        float4 av = am ? *(const float4*)(Aptr + k0) : make_float4(0.f,0.f,0.f,0.f);
        float4 wv = wn ? *(const float4*)(Wptr + k0) : make_float4(0.f,0.f,0.f,0.f);
        As[lc+0][lr]=av.x; As[lc+1][lr]=av.y; As[lc+2][lr]=av.z; As[lc+3][lr]=av.w;
        Bs[lc+0][lr]=wv.x; Bs[lc+1][lr]=wv.y; Bs[lc+2][lr]=wv.z; Bs[lc+3][lr]=wv.w;
        __syncthreads();
        #pragma unroll
        for (int kk = 0; kk < 16; kk++) {
            float4 a = *(const float4*)(&As[kk][ty << 2]);
            float4 b = *(const float4*)(&Bs[kk][tx << 2]);
            acc[0][0] += a.x*b.x; acc[0][1] += a.x*b.y; acc[0][2] += a.x*b.z; acc[0][3] += a.x*b.w;
            acc[1][0] += a.y*b.x; acc[1][1] += a.y*b.y; acc[1][2] += a.y*b.z; acc[1][3] += a.y*b.w;
            acc[2][0] += a.z*b.x; acc[2][1] += a.z*b.y; acc[2][2] += a.z*b.z; acc[2][3] += a.z*b.w;
            acc[3][0] += a.w*b.x; acc[3][1] += a.w*b.y; acc[3][2] += a.w*b.z; acc[3][3] += a.w*b.w;
        }
        __syncthreads();
    }
    #pragma unroll
    for (int i = 0; i < 4; i++) {
        int m = m0 + (ty << 2) + i;
        if (m >= M) continue;
        #pragma unroll
        for (int j = 0; j < 4; j++) {
            int n = n0 + (tx << 2) + j;
            if (n >= N) continue;
            float v = acc[i][j];
            if (bias) v += bias[n];
            if (RES)  v += Rs[(long)m * N + n];
            if (GELU) v = gelu_f(v);
            C[(long)m * N + n] = v;
        }
    }
}

// ---------------------------------------------------------------------------
// Fused attention: one block per (b, h). K/V staged in smem (pitch 65).
// qkv layout: [b, n, which*768 + h*64 + d]; out layout: [b, n, h*64 + d]
// ---------------------------------------------------------------------------
#define ATTN_SMEM ((197*65*2 + 64 + 256 + 256 + 16) * 4)

__global__ void attn_kernel(const float* __restrict__ qkv, float* __restrict__ out) {
    int b = blockIdx.x / NH, h = blockIdx.x % NH;
    int tid = threadIdx.x;
    int lane = tid & 31, warp = tid >> 5;
    extern __shared__ float sm[];
    float* Ks  = sm;                 // 197*65
    float* Vs  = Ks + 197*65;        // 197*65
    float* qs  = Vs + 197*65;        // 64
    float* ss  = qs + 64;            // 256
    float* pv  = ss + 256;           // 256
    float* red = pv + 256;           // 16

    const float* base = qkv + (long)b * NTOK * (3*DD) + h * DH;
    for (int idx = tid; idx < NTOK * DH; idx += 256) {
        int j = idx >> 6, d = idx & 63;
        Ks[j*65 + d] = base[(long)j*(3*DD) + DD   + d];
        Vs[j*65 + d] = base[(long)j*(3*DD) + 2*DD + d];
    }
    __syncthreads();

    for (int i = 0; i < NTOK; i++) {
        if (tid < DH) qs[tid] = base[(long)i*(3*DD) + tid];
        __syncthreads();

        float s = -1e30f;
        if (tid < NTOK) {
            float acc = 0.f;
            #pragma unroll 16
            for (int d = 0; d < DH; d++) acc += qs[d] * Ks[tid*65 + d];
            s = acc * 0.125f;   // 1/sqrt(64)
        }
        float mx = s;
        #pragma unroll
        for (int o = 16; o; o >>= 1) mx = fmaxf(mx, __shfl_xor_sync(0xffffffffu, mx, o));
        if (lane == 0) red[warp] = mx;
        __syncthreads();
        float rowmax = red[0];
        #pragma unroll
        for (int w = 1; w < 8; w++) rowmax = fmaxf(rowmax, red[w]);

        float p = (tid < NTOK) ? expf(s - rowmax) : 0.f;
        ss[tid] = p;
        float sum = p;
        #pragma unroll
        for (int o = 16; o; o >>= 1) sum += __shfl_xor_sync(0xffffffffu, sum, o);
        if (lane == 0) red[8 + warp] = sum;
        __syncthreads();
        float tot = red[8];
        #pragma unroll
        for (int w = 1; w < 8; w++) tot += red[8 + w];
        float inv = 1.0f / tot;

        int d = tid & 63, jg = tid >> 6;
        float acc = 0.f;
        for (int j = jg; j < NTOK; j += 4) acc += ss[j] * Vs[j*65 + d];
        pv[tid] = acc;
        __syncthreads();
        if (tid < DH) {
            float ov = (pv[tid] + pv[tid+64] + pv[tid+128] + pv[tid+192]) * inv;
            out[((long)b*NTOK + i)*DD + h*DH + tid] = ov;
        }
        __syncthreads();   // protect qs/ss/pv/red for next iteration
    }
}

// ---------------------------------------------------------------------------
// host orchestration
// ---------------------------------------------------------------------------
extern "C" void kernel_launch(void* const* d_in, const int* in_sizes, int n_in,
                              void* d_out, int out_size) {
    const float* x_in    = (const float*)d_in[0];
    const float* conv_w  = (const float*)d_in[1];
    const float* cls_tok = (const float*)d_in[2];
    const float* pos     = (const float*)d_in[3];
    const float* lnprew  = (const float*)d_in[4];
    const float* lnpreb  = (const float*)d_in[5];
    const float* ln1w    = (const float*)d_in[6];
    const float* ln1b    = (const float*)d_in[7];
    const float* qkvw    = (const float*)d_in[8];
    const float* qkvb    = (const float*)d_in[9];
    const float* pw      = (const float*)d_in[10];
    const float* pb      = (const float*)d_in[11];
    const float* ln2w    = (const float*)d_in[12];
    const float* ln2b    = (const float*)d_in[13];
    const float* fw      = (const float*)d_in[14];
    const float* fb      = (const float*)d_in[15];
    const float* cw      = (const float*)d_in[16];
    const float* cb      = (const float*)d_in[17];
    const float* lnpostw = (const float*)d_in[18];
    const float* lnpostb = (const float*)d_in[19];
    const float* projw   = (const float*)d_in[20];
    const float* headw   = (const float*)d_in[21];
    const float* headb   = (const float*)d_in[22];

    float *gx, *gh, *gq, *go, *gm, *gp, *gc, *gz;
    cudaGetSymbolAddress((void**)&gx, g_x);
    cudaGetSymbolAddress((void**)&gh, g_h);
    cudaGetSymbolAddress((void**)&gq, g_qkv);
    cudaGetSymbolAddress((void**)&go, g_o);
    cudaGetSymbolAddress((void**)&gm, g_mlp);
    cudaGetSymbolAddress((void**)&gp, g_pat);
    cudaGetSymbolAddress((void**)&gc, g_cls);
    cudaGetSymbolAddress((void**)&gz, g_z);

    cudaFuncSetAttribute(attn_kernel, cudaFuncAttributeMaxDynamicSharedMemorySize, ATTN_SMEM);

    // patch embed
    im2col_kernel<<<(PROWS*DD + 255)/256, 256>>>(x_in);
    gemm_nt<false,false><<<dim3(DD/64, (PROWS+63)/64), 256>>>(gp, conv_w, nullptr, nullptr, go, PROWS, DD, DD);
    assemble_kernel<<<(MROWS*DD + 255)/256, 256>>>(go, cls_tok, pos);
    ln_kernel<<<MROWS, 256>>>(gh, gx, lnprew, lnpreb, DD, DD);

    dim3 gM((6304+63)/64);  // 99
    for (int l = 0; l < DEPTH; l++) {
        // attention sub-block
        ln_kernel<<<MROWS, 256>>>(gx, gh, ln1w + l*DD, ln1b + l*DD, DD, DD);
        gemm_nt<false,false><<<dim3((3*DD)/64, gM.x), 256>>>(
            gh, qkvw + (long)l*3*DD*DD, qkvb + (long)l*3*DD, nullptr, gq, MROWS, 3*DD, DD);
        attn_kernel<<<BB*NH, 256, ATTN_SMEM>>>(gq, go);
        gemm_nt<false,true><<<dim3(DD/64, gM.x), 256>>>(
            go, pw + (long)l*DD*DD, pb + (long)l*DD, gx, gx, MROWS, DD, DD);
        // MLP sub-block
        ln_kernel<<<MROWS, 256>>>(gx, gh, ln2w + l*DD, ln2b + l*DD, DD, DD);
        gemm_nt<true,false><<<dim3(MLPD/64, gM.x), 256>>>(
            gh, fw + (long)l*MLPD*DD, fb + (long)l*MLPD, nullptr, gm, MROWS, MLPD, DD);
        gemm_nt<false,true><<<dim3(DD/64, gM.x), 256>>>(
            gm, cw + (long)l*DD*MLPD, cb + (long)l*DD, gx, gx, MROWS, DD, MLPD);
    }

    // head: ln_post on cls rows only, then proj, then classifier
    ln_kernel<<<BB, 256>>>(gx, gc, lnpostw, lnpostb, (long)NTOK*DD, DD);
    gemm_nt<false,false><<<dim3(PROJD/64, 1), 256>>>(gc, projw, nullptr, nullptr, gz, BB, PROJD, DD);
    gemm_nt<false,false><<<dim3((NCLS+63)/64, 1), 256>>>(gz, headw, headb, nullptr, (float*)d_out, BB, NCLS, PROJD);
}

// round 4
// speedup vs baseline: 2.2273x; 2.2273x over previous
#include <cuda_runtime.h>
#include <math.h>
#include <stdint.h>

// ---------------------------------------------------------------------------
// CLIP ViT-B/16 forward. B=32, C=3, IMG=224, P=16 -> 196 patches + cls = 197
// D=768, DEPTH=12, H=12, DH=64, MLP=3072, PROJ=512, NCLS=1000
// Round 3: TF32 tensor-core GEMM (m16n8k8 mma.sync) for all big GEMMs.
// ---------------------------------------------------------------------------

#define BB      32
#define NTOK    197
#define NPAT    196
#define DD      768
#define DEPTH   12
#define NH      12
#define DH      64
#define MLPD    3072
#define PROJD   512
#define NCLS    1000
#define MROWS   (BB*NTOK)          // 6304
#define PROWS   (BB*NPAT)          // 6272

// scratch (device globals: allocated at module load, not in kernel_launch)
__device__ __align__(128) float g_x   [MROWS*DD];      // residual stream
__device__ __align__(128) float g_h   [MROWS*DD];      // LN output
__device__ __align__(128) float g_qkv [MROWS*3*DD];    // qkv
__device__ __align__(128) float g_o   [MROWS*DD];      // attention out / patch-embed out
__device__ __align__(128) float g_mlp [MROWS*MLPD];    // mlp hidden
__device__ __align__(128) float g_pat [PROWS*DD];      // im2col patches
__device__ __align__(128) float g_cls [BB*DD];
__device__ __align__(128) float g_z   [BB*PROJD];

// ---------------------------------------------------------------------------
// im2col: gather 16x16x3 patches -> (6272, 768), k = c*256 + r*16 + col
// ---------------------------------------------------------------------------
__global__ void im2col_kernel(const float* __restrict__ x) {
    int idx = blockIdx.x * 256 + threadIdx.x;
    if (idx >= PROWS * DD) return;
    int k = idx % DD;
    int m = idx / DD;
    int b = m / NPAT, p = m % NPAT;
    int ph = p / 14, pw = p % 14;
    int c = k >> 8, r = (k >> 4) & 15, col = k & 15;
    g_pat[idx] = x[(((long)(b*3 + c)*224 + ph*16 + r)*224) + pw*16 + col];
}

// ---------------------------------------------------------------------------
// assemble tokens: y[b,0,:] = cls + pos[0]; y[b,n,:] = pe[b,n-1,:] + pos[n]
// ---------------------------------------------------------------------------
__global__ void assemble_kernel(const float* __restrict__ pe,
                                const float* __restrict__ cls_tok,
                                const float* __restrict__ pos) {
    int idx = blockIdx.x * 256 + threadIdx.x;
    if (idx >= MROWS * DD) return;
    int d = idx % DD;
    int bn = idx / DD;
    int b = bn / NTOK, n = bn % NTOK;
    float v;
    if (n == 0) v = cls_tok[d] + pos[d];
    else        v = pe[((long)b*NPAT + (n-1))*DD + d] + pos[(long)n*DD + d];
    g_h[idx] = v;
}

// ---------------------------------------------------------------------------
// LayerNorm over 768: one block per row, 256 threads * 3 elems
// ---------------------------------------------------------------------------
__global__ void ln_kernel(const float* __restrict__ in, float* __restrict__ out,
                          const float* __restrict__ gam, const float* __restrict__ bet,
                          long in_stride, long out_stride) {
    __shared__ float red[16];
    int row = blockIdx.x, tid = threadIdx.x;
    const float* xr = in + (long)row * in_stride;
    float v0 = xr[tid], v1 = xr[tid + 256], v2 = xr[tid + 512];
    float s = v0 + v1 + v2;
    #pragma unroll
    for (int o = 16; o; o >>= 1) s += __shfl_xor_sync(0xffffffffu, s, o);
    if ((tid & 31) == 0) red[tid >> 5] = s;
    __syncthreads();
    float tot = red[0]+red[1]+red[2]+red[3]+red[4]+red[5]+red[6]+red[7];
    float mean = tot * (1.0f / 768.0f);
    float d0 = v0 - mean, d1 = v1 - mean, d2 = v2 - mean;
    float q = d0*d0 + d1*d1 + d2*d2;
    #pragma unroll
    for (int o = 16; o; o >>= 1) q += __shfl_xor_sync(0xffffffffu, q, o);
    if ((tid & 31) == 0) red[8 + (tid >> 5)] = q;
    __syncthreads();
    float var = (red[8]+red[9]+red[10]+red[11]+red[12]+red[13]+red[14]+red[15]) * (1.0f/768.0f);
    float rs = rsqrtf(var + 1e-5f);
    float* orow = out + (long)row * out_stride;
    orow[tid      ] = d0 * rs * gam[tid      ] + bet[tid      ];
    orow[tid + 256] = d1 * rs * gam[tid + 256] + bet[tid + 256];
    orow[tid + 512] = d2 * rs * gam[tid + 512] + bet[tid + 512];
}

__device__ __forceinline__ float gelu_f(float v) {
    return 0.5f * v * (1.0f + erff(v * 0.70710678118654752f));
}

// ---------------------------------------------------------------------------
// TF32 tensor-core NT GEMM: C[M,N] = A[M,K] @ W[N,K]^T (+bias)(+res)(gelu)
// 128x128 block tile, BK=32, 256 threads (8 warps, 2x4), warp tile 64x32.
// mma.sync.aligned.m16n8k8.row.col.f32.tf32.tf32.f32
// Smem layout (per operand): [buf][kgroup(4)][row(128)][8], where within a
// k-group of 8 the element k is stored at kp = 2*(k&3) + (k>>2), XOR-swizzled
// by ((row&3)<<1) ^ (kg<<1). This makes each fragment load a single LDS.64
// (k and k+4 adjacent) and staging stores conflict-free.
// Requires: K % 32 == 0, N % 128 == 0.
// ---------------------------------------------------------------------------
__device__ __forceinline__ unsigned f2tf(float f) {
    unsigned r;
    asm("cvt.rna.tf32.f32 %0, %1;" : "=r"(r) : "f"(f));
    return r;
}

#define GSM_BUFU (4*128*8)   // unsigneds per buffer per operand

template<bool GELU, bool RES>
__global__ __launch_bounds__(256, 2)
void gemm_tc(const float* __restrict__ A, const float* __restrict__ W,
             const float* __restrict__ bias, const float* __restrict__ Rs,
             float* __restrict__ Cp, int M, int N, int K) {
    extern __shared__ unsigned sm_u[];
    unsigned* As = sm_u;                 // 2 * 4096
    unsigned* Bs = sm_u + 2*GSM_BUFU;    // 2 * 4096

    const int tid  = threadIdx.x;
    const int lane = tid & 31;
    const int warp = tid >> 5;
    const int wm = warp >> 2;            // 0..1
    const int wn = warp & 3;             // 0..3
    const int lr = lane >> 2;            // 0..7
    const int lc = lane & 3;             // 0..3
    const int m0 = blockIdx.y * 128;
    const int n0 = blockIdx.x * 128;

    float acc[4][4][4];
    #pragma unroll
    for (int i=0;i<4;i++)
      #pragma unroll
      for (int j=0;j<4;j++)
        #pragma unroll
        for (int f=0;f<4;f++) acc[i][j][f]=0.f;

    const int ntiles = K >> 5;
    const int swz = (lr & 3) << 1;

    // staging row/col per iteration: linear = tid + it*256; row=linear>>3, c4=linear&7
    float4 ra[4], rb[4];
    const float4 z4 = make_float4(0.f,0.f,0.f,0.f);

    // ---- prologue: load tile 0 ----
    {
        const float* Ab = A + (long)m0 * K;
        const float* Wb = W + (long)n0 * K;
        #pragma unroll
        for (int it = 0; it < 4; it++) {
            int linear = tid + it*256;
            int row = linear >> 3, c4 = linear & 7;
            long off = (long)row * K + c4*4;
            ra[it] = (m0+row < M) ? *(const float4*)(Ab + off) : z4;
            rb[it] = (n0+row < N) ? *(const float4*)(Wb + off) : z4;
        }
        #pragma unroll
        for (int it = 0; it < 4; it++) {
            int linear = tid + it*256;
            int row = linear >> 3, c4 = linear & 7;
            int kg = c4 >> 1, d = c4 & 1;
            int msk = ((row & 3) << 1) ^ (kg << 1);
            unsigned* pA = &As[((0*4 + kg)*128 + row)*8];
            unsigned* pB = &Bs[((0*4 + kg)*128 + row)*8];
            pA[(0^msk)+d] = f2tf(ra[it].x); pA[(2^msk)+d] = f2tf(ra[it].y);
            pA[(4^msk)+d] = f2tf(ra[it].z); pA[(6^msk)+d] = f2tf(ra[it].w);
            pB[(0^msk)+d] = f2tf(rb[it].x); pB[(2^msk)+d] = f2tf(rb[it].y);
            pB[(4^msk)+d] = f2tf(rb[it].z); pB[(6^msk)+d] = f2tf(rb[it].w);
        }
    }
    __syncthreads();

    for (int kt = 0; kt < ntiles; kt++) {
        const int cur = kt & 1;
        // prefetch next tile into registers
        if (kt + 1 < ntiles) {
            const float* Ab = A + (long)m0 * K + (kt+1)*32;
            const float* Wb = W + (long)n0 * K + (kt+1)*32;
            #pragma unroll
            for (int it = 0; it < 4; it++) {
                int linear = tid + it*256;
                int row = linear >> 3, c4 = linear & 7;
                long off = (long)row * K + c4*4;
                ra[it] = (m0+row < M) ? *(const float4*)(Ab + off) : z4;
                rb[it] = (n0+row < N) ? *(const float4*)(Wb + off) : z4;
            }
        }
        // compute on buffer cur
        #pragma unroll
        for (int ks = 0; ks < 4; ks++) {
            const int kpo = (lc << 1) ^ swz ^ (ks << 1);
            unsigned a0[4], a1[4], a2[4], a3[4];
            #pragma unroll
            for (int mt = 0; mt < 4; mt++) {
                int row = wm*64 + mt*16 + lr;
                uint2 lo = *(const uint2*)&As[((cur*4 + ks)*128 + row    )*8 + kpo];
                uint2 hi = *(const uint2*)&As[((cur*4 + ks)*128 + row + 8)*8 + kpo];
                a0[mt]=lo.x; a2[mt]=lo.y; a1[mt]=hi.x; a3[mt]=hi.y;
            }
            unsigned b0[4], b1[4];
            #pragma unroll
            for (int nt = 0; nt < 4; nt++) {
                int col = wn*32 + nt*8 + lr;
                uint2 bv = *(const uint2*)&Bs[((cur*4 + ks)*128 + col)*8 + kpo];
                b0[nt]=bv.x; b1[nt]=bv.y;
            }
            #pragma unroll
            for (int mt = 0; mt < 4; mt++)
              #pragma unroll
              for (int nt = 0; nt < 4; nt++) {
                asm volatile(
                  "mma.sync.aligned.m16n8k8.row.col.f32.tf32.tf32.f32 "
                  "{%0,%1,%2,%3}, {%4,%5,%6,%7}, {%8,%9}, {%0,%1,%2,%3};"
                  : "+f"(acc[mt][nt][0]), "+f"(acc[mt][nt][1]),
                    "+f"(acc[mt][nt][2]), "+f"(acc[mt][nt][3])
                  : "r"(a0[mt]), "r"(a1[mt]), "r"(a2[mt]), "r"(a3[mt]),
                    "r"(b0[nt]), "r"(b1[nt]));
              }
        }
        // store prefetched tile into the other buffer
        if (kt + 1 < ntiles) {
            const int nxt = cur ^ 1;
            #pragma unroll
            for (int it = 0; it < 4; it++) {
                int linear = tid + it*256;
                int row = linear >> 3, c4 = linear & 7;
                int kg = c4 >> 1, d = c4 & 1;
                int msk = ((row & 3) << 1) ^ (kg << 1);
                unsigned* pA = &As[((nxt*4 + kg)*128 + row)*8];
                unsigned* pB = &Bs[((nxt*4 + kg)*128 + row)*8];
                pA[(0^msk)+d] = f2tf(ra[it].x); pA[(2^msk)+d] = f2tf(ra[it].y);
                pA[(4^msk)+d] = f2tf(ra[it].z); pA[(6^msk)+d] = f2tf(ra[it].w);
                pB[(0^msk)+d] = f2tf(rb[it].x); pB[(2^msk)+d] = f2tf(rb[it].y);
                pB[(4^msk)+d] = f2tf(rb[it].z); pB[(6^msk)+d] = f2tf(rb[it].w);
            }
        }
        __syncthreads();
    }

    // ---- epilogue ----
    #pragma unroll
    for (int mt = 0; mt < 4; mt++) {
        int r0 = m0 + wm*64 + mt*16 + lr;
        #pragma unroll
        for (int nt = 0; nt < 4; nt++) {
            int cc = n0 + wn*32 + nt*8 + (lc << 1);
            float v0 = acc[mt][nt][0], v1 = acc[mt][nt][1];
            float v2 = acc[mt][nt][2], v3 = acc[mt][nt][3];
            if (bias) {
                float bb0 = bias[cc], bb1 = bias[cc+1];
                v0 += bb0; v1 += bb1; v2 += bb0; v3 += bb1;
            }
            if (RES) {
                if (r0 < M) {
                    float2 rr = *(const float2*)&Rs[(long)r0*N + cc];
                    v0 += rr.x; v1 += rr.y;
                }
                if (r0 + 8 < M) {
                    float2 rr = *(const float2*)&Rs[(long)(r0+8)*N + cc];
                    v2 += rr.x; v3 += rr.y;
                }
            }
            if (GELU) { v0 = gelu_f(v0); v1 = gelu_f(v1); v2 = gelu_f(v2); v3 = gelu_f(v3); }
            if (r0 < M)     *(float2*)&Cp[(long)r0*N + cc]     = make_float2(v0, v1);
            if (r0 + 8 < M) *(float2*)&Cp[(long)(r0+8)*N + cc] = make_float2(v2, v3);
        }
    }
}

#define GSM_BYTES (4u * 4 * GSM_BUFU)   // 65536

// ---------------------------------------------------------------------------
// SIMT NT SGEMM for the tiny head GEMMs (M=32): 64x64 tile, BK=16
// ---------------------------------------------------------------------------
template<bool GELU, bool RES>
__global__ void gemm_nt(const float* __restrict__ A, const float* __restrict__ W,
                        const float* __restrict__ bias, const float* __restrict__ Rs,
                        float* __restrict__ C, int M, int N, int K) {
    __shared__ float As[16][64];
    __shared__ float Bs[16][64];
    int tid = threadIdx.x;
    int tx = tid & 15, ty = tid >> 4;
    int m0 = blockIdx.y * 64, n0 = blockIdx.x * 64;
    int lr = tid >> 2;
    int lc = (tid & 3) << 2;
    float acc[4][4] = {};
    const float* Aptr = A + (long)(m0 + lr) * K + lc;
    const float* Wptr = W + (long)(n0 + lr) * K + lc;
    bool am = (m0 + lr) < M;
    bool wn = (n0 + lr) < N;
    for (int k0 = 0; k0 < K; k0 += 16) {
        float4 av = am ? *(const float4*)(Aptr + k0) : make_float4(0.f,0.f,0.f,0.f);
        float4 wv = wn ? *(const float4*)(Wptr + k0) : make_float4(0.f,0.f,0.f,0.f);
        As[lc+0][lr]=av.x; As[lc+1][lr]=av.y; As[lc+2][lr]=av.z; As[lc+3][lr]=av.w;
        Bs[lc+0][lr]=wv.x; Bs[lc+1][lr]=wv.y; Bs[lc+2][lr]=wv.z; Bs[lc+3][lr]=wv.w;
        __syncthreads();
        #pragma unroll
        for (int kk = 0; kk < 16; kk++) {
            float4 a = *(const float4*)(&As[kk][ty << 2]);
            float4 b = *(const float4*)(&Bs[kk][tx << 2]);
            acc[0][0] += a.x*b.x; acc[0][1] += a.x*b.y; acc[0][2] += a.x*b.z; acc[0][3] += a.x*b.w;
            acc[1][0] += a.y*b.x; acc[1][1] += a.y*b.y; acc[1][2] += a.y*b.z; acc[1][3] += a.y*b.w;
            acc[2][0] += a.z*b.x; acc[2][1] += a.z*b.y; acc[2][2] += a.z*b.z; acc[2][3] += a.z*b.w;
            acc[3][0] += a.w*b.x; acc[3][1] += a.w*b.y; acc[3][2] += a.w*b.z; acc[3][3] += a.w*b.w;
        }
        __syncthreads();
    }
    #pragma unroll
    for (int i = 0; i < 4; i++) {
        int m = m0 + (ty << 2) + i;
        if (m >= M) continue;
        #pragma unroll
        for (int j = 0; j < 4; j++) {
            int n = n0 + (tx << 2) + j;
            if (n >= N) continue;
            float v = acc[i][j];
            if (bias) v += bias[n];
            if (RES)  v += Rs[(long)m * N + n];
            if (GELU) v = gelu_f(v);
            C[(long)m * N + n] = v;
        }
    }
}

// ---------------------------------------------------------------------------
// Fused attention: one block per (b, h). K/V staged in smem (pitch 65).
// ---------------------------------------------------------------------------
#define ATTN_SMEM ((197*65*2 + 64 + 256 + 256 + 16) * 4)

__global__ void attn_kernel(const float* __restrict__ qkv, float* __restrict__ out) {
    int b = blockIdx.x / NH, h = blockIdx.x % NH;
    int tid = threadIdx.x;
    int lane = tid & 31, warp = tid >> 5;
    extern __shared__ float sm[];
    float* Ks  = sm;
    float* Vs  = Ks + 197*65;
    float* qs  = Vs + 197*65;
    float* ss  = qs + 64;
    float* pv  = ss + 256;
    float* red = pv + 256;

    const float* base = qkv + (long)b * NTOK * (3*DD) + h * DH;
    for (int idx = tid; idx < NTOK * DH; idx += 256) {
        int j = idx >> 6, d = idx & 63;
        Ks[j*65 + d] = base[(long)j*(3*DD) + DD   + d];
        Vs[j*65 + d] = base[(long)j*(3*DD) + 2*DD + d];
    }
    __syncthreads();

    for (int i = 0; i < NTOK; i++) {
        if (tid < DH) qs[tid] = base[(long)i*(3*DD) + tid];
        __syncthreads();

        float s = -1e30f;
        if (tid < NTOK) {
            float acc = 0.f;
            #pragma unroll 16
            for (int d = 0; d < DH; d++) acc += qs[d] * Ks[tid*65 + d];
            s = acc * 0.125f;
        }
        float mx = s;
        #pragma unroll
        for (int o = 16; o; o >>= 1) mx = fmaxf(mx, __shfl_xor_sync(0xffffffffu, mx, o));
        if (lane == 0) red[warp] = mx;
        __syncthreads();
        float rowmax = red[0];
        #pragma unroll
        for (int w = 1; w < 8; w++) rowmax = fmaxf(rowmax, red[w]);

        float p = (tid < NTOK) ? expf(s - rowmax) : 0.f;
        ss[tid] = p;
        float sum = p;
        #pragma unroll
        for (int o = 16; o; o >>= 1) sum += __shfl_xor_sync(0xffffffffu, sum, o);
        if (lane == 0) red[8 + warp] = sum;
        __syncthreads();
        float tot = red[8];
        #pragma unroll
        for (int w = 1; w < 8; w++) tot += red[8 + w];
        float inv = 1.0f / tot;

        int d = tid & 63, jg = tid >> 6;
        float acc = 0.f;
        for (int j = jg; j < NTOK; j += 4) acc += ss[j] * Vs[j*65 + d];
        pv[tid] = acc;
        __syncthreads();
        if (tid < DH) {
            float ov = (pv[tid] + pv[tid+64] + pv[tid+128] + pv[tid+192]) * inv;
            out[((long)b*NTOK + i)*DD + h*DH + tid] = ov;
        }
        __syncthreads();
    }
}

// ---------------------------------------------------------------------------
// host orchestration
// ---------------------------------------------------------------------------
extern "C" void kernel_launch(void* const* d_in, const int* in_sizes, int n_in,
                              void* d_out, int out_size) {
    const float* x_in    = (const float*)d_in[0];
    const float* conv_w  = (const float*)d_in[1];
    const float* cls_tok = (const float*)d_in[2];
    const float* pos     = (const float*)d_in[3];
    const float* lnprew  = (const float*)d_in[4];
    const float* lnpreb  = (const float*)d_in[5];
    const float* ln1w    = (const float*)d_in[6];
    const float* ln1b    = (const float*)d_in[7];
    const float* qkvw    = (const float*)d_in[8];
    const float* qkvb    = (const float*)d_in[9];
    const float* pw      = (const float*)d_in[10];
    const float* pb      = (const float*)d_in[11];
    const float* ln2w    = (const float*)d_in[12];
    const float* ln2b    = (const float*)d_in[13];
    const float* fw      = (const float*)d_in[14];
    const float* fb      = (const float*)d_in[15];
    const float* cw      = (const float*)d_in[16];
    const float* cb      = (const float*)d_in[17];
    const float* lnpostw = (const float*)d_in[18];
    const float* lnpostb = (const float*)d_in[19];
    const float* projw   = (const float*)d_in[20];
    const float* headw   = (const float*)d_in[21];
    const float* headb   = (const float*)d_in[22];

    float *gx, *gh, *gq, *go, *gm, *gp, *gc, *gz;
    cudaGetSymbolAddress((void**)&gx, g_x);
    cudaGetSymbolAddress((void**)&gh, g_h);
    cudaGetSymbolAddress((void**)&gq, g_qkv);
    cudaGetSymbolAddress((void**)&go, g_o);
    cudaGetSymbolAddress((void**)&gm, g_mlp);
    cudaGetSymbolAddress((void**)&gp, g_pat);
    cudaGetSymbolAddress((void**)&gc, g_cls);
    cudaGetSymbolAddress((void**)&gz, g_z);

    cudaFuncSetAttribute(attn_kernel, cudaFuncAttributeMaxDynamicSharedMemorySize, ATTN_SMEM);
    cudaFuncSetAttribute(gemm_tc<false,false>, cudaFuncAttributeMaxDynamicSharedMemorySize, GSM_BYTES);
    cudaFuncSetAttribute(gemm_tc<false,true >, cudaFuncAttributeMaxDynamicSharedMemorySize, GSM_BYTES);
    cudaFuncSetAttribute(gemm_tc<true ,false>, cudaFuncAttributeMaxDynamicSharedMemorySize, GSM_BYTES);

    const int MB  = (MROWS + 127) / 128;   // 50
    const int MBP = (PROWS + 127) / 128;   // 49

    // patch embed
    im2col_kernel<<<(PROWS*DD + 255)/256, 256>>>(x_in);
    gemm_tc<false,false><<<dim3(DD/128, MBP), 256, GSM_BYTES>>>(
        gp, conv_w, nullptr, nullptr, go, PROWS, DD, DD);
    assemble_kernel<<<(MROWS*DD + 255)/256, 256>>>(go, cls_tok, pos);
    ln_kernel<<<MROWS, 256>>>(gh, gx, lnprew, lnpreb, DD, DD);

    for (int l = 0; l < DEPTH; l++) {
        // attention sub-block
        ln_kernel<<<MROWS, 256>>>(gx, gh, ln1w + l*DD, ln1b + l*DD, DD, DD);
        gemm_tc<false,false><<<dim3((3*DD)/128, MB), 256, GSM_BYTES>>>(
            gh, qkvw + (long)l*3*DD*DD, qkvb + (long)l*3*DD, nullptr, gq, MROWS, 3*DD, DD);
        attn_kernel<<<BB*NH, 256, ATTN_SMEM>>>(gq, go);
        gemm_tc<false,true><<<dim3(DD/128, MB), 256, GSM_BYTES>>>(
            go, pw + (long)l*DD*DD, pb + (long)l*DD, gx, gx, MROWS, DD, DD);
        // MLP sub-block
        ln_kernel<<<MROWS, 256>>>(gx, gh, ln2w + l*DD, ln2b + l*DD, DD, DD);
        gemm_tc<true,false><<<dim3(MLPD/128, MB), 256, GSM_BYTES>>>(
            gh, fw + (long)l*MLPD*DD, fb + (long)l*MLPD, nullptr, gm, MROWS, MLPD, DD);
        gemm_tc<false,true><<<dim3(DD/128, MB), 256, GSM_BYTES>>>(
            gm, cw + (long)l*DD*MLPD, cb + (long)l*DD, gx, gx, MROWS, DD, MLPD);
    }

    // head: ln_post on cls rows only, then proj, then classifier (tiny: SIMT)
    ln_kernel<<<BB, 256>>>(gx, gc, lnpostw, lnpostb, (long)NTOK*DD, DD);
    gemm_nt<false,false><<<dim3(PROJD/64, 1), 256>>>(gc, projw, nullptr, nullptr, gz, BB, PROJD, DD);
    gemm_nt<false,false><<<dim3((NCLS+63)/64, 1), 256>>>(gz, headw, headb, nullptr, (float*)d_out, BB, NCLS, PROJD);
}

// round 6
// speedup vs baseline: 3.0056x; 1.3495x over previous
#include <cuda_runtime.h>
#include <cuda_fp16.h>
#include <math.h>
#include <stdint.h>

// ---------------------------------------------------------------------------
// CLIP ViT-B/16 forward. Round 5: fp16 mma.sync(m16n8k16) + ldmatrix GEMMs,
// fp16 operand storage (weights pre-converted once per launch).
// ---------------------------------------------------------------------------

#define BB      32
#define NTOK    197
#define NPAT    196
#define DD      768
#define DEPTH   12
#define NH      12
#define DH      64
#define MLPD    3072
#define PROJD   512
#define NCLS    1000
#define MROWS   (BB*NTOK)          // 6304
#define PROWS   (BB*NPAT)          // 6272

// fp32 buffers
__device__ __align__(128) float  g_x   [MROWS*DD];      // residual stream
__device__ __align__(128) float  g_qkv [MROWS*3*DD];    // qkv (also temp for assemble)
__device__ __align__(128) float  g_pe  [PROWS*DD];      // patch embed out
__device__ __align__(128) float  g_cls [BB*DD];
__device__ __align__(128) float  g_z   [BB*PROJD];
// fp16 buffers
__device__ __align__(128) __half g_h   [MROWS*DD];      // LN output (GEMM A)
__device__ __align__(128) __half g_o   [MROWS*DD];      // attention out (GEMM A)
__device__ __align__(128) __half g_mlp [MROWS*MLPD];    // mlp hidden (GEMM A)
__device__ __align__(128) __half g_pat [PROWS*DD];      // im2col patches (GEMM A)
// fp16 weights (converted once per launch)
__device__ __align__(128) __half g_wconv [DD*DD];
__device__ __align__(128) __half g_wqkv  [DEPTH*3*DD*DD];
__device__ __align__(128) __half g_wproj [DEPTH*DD*DD];
__device__ __align__(128) __half g_wfc   [DEPTH*MLPD*DD];
__device__ __align__(128) __half g_wcpr  [DEPTH*DD*MLPD];

// ---------------------------------------------------------------------------
// fp32 -> fp16 weight conversion (vectorized, 8 elems/thread)
// ---------------------------------------------------------------------------
__global__ void f2h_kernel(const float* __restrict__ in, __half* __restrict__ out, int n8) {
    int i = blockIdx.x * 256 + threadIdx.x;
    if (i >= n8) return;
    const float4* p = (const float4*)in + i*2;
    float4 a = p[0], b = p[1];
    __half2 h0 = __floats2half2_rn(a.x, a.y);
    __half2 h1 = __floats2half2_rn(a.z, a.w);
    __half2 h2 = __floats2half2_rn(b.x, b.y);
    __half2 h3 = __floats2half2_rn(b.z, b.w);
    uint4 v;
    v.x = *(uint32_t*)&h0; v.y = *(uint32_t*)&h1;
    v.z = *(uint32_t*)&h2; v.w = *(uint32_t*)&h3;
    ((uint4*)out)[i] = v;
}

// ---------------------------------------------------------------------------
// im2col: gather 16x16x3 patches -> (6272, 768) fp16
// ---------------------------------------------------------------------------
__global__ void im2col_kernel(const float* __restrict__ x) {
    int idx = blockIdx.x * 256 + threadIdx.x;
    if (idx >= PROWS * DD) return;
    int k = idx % DD;
    int m = idx / DD;
    int b = m / NPAT, p = m % NPAT;
    int ph = p / 14, pw = p % 14;
    int c = k >> 8, r = (k >> 4) & 15, col = k & 15;
    g_pat[idx] = __float2half_rn(x[(((long)(b*3 + c)*224 + ph*16 + r)*224) + pw*16 + col]);
}

// ---------------------------------------------------------------------------
// assemble tokens into g_qkv (fp32 temp): cls+pos / pe+pos
// ---------------------------------------------------------------------------
__global__ void assemble_kernel(const float* __restrict__ pe,
                                const float* __restrict__ cls_tok,
                                const float* __restrict__ pos) {
    int idx = blockIdx.x * 256 + threadIdx.x;
    if (idx >= MROWS * DD) return;
    int d = idx % DD;
    int bn = idx / DD;
    int b = bn / NTOK, n = bn % NTOK;
    float v;
    if (n == 0) v = cls_tok[d] + pos[d];
    else        v = pe[((long)b*NPAT + (n-1))*DD + d] + pos[(long)n*DD + d];
    g_qkv[idx] = v;
}

// ---------------------------------------------------------------------------
// LayerNorm over 768, templated output type (float or __half)
// ---------------------------------------------------------------------------
template<typename OutT>
__global__ void ln_kernel(const float* __restrict__ in, OutT* __restrict__ out,
                          const float* __restrict__ gam, const float* __restrict__ bet,
                          long in_stride, long out_stride) {
    __shared__ float red[16];
    int row = blockIdx.x, tid = threadIdx.x;
    const float* xr = in + (long)row * in_stride;
    float v0 = xr[tid], v1 = xr[tid + 256], v2 = xr[tid + 512];
    float s = v0 + v1 + v2;
    #pragma unroll
    for (int o = 16; o; o >>= 1) s += __shfl_xor_sync(0xffffffffu, s, o);
    if ((tid & 31) == 0) red[tid >> 5] = s;
    __syncthreads();
    float tot = red[0]+red[1]+red[2]+red[3]+red[4]+red[5]+red[6]+red[7];
    float mean = tot * (1.0f / 768.0f);
    float d0 = v0 - mean, d1 = v1 - mean, d2 = v2 - mean;
    float q = d0*d0 + d1*d1 + d2*d2;
    #pragma unroll
    for (int o = 16; o; o >>= 1) q += __shfl_xor_sync(0xffffffffu, q, o);
    if ((tid & 31) == 0) red[8 + (tid >> 5)] = q;
    __syncthreads();
    float var = (red[8]+red[9]+red[10]+red[11]+red[12]+red[13]+red[14]+red[15]) * (1.0f/768.0f);
    float rs = rsqrtf(var + 1e-5f);
    OutT* orow = out + (long)row * out_stride;
    orow[tid      ] = (OutT)(d0 * rs * gam[tid      ] + bet[tid      ]);
    orow[tid + 256] = (OutT)(d1 * rs * gam[tid + 256] + bet[tid + 256]);
    orow[tid + 512] = (OutT)(d2 * rs * gam[tid + 512] + bet[tid + 512]);
}

__device__ __forceinline__ float gelu_f(float v) {
    return 0.5f * v * (1.0f + erff(v * 0.70710678118654752f));
}

// ---------------------------------------------------------------------------
// fp16 tensor-core NT GEMM: C[M,N] = A[M,K] @ W[N,K]^T (+bias)(+res)(gelu)
// A, W fp16; C float or __half. 128x128 tile, BK=32, 256 threads (8 warps 2x4),
// warp tile 64x32. mma.sync.m16n8k16.f32.f16.f16.f32, ldmatrix.x4 frag loads.
// Smem: 80B row pitch (conflict-free ldmatrix), double buffered:
//   stage s at s*20480: A rows 0..127 (32 halves each), B at +10240.
// Requires N % 128 == 0, K % 32 == 0.
// ---------------------------------------------------------------------------
__device__ __forceinline__ uint32_t smem_u32(const void* p) {
    uint32_t a;
    asm("{ .reg .u64 t; cvta.to.shared.u64 t, %1; cvt.u32.u64 %0, t; }" : "=r"(a) : "l"(p));
    return a;
}

#define LDSM_X4(r0,r1,r2,r3,addr) \
    asm volatile("ldmatrix.sync.aligned.m8n8.x4.shared.b16 {%0,%1,%2,%3}, [%4];" \
                 : "=r"(r0), "=r"(r1), "=r"(r2), "=r"(r3) : "r"(addr))

#define HMMA16816(d, a0,a1,a2,a3, b0,b1) \
    asm volatile("mma.sync.aligned.m16n8k16.row.col.f32.f16.f16.f32 " \
                 "{%0,%1,%2,%3}, {%4,%5,%6,%7}, {%8,%9}, {%0,%1,%2,%3};" \
                 : "+f"((d)[0]), "+f"((d)[1]), "+f"((d)[2]), "+f"((d)[3]) \
                 : "r"(a0), "r"(a1), "r"(a2), "r"(a3), "r"(b0), "r"(b1))

#define HSTAGE 20480   // bytes per stage (A 10240 + B 10240)

template<typename OutT, bool GELU, bool RES>
__global__ __launch_bounds__(256, 2)
void gemm_h(const __half* __restrict__ A, const __half* __restrict__ W,
            const float* __restrict__ bias, const float* __restrict__ Rs,
            OutT* __restrict__ Cp, int M, int N, int K) {
    __shared__ __align__(16) uint8_t smem[2 * HSTAGE];
    const uint32_t sb = smem_u32(smem);
    const int tid = threadIdx.x, lane = tid & 31, warp = tid >> 5;
    const int wm = warp >> 2, wn = warp & 3;
    const int m0 = blockIdx.y * 128, n0 = blockIdx.x * 128;

    float acc[4][4][4];
    #pragma unroll
    for (int i=0;i<4;i++)
      #pragma unroll
      for (int j=0;j<4;j++)
        #pragma unroll
        for (int f=0;f<4;f++) acc[i][j][f]=0.f;

    const int T = K >> 5;
    // staging: thread handles 16B chunks; ch = tid + it*256; row=ch>>2, c=ch&3
    const int srow = tid >> 2, sc = tid & 3;
    const uint32_t soff0 = (uint32_t)srow * 80 + sc * 16;          // it=0 (rows 0..63)
    const uint32_t soff1 = (uint32_t)(srow + 64) * 80 + sc * 16;   // it=1 (rows 64..127)
    uint4 ra[2], rb[2];
    const uint4 z4 = make_uint4(0u,0u,0u,0u);

    auto ldg_tile = [&](int t) {
        const __half* Ab = A + (size_t)m0 * K + t * 32;
        const __half* Bb = W + (size_t)n0 * K + t * 32;
        ra[0] = (m0 + srow      < M) ? *(const uint4*)(Ab + (size_t)srow      * K + sc*8) : z4;
        ra[1] = (m0 + srow + 64 < M) ? *(const uint4*)(Ab + (size_t)(srow+64) * K + sc*8) : z4;
        rb[0] = *(const uint4*)(Bb + (size_t)srow      * K + sc*8);
        rb[1] = *(const uint4*)(Bb + (size_t)(srow+64) * K + sc*8);
    };
    auto sts_tile = [&](int s) {
        uint8_t* base = smem + s * HSTAGE;
        *(uint4*)(base + soff0)         = ra[0];
        *(uint4*)(base + soff1)         = ra[1];
        *(uint4*)(base + 10240 + soff0) = rb[0];
        *(uint4*)(base + 10240 + soff1) = rb[1];
    };

    // fragment-load address bases (per-lane, stage-relative)
    const uint32_t a_l15 = lane & 15, a_hi = lane >> 4;
    const uint32_t aoff = (uint32_t)(wm*64 + a_l15) * 80 + a_hi * 16;
    const uint32_t brow = (uint32_t)(wn*32 + (lane & 7) + ((lane >> 4) << 3));
    const uint32_t boff = 10240 + brow * 80 + ((lane >> 3) & 1) * 16;

    ldg_tile(0);
    sts_tile(0);
    __syncthreads();

    for (int t = 0; t < T; t++) {
        const uint32_t stb = sb + (t & 1) * HSTAGE;
        if (t + 1 < T) ldg_tile(t + 1);
        #pragma unroll
        for (int kc = 0; kc < 2; kc++) {
            uint32_t af[4][4];
            #pragma unroll
            for (int mt = 0; mt < 4; mt++) {
                uint32_t addr = stb + aoff + mt*16*80 + kc*32;
                LDSM_X4(af[mt][0], af[mt][1], af[mt][2], af[mt][3], addr);
            }
            uint32_t bf[2][4];
            #pragma unroll
            for (int pr = 0; pr < 2; pr++) {
                uint32_t addr = stb + boff + pr*16*80 + kc*32;
                LDSM_X4(bf[pr][0], bf[pr][1], bf[pr][2], bf[pr][3], addr);
            }
            #pragma unroll
            for (int mt = 0; mt < 4; mt++) {
                #pragma unroll
                for (int nt = 0; nt < 4; nt++) {
                    HMMA16816(acc[mt][nt],
                              af[mt][0], af[mt][1], af[mt][2], af[mt][3],
                              bf[nt>>1][(nt&1)*2], bf[nt>>1][(nt&1)*2+1]);
                }
            }
        }
        if (t + 1 < T) sts_tile((t + 1) & 1);
        __syncthreads();
    }

    // ---- epilogue ----
    const int lr = lane >> 2, lc = lane & 3;
    #pragma unroll
    for (int mt = 0; mt < 4; mt++) {
        int r0 = m0 + wm*64 + mt*16 + lr;
        #pragma unroll
        for (int nt = 0; nt < 4; nt++) {
            int cc = n0 + wn*32 + nt*8 + lc*2;
            float v0 = acc[mt][nt][0], v1 = acc[mt][nt][1];
            float v2 = acc[mt][nt][2], v3 = acc[mt][nt][3];
            if (bias) {
                float bb0 = bias[cc], bb1 = bias[cc+1];
                v0 += bb0; v1 += bb1; v2 += bb0; v3 += bb1;
            }
            if (RES) {
                if (r0 < M) {
                    float2 rr = *(const float2*)&Rs[(size_t)r0*N + cc];
                    v0 += rr.x; v1 += rr.y;
                }
                if (r0 + 8 < M) {
                    float2 rr = *(const float2*)&Rs[(size_t)(r0+8)*N + cc];
                    v2 += rr.x; v3 += rr.y;
                }
            }
            if (GELU) { v0 = gelu_f(v0); v1 = gelu_f(v1); v2 = gelu_f(v2); v3 = gelu_f(v3); }
            if (sizeof(OutT) == 4) {
                if (r0 < M)     *(float2*)&(((float*)Cp)[(size_t)r0*N + cc])     = make_float2(v0, v1);
                if (r0 + 8 < M) *(float2*)&(((float*)Cp)[(size_t)(r0+8)*N + cc]) = make_float2(v2, v3);
            } else {
                if (r0 < M) {
                    __half2 h = __floats2half2_rn(v0, v1);
                    *(__half2*)&(((__half*)Cp)[(size_t)r0*N + cc]) = h;
                }
                if (r0 + 8 < M) {
                    __half2 h = __floats2half2_rn(v2, v3);
                    *(__half2*)&(((__half*)Cp)[(size_t)(r0+8)*N + cc]) = h;
                }
            }
        }
    }
}

// ---------------------------------------------------------------------------
// SIMT NT SGEMM for the tiny head GEMMs (M=32), fp32
// ---------------------------------------------------------------------------
__global__ void gemm_nt(const float* __restrict__ A, const float* __restrict__ W,
                        const float* __restrict__ bias, float* __restrict__ C,
                        int M, int N, int K) {
    __shared__ float As[16][64];
    __shared__ float Bs[16][64];
    int tid = threadIdx.x;
    int tx = tid & 15, ty = tid >> 4;
    int m0 = blockIdx.y * 64, n0 = blockIdx.x * 64;
    int lr = tid >> 2;
    int lc = (tid & 3) << 2;
    float acc[4][4] = {};
    const float* Aptr = A + (long)(m0 + lr) * K + lc;
    const float* Wptr = W + (long)(n0 + lr) * K + lc;
    bool am = (m0 + lr) < M;
    bool wn = (n0 + lr) < N;
    for (int k0 = 0; k0 < K; k0 += 16) {
        float4 av = am ? *(const float4*)(Aptr + k0) : make_float4(0.f,0.f,0.f,0.f);
        float4 wv = wn ? *(const float4*)(Wptr + k0) : make_float4(0.f,0.f,0.f,0.f);
        As[lc+0][lr]=av.x; As[lc+1][lr]=av.y; As[lc+2][lr]=av.z; As[lc+3][lr]=av.w;
        Bs[lc+0][lr]=wv.x; Bs[lc+1][lr]=wv.y; Bs[lc+2][lr]=wv.z; Bs[lc+3][lr]=wv.w;
        __syncthreads();
        #pragma unroll
        for (int kk = 0; kk < 16; kk++) {
            float4 a = *(const float4*)(&As[kk][ty << 2]);
            float4 b = *(const float4*)(&Bs[kk][tx << 2]);
            acc[0][0] += a.x*b.x; acc[0][1] += a.x*b.y; acc[0][2] += a.x*b.z; acc[0][3] += a.x*b.w;
            acc[1][0] += a.y*b.x; acc[1][1] += a.y*b.y; acc[1][2] += a.y*b.z; acc[1][3] += a.y*b.w;
            acc[2][0] += a.z*b.x; acc[2][1] += a.z*b.y; acc[2][2] += a.z*b.z; acc[2][3] += a.z*b.w;
            acc[3][0] += a.w*b.x; acc[3][1] += a.w*b.y; acc[3][2] += a.w*b.z; acc[3][3] += a.w*b.w;
        }
        __syncthreads();
    }
    #pragma unroll
    for (int i = 0; i < 4; i++) {
        int m = m0 + (ty << 2) + i;
        if (m >= M) continue;
        #pragma unroll
        for (int j = 0; j < 4; j++) {
            int n = n0 + (tx << 2) + j;
            if (n >= N) continue;
            float v = acc[i][j];
            if (bias) v += bias[n];
            C[(long)m * N + n] = v;
        }
    }
}

// ---------------------------------------------------------------------------
// Fused attention: one block per (b, h). Reads fp32 qkv, writes fp16 out.
// ---------------------------------------------------------------------------
#define ATTN_SMEM ((197*65*2 + 64 + 256 + 256 + 16) * 4)

__global__ void attn_kernel(const float* __restrict__ qkv, __half* __restrict__ out) {
    int b = blockIdx.x / NH, h = blockIdx.x % NH;
    int tid = threadIdx.x;
    int lane = tid & 31, warp = tid >> 5;
    extern __shared__ float sm[];
    float* Ks  = sm;
    float* Vs  = Ks + 197*65;
    float* qs  = Vs + 197*65;
    float* ss  = qs + 64;
    float* pv  = ss + 256;
    float* red = pv + 256;

    const float* base = qkv + (long)b * NTOK * (3*DD) + h * DH;
    for (int idx = tid; idx < NTOK * DH; idx += 256) {
        int j = idx >> 6, d = idx & 63;
        Ks[j*65 + d] = base[(long)j*(3*DD) + DD   + d];
        Vs[j*65 + d] = base[(long)j*(3*DD) + 2*DD + d];
    }
    __syncthreads();

    for (int i = 0; i < NTOK; i++) {
        if (tid < DH) qs[tid] = base[(long)i*(3*DD) + tid];
        __syncthreads();

        float s = -1e30f;
        if (tid < NTOK) {
            float acc = 0.f;
            #pragma unroll 16
            for (int d = 0; d < DH; d++) acc += qs[d] * Ks[tid*65 + d];
            s = acc * 0.125f;
        }
        float mx = s;
        #pragma unroll
        for (int o = 16; o; o >>= 1) mx = fmaxf(mx, __shfl_xor_sync(0xffffffffu, mx, o));
        if (lane == 0) red[warp] = mx;
        __syncthreads();
        float rowmax = red[0];
        #pragma unroll
        for (int w = 1; w < 8; w++) rowmax = fmaxf(rowmax, red[w]);

        float p = (tid < NTOK) ? expf(s - rowmax) : 0.f;
        ss[tid] = p;
        float sum = p;
        #pragma unroll
        for (int o = 16; o; o >>= 1) sum += __shfl_xor_sync(0xffffffffu, sum, o);
        if (lane == 0) red[8 + warp] = sum;
        __syncthreads();
        float tot = red[8];
        #pragma unroll
        for (int w = 1; w < 8; w++) tot += red[8 + w];
        float inv = 1.0f / tot;

        int d = tid & 63, jg = tid >> 6;
        float acc = 0.f;
        for (int j = jg; j < NTOK; j += 4) acc += ss[j] * Vs[j*65 + d];
        pv[tid] = acc;
        __syncthreads();
        if (tid < DH) {
            float ov = (pv[tid] + pv[tid+64] + pv[tid+128] + pv[tid+192]) * inv;
            out[((long)b*NTOK + i)*DD + h*DH + tid] = __float2half_rn(ov);
        }
        __syncthreads();
    }
}

// ---------------------------------------------------------------------------
// host orchestration
// ---------------------------------------------------------------------------
extern "C" void kernel_launch(void* const* d_in, const int* in_sizes, int n_in,
                              void* d_out, int out_size) {
    const float* x_in    = (const float*)d_in[0];
    const float* conv_w  = (const float*)d_in[1];
    const float* cls_tok = (const float*)d_in[2];
    const float* pos     = (const float*)d_in[3];
    const float* lnprew  = (const float*)d_in[4];
    const float* lnpreb  = (const float*)d_in[5];
    const float* ln1w    = (const float*)d_in[6];
    const float* ln1b    = (const float*)d_in[7];
    const float* qkvw    = (const float*)d_in[8];
    const float* qkvb    = (const float*)d_in[9];
    const float* pw      = (const float*)d_in[10];
    const float* pb      = (const float*)d_in[11];
    const float* ln2w    = (const float*)d_in[12];
    const float* ln2b    = (const float*)d_in[13];
    const float* fw      = (const float*)d_in[14];
    const float* fb      = (const float*)d_in[15];
    const float* cw      = (const float*)d_in[16];
    const float* cb      = (const float*)d_in[17];
    const float* lnpostw = (const float*)d_in[18];
    const float* lnpostb = (const float*)d_in[19];
    const float* projw   = (const float*)d_in[20];
    const float* headw   = (const float*)d_in[21];
    const float* headb   = (const float*)d_in[22];

    float  *gx, *gq, *gpe, *gc, *gz;
    __half *gh, *go, *gm, *gp;
    __half *wconv, *wqkv, *wproj, *wfc, *wcpr;
    cudaGetSymbolAddress((void**)&gx,  g_x);
    cudaGetSymbolAddress((void**)&gq,  g_qkv);
    cudaGetSymbolAddress((void**)&gpe, g_pe);
    cudaGetSymbolAddress((void**)&gc,  g_cls);
    cudaGetSymbolAddress((void**)&gz,  g_z);
    cudaGetSymbolAddress((void**)&gh,  g_h);
    cudaGetSymbolAddress((void**)&go,  g_o);
    cudaGetSymbolAddress((void**)&gm,  g_mlp);
    cudaGetSymbolAddress((void**)&gp,  g_pat);
    cudaGetSymbolAddress((void**)&wconv, g_wconv);
    cudaGetSymbolAddress((void**)&wqkv,  g_wqkv);
    cudaGetSymbolAddress((void**)&wproj, g_wproj);
    cudaGetSymbolAddress((void**)&wfc,   g_wfc);
    cudaGetSymbolAddress((void**)&wcpr,  g_wcpr);

    cudaFuncSetAttribute(attn_kernel, cudaFuncAttributeMaxDynamicSharedMemorySize, ATTN_SMEM);

    // ---- weight conversion (fp32 -> fp16) ----
    {
        int n;
        n = DD*DD/8;             f2h_kernel<<<(n+255)/256, 256>>>(conv_w, wconv, n);
        n = DEPTH*3*DD*DD/8;     f2h_kernel<<<(n+255)/256, 256>>>(qkvw,  wqkv,  n);
        n = DEPTH*DD*DD/8;       f2h_kernel<<<(n+255)/256, 256>>>(pw,    wproj, n);
        n = DEPTH*MLPD*DD/8;     f2h_kernel<<<(n+255)/256, 256>>>(fw,    wfc,   n);
        n = DEPTH*DD*MLPD/8;     f2h_kernel<<<(n+255)/256, 256>>>(cw,    wcpr,  n);
    }

    const int MB  = (MROWS + 127) / 128;   // 50
    const int MBP = (PROWS + 127) / 128;   // 49

    // ---- patch embed ----
    im2col_kernel<<<(PROWS*DD + 255)/256, 256>>>(x_in);
    gemm_h<float,false,false><<<dim3(DD/128, MBP), 256>>>(
        gp, wconv, nullptr, nullptr, gpe, PROWS, DD, DD);
    assemble_kernel<<<(MROWS*DD + 255)/256, 256>>>(gpe, cls_tok, pos);
    ln_kernel<float><<<MROWS, 256>>>(gq, gx, lnprew, lnpreb, DD, DD);

    for (int l = 0; l < DEPTH; l++) {
        // attention sub-block
        ln_kernel<__half><<<MROWS, 256>>>(gx, gh, ln1w + l*DD, ln1b + l*DD, DD, DD);
        gemm_h<float,false,false><<<dim3((3*DD)/128, MB), 256>>>(
            gh, wqkv + (size_t)l*3*DD*DD, qkvb + (long)l*3*DD, nullptr, gq, MROWS, 3*DD, DD);
        attn_kernel<<<BB*NH, 256, ATTN_SMEM>>>(gq, go);
        gemm_h<float,false,true><<<dim3(DD/128, MB), 256>>>(
            go, wproj + (size_t)l*DD*DD, pb + (long)l*DD, gx, gx, MROWS, DD, DD);
        // MLP sub-block
        ln_kernel<__half><<<MROWS, 256>>>(gx, gh, ln2w + l*DD, ln2b + l*DD, DD, DD);
        gemm_h<__half,true,false><<<dim3(MLPD/128, MB), 256>>>(
            gh, wfc + (size_t)l*MLPD*DD, fb + (long)l*MLPD, nullptr, gm, MROWS, MLPD, DD);
        gemm_h<float,false,true><<<dim3(DD/128, MB), 256>>>(
            gm, wcpr + (size_t)l*DD*MLPD, cb + (long)l*DD, gx, gx, MROWS, DD, MLPD);
    }

    // ---- head: ln_post on cls rows only, proj, classifier (tiny: SIMT fp32) ----
    ln_kernel<float><<<BB, 256>>>(gx, gc, lnpostw, lnpostb, (long)NTOK*DD, DD);
    gemm_nt<<<dim3(PROJD/64, 1), 256>>>(gc, projw, nullptr, gz, BB, PROJD, DD);
    gemm_nt<<<dim3((NCLS+63)/64, 1), 256>>>(gz, headw, headb, (float*)d_out, BB, NCLS, PROJD);
}

// round 7
// speedup vs baseline: 3.0492x; 1.0145x over previous
#include <cuda_runtime.h>
#include <cuda_fp16.h>
#include <math.h>
#include <stdint.h>

// ---------------------------------------------------------------------------
// CLIP ViT-B/16 forward. Round 6: cp.async 4-stage pipelined fp16 HMMA GEMM.
// ---------------------------------------------------------------------------

#define BB      32
#define NTOK    197
#define NPAT    196
#define DD      768
#define DEPTH   12
#define NH      12
#define DH      64
#define MLPD    3072
#define PROJD   512
#define NCLS    1000
#define MROWS   (BB*NTOK)          // 6304
#define PROWS   (BB*NPAT)          // 6272

// fp32 buffers
__device__ __align__(128) float  g_x   [MROWS*DD];      // residual stream
__device__ __align__(128) float  g_qkv [MROWS*3*DD];    // qkv (also temp for assemble)
__device__ __align__(128) float  g_pe  [PROWS*DD];      // patch embed out
__device__ __align__(128) float  g_cls [BB*DD];
__device__ __align__(128) float  g_z   [BB*PROJD];
// fp16 buffers
__device__ __align__(128) __half g_h   [MROWS*DD];      // LN output (GEMM A)
__device__ __align__(128) __half g_o   [MROWS*DD];      // attention out (GEMM A)
__device__ __align__(128) __half g_mlp [MROWS*MLPD];    // mlp hidden (GEMM A)
__device__ __align__(128) __half g_pat [PROWS*DD];      // im2col patches (GEMM A)
// fp16 weights (converted every launch — determinism)
__device__ __align__(128) __half g_wconv [DD*DD];
__device__ __align__(128) __half g_wqkv  [DEPTH*3*DD*DD];
__device__ __align__(128) __half g_wproj [DEPTH*DD*DD];
__device__ __align__(128) __half g_wfc   [DEPTH*MLPD*DD];
__device__ __align__(128) __half g_wcpr  [DEPTH*DD*MLPD];

// ---------------------------------------------------------------------------
// fp32 -> fp16 weight conversion (8 elems/thread)
// ---------------------------------------------------------------------------
__global__ void f2h_kernel(const float* __restrict__ in, __half* __restrict__ out, int n8) {
    int i = blockIdx.x * 256 + threadIdx.x;
    if (i >= n8) return;
    const float4* p = (const float4*)in + i*2;
    float4 a = p[0], b = p[1];
    __half2 h0 = __floats2half2_rn(a.x, a.y);
    __half2 h1 = __floats2half2_rn(a.z, a.w);
    __half2 h2 = __floats2half2_rn(b.x, b.y);
    __half2 h3 = __floats2half2_rn(b.z, b.w);
    uint4 v;
    v.x = *(uint32_t*)&h0; v.y = *(uint32_t*)&h1;
    v.z = *(uint32_t*)&h2; v.w = *(uint32_t*)&h3;
    ((uint4*)out)[i] = v;
}

// ---------------------------------------------------------------------------
// im2col: gather 16x16x3 patches -> (6272, 768) fp16
// ---------------------------------------------------------------------------
__global__ void im2col_kernel(const float* __restrict__ x) {
    int idx = blockIdx.x * 256 + threadIdx.x;
    if (idx >= PROWS * DD) return;
    int k = idx % DD;
    int m = idx / DD;
    int b = m / NPAT, p = m % NPAT;
    int ph = p / 14, pw = p % 14;
    int c = k >> 8, r = (k >> 4) & 15, col = k & 15;
    g_pat[idx] = __float2half_rn(x[(((long)(b*3 + c)*224 + ph*16 + r)*224) + pw*16 + col]);
}

// ---------------------------------------------------------------------------
// assemble tokens into g_qkv (fp32 temp): cls+pos / pe+pos
// ---------------------------------------------------------------------------
__global__ void assemble_kernel(const float* __restrict__ pe,
                                const float* __restrict__ cls_tok,
                                const float* __restrict__ pos) {
    int idx = blockIdx.x * 256 + threadIdx.x;
    if (idx >= MROWS * DD) return;
    int d = idx % DD;
    int bn = idx / DD;
    int b = bn / NTOK, n = bn % NTOK;
    float v;
    if (n == 0) v = cls_tok[d] + pos[d];
    else        v = pe[((long)b*NPAT + (n-1))*DD + d] + pos[(long)n*DD + d];
    g_qkv[idx] = v;
}

// ---------------------------------------------------------------------------
// LayerNorm over 768, templated output type (float or __half)
// ---------------------------------------------------------------------------
template<typename OutT>
__global__ void ln_kernel(const float* __restrict__ in, OutT* __restrict__ out,
                          const float* __restrict__ gam, const float* __restrict__ bet,
                          long in_stride, long out_stride) {
    __shared__ float red[16];
    int row = blockIdx.x, tid = threadIdx.x;
    const float* xr = in + (long)row * in_stride;
    float v0 = xr[tid], v1 = xr[tid + 256], v2 = xr[tid + 512];
    float s = v0 + v1 + v2;
    #pragma unroll
    for (int o = 16; o; o >>= 1) s += __shfl_xor_sync(0xffffffffu, s, o);
    if ((tid & 31) == 0) red[tid >> 5] = s;
    __syncthreads();
    float tot = red[0]+red[1]+red[2]+red[3]+red[4]+red[5]+red[6]+red[7];
    float mean = tot * (1.0f / 768.0f);
    float d0 = v0 - mean, d1 = v1 - mean, d2 = v2 - mean;
    float q = d0*d0 + d1*d1 + d2*d2;
    #pragma unroll
    for (int o = 16; o; o >>= 1) q += __shfl_xor_sync(0xffffffffu, q, o);
    if ((tid & 31) == 0) red[8 + (tid >> 5)] = q;
    __syncthreads();
    float var = (red[8]+red[9]+red[10]+red[11]+red[12]+red[13]+red[14]+red[15]) * (1.0f/768.0f);
    float rs = rsqrtf(var + 1e-5f);
    OutT* orow = out + (long)row * out_stride;
    orow[tid      ] = (OutT)(d0 * rs * gam[tid      ] + bet[tid      ]);
    orow[tid + 256] = (OutT)(d1 * rs * gam[tid + 256] + bet[tid + 256]);
    orow[tid + 512] = (OutT)(d2 * rs * gam[tid + 512] + bet[tid + 512]);
}

__device__ __forceinline__ float gelu_f(float v) {
    return 0.5f * v * (1.0f + erff(v * 0.70710678118654752f));
}

// ---------------------------------------------------------------------------
// fp16 tensor-core NT GEMM, cp.async 4-stage pipeline.
// C[M,N] = A[M,K] @ W[N,K]^T (+bias)(+res)(gelu). A,W fp16; C f32 or f16.
// 128x128 tile, BK=32, 256 threads (8 warps 2x4), warp tile 64x32.
// Smem/stage: A 128 rows x 80B pitch (64B payload) = 10240B, B same; 20480B.
// 4 stages = 81920B dynamic smem, 2 CTAs/SM.
// Requires N % 128 == 0, K % 32 == 0.
// ---------------------------------------------------------------------------
__device__ __forceinline__ uint32_t smem_u32(const void* p) {
    uint32_t a;
    asm("{ .reg .u64 t; cvta.to.shared.u64 t, %1; cvt.u32.u64 %0, t; }" : "=r"(a) : "l"(p));
    return a;
}

#define LDSM_X4(r0,r1,r2,r3,addr) \
    asm volatile("ldmatrix.sync.aligned.m8n8.x4.shared.b16 {%0,%1,%2,%3}, [%4];" \
                 : "=r"(r0), "=r"(r1), "=r"(r2), "=r"(r3) : "r"(addr))

#define HMMA16816(d, a0,a1,a2,a3, b0,b1) \
    asm volatile("mma.sync.aligned.m16n8k16.row.col.f32.f16.f16.f32 " \
                 "{%0,%1,%2,%3}, {%4,%5,%6,%7}, {%8,%9}, {%0,%1,%2,%3};" \
                 : "+f"((d)[0]), "+f"((d)[1]), "+f"((d)[2]), "+f"((d)[3]) \
                 : "r"(a0), "r"(a1), "r"(a2), "r"(a3), "r"(b0), "r"(b1))

__device__ __forceinline__ void cp16(uint32_t saddr, const void* gaddr) {
    asm volatile("cp.async.cg.shared.global [%0], [%1], 16;" :: "r"(saddr), "l"(gaddr));
}
__device__ __forceinline__ void cp16z(uint32_t saddr, const void* gaddr, int sz) {
    asm volatile("cp.async.cg.shared.global [%0], [%1], 16, %2;" :: "r"(saddr), "l"(gaddr), "r"(sz));
}
#define CP_COMMIT() asm volatile("cp.async.commit_group;" ::: "memory")
#define CP_WAIT2()  asm volatile("cp.async.wait_group 2;" ::: "memory")

#define HSTAGE 20480
#define GH_SMEM (4 * HSTAGE)   // 81920

template<typename OutT, bool GELU, bool RES>
__global__ __launch_bounds__(256, 2)
void gemm_h(const __half* __restrict__ A, const __half* __restrict__ W,
            const float* __restrict__ bias, const float* __restrict__ Rs,
            OutT* __restrict__ Cp, int M, int N, int K) {
    extern __shared__ uint8_t smem[];
    const uint32_t sb = smem_u32(smem);
    const int tid = threadIdx.x, lane = tid & 31, warp = tid >> 5;
    const int wm = warp >> 2, wn = warp & 3;
    const int m0 = blockIdx.y * 128, n0 = blockIdx.x * 128;

    float acc[4][4][4];
    #pragma unroll
    for (int i=0;i<4;i++)
      #pragma unroll
      for (int j=0;j<4;j++)
        #pragma unroll
        for (int f=0;f<4;f++) acc[i][j][f]=0.f;

    const int T = K >> 5;

    // --- cp.async staging: thread -> (row=tid>>2 [+64], chunk=tid&3) ---
    const int srow = tid >> 2, sc = tid & 3;
    const int szA0 = (m0 + srow      < M) ? 16 : 0;
    const int szA1 = (m0 + srow + 64 < M) ? 16 : 0;
    const __half* Ag0 = A + (szA0 ? ((size_t)(m0 + srow     ) * K + sc*8) : 0);
    const __half* Ag1 = A + (szA1 ? ((size_t)(m0 + srow + 64) * K + sc*8) : 0);
    const __half* Bg0 = W + (size_t)(n0 + srow     ) * K + sc*8;
    const __half* Bg1 = W + (size_t)(n0 + srow + 64) * K + sc*8;
    const uint32_t sA0 = sb + (uint32_t)srow*80 + sc*16;
    const uint32_t sA1 = sb + (uint32_t)(srow+64)*80 + sc*16;

    auto issue_stage = [&](int t, int s) {
        if (t < T) {
            uint32_t so = (uint32_t)s * HSTAGE;
            int ko = t * 32;
            cp16z(sA0 + so,         Ag0 + (szA0 ? ko : 0), szA0);
            cp16z(sA1 + so,         Ag1 + (szA1 ? ko : 0), szA1);
            cp16 (sA0 + so + 10240, Bg0 + ko);
            cp16 (sA1 + so + 10240, Bg1 + ko);
        }
        CP_COMMIT();
    };

    // --- fragment-load address bases (stage-relative) ---
    const uint32_t aoff = (uint32_t)(wm*64 + (lane & 15)) * 80 + (lane >> 4) * 16;
    const uint32_t boff = 10240 + (uint32_t)(wn*32 + (lane & 7) + ((lane >> 4) << 3)) * 80
                        + ((lane >> 3) & 1) * 16;

    issue_stage(0, 0);
    issue_stage(1, 1);
    issue_stage(2, 2);

    for (int t = 0; t < T; t++) {
        CP_WAIT2();
        __syncthreads();
        issue_stage(t + 3, (t + 3) & 3);
        const uint32_t stb = sb + (uint32_t)(t & 3) * HSTAGE;
        #pragma unroll
        for (int kc = 0; kc < 2; kc++) {
            uint32_t af[4][4];
            #pragma unroll
            for (int mt = 0; mt < 4; mt++) {
                uint32_t addr = stb + aoff + mt*16*80 + kc*32;
                LDSM_X4(af[mt][0], af[mt][1], af[mt][2], af[mt][3], addr);
            }
            uint32_t bf[2][4];
            #pragma unroll
            for (int pr = 0; pr < 2; pr++) {
                uint32_t addr = stb + boff + pr*16*80 + kc*32;
                LDSM_X4(bf[pr][0], bf[pr][1], bf[pr][2], bf[pr][3], addr);
            }
            #pragma unroll
            for (int mt = 0; mt < 4; mt++) {
                #pragma unroll
                for (int nt = 0; nt < 4; nt++) {
                    HMMA16816(acc[mt][nt],
                              af[mt][0], af[mt][1], af[mt][2], af[mt][3],
                              bf[nt>>1][(nt&1)*2], bf[nt>>1][(nt&1)*2+1]);
                }
            }
        }
    }

    // ---- epilogue ----
    const int lr = lane >> 2, lc = lane & 3;
    #pragma unroll
    for (int mt = 0; mt < 4; mt++) {
        int r0 = m0 + wm*64 + mt*16 + lr;
        #pragma unroll
        for (int nt = 0; nt < 4; nt++) {
            int cc = n0 + wn*32 + nt*8 + lc*2;
            float v0 = acc[mt][nt][0], v1 = acc[mt][nt][1];
            float v2 = acc[mt][nt][2], v3 = acc[mt][nt][3];
            if (bias) {
                float bb0 = bias[cc], bb1 = bias[cc+1];
                v0 += bb0; v1 += bb1; v2 += bb0; v3 += bb1;
            }
            if (RES) {
                if (r0 < M) {
                    float2 rr = *(const float2*)&Rs[(size_t)r0*N + cc];
                    v0 += rr.x; v1 += rr.y;
                }
                if (r0 + 8 < M) {
                    float2 rr = *(const float2*)&Rs[(size_t)(r0+8)*N + cc];
                    v2 += rr.x; v3 += rr.y;
                }
            }
            if (GELU) { v0 = gelu_f(v0); v1 = gelu_f(v1); v2 = gelu_f(v2); v3 = gelu_f(v3); }
            if (sizeof(OutT) == 4) {
                if (r0 < M)     *(float2*)&(((float*)Cp)[(size_t)r0*N + cc])     = make_float2(v0, v1);
                if (r0 + 8 < M) *(float2*)&(((float*)Cp)[(size_t)(r0+8)*N + cc]) = make_float2(v2, v3);
            } else {
                if (r0 < M) {
                    __half2 h = __floats2half2_rn(v0, v1);
                    *(__half2*)&(((__half*)Cp)[(size_t)r0*N + cc]) = h;
                }
                if (r0 + 8 < M) {
                    __half2 h = __floats2half2_rn(v2, v3);
                    *(__half2*)&(((__half*)Cp)[(size_t)(r0+8)*N + cc]) = h;
                }
            }
        }
    }
}

// ---------------------------------------------------------------------------
// SIMT NT SGEMM for the tiny head GEMMs (M=32), fp32
// ---------------------------------------------------------------------------
__global__ void gemm_nt(const float* __restrict__ A, const float* __restrict__ W,
                        const float* __restrict__ bias, float* __restrict__ C,
                        int M, int N, int K) {
    __shared__ float As[16][64];
    __shared__ float Bs[16][64];
    int tid = threadIdx.x;
    int tx = tid & 15, ty = tid >> 4;
    int m0 = blockIdx.y * 64, n0 = blockIdx.x * 64;
    int lr = tid >> 2;
    int lc = (tid & 3) << 2;
    float acc[4][4] = {};
    const float* Aptr = A + (long)(m0 + lr) * K + lc;
    const float* Wptr = W + (long)(n0 + lr) * K + lc;
    bool am = (m0 + lr) < M;
    bool wn = (n0 + lr) < N;
    for (int k0 = 0; k0 < K; k0 += 16) {
        float4 av = am ? *(const float4*)(Aptr + k0) : make_float4(0.f,0.f,0.f,0.f);
        float4 wv = wn ? *(const float4*)(Wptr + k0) : make_float4(0.f,0.f,0.f,0.f);
        As[lc+0][lr]=av.x; As[lc+1][lr]=av.y; As[lc+2][lr]=av.z; As[lc+3][lr]=av.w;
        Bs[lc+0][lr]=wv.x; Bs[lc+1][lr]=wv.y; Bs[lc+2][lr]=wv.z; Bs[lc+3][lr]=wv.w;
        __syncthreads();
        #pragma unroll
        for (int kk = 0; kk < 16; kk++) {
            float4 a = *(const float4*)(&As[kk][ty << 2]);
            float4 b = *(const float4*)(&Bs[kk][tx << 2]);
            acc[0][0] += a.x*b.x; acc[0][1] += a.x*b.y; acc[0][2] += a.x*b.z; acc[0][3] += a.x*b.w;
            acc[1][0] += a.y*b.x; acc[1][1] += a.y*b.y; acc[1][2] += a.y*b.z; acc[1][3] += a.y*b.w;
            acc[2][0] += a.z*b.x; acc[2][1] += a.z*b.y; acc[2][2] += a.z*b.z; acc[2][3] += a.z*b.w;
            acc[3][0] += a.w*b.x; acc[3][1] += a.w*b.y; acc[3][2] += a.w*b.z; acc[3][3] += a.w*b.w;
        }
        __syncthreads();
    }
    #pragma unroll
    for (int i = 0; i < 4; i++) {
        int m = m0 + (ty << 2) + i;
        if (m >= M) continue;
        #pragma unroll
        for (int j = 0; j < 4; j++) {
            int n = n0 + (tx << 2) + j;
            if (n >= N) continue;
            float v = acc[i][j];
            if (bias) v += bias[n];
            C[(long)m * N + n] = v;
        }
    }
}

// ---------------------------------------------------------------------------
// Fused attention: one block per (b, h). Reads fp32 qkv, writes fp16 out.
// ---------------------------------------------------------------------------
#define ATTN_SMEM ((197*65*2 + 64 + 256 + 256 + 16) * 4)

__global__ void attn_kernel(const float* __restrict__ qkv, __half* __restrict__ out) {
    int b = blockIdx.x / NH, h = blockIdx.x % NH;
    int tid = threadIdx.x;
    int lane = tid & 31, warp = tid >> 5;
    extern __shared__ float sm[];
    float* Ks  = sm;
    float* Vs  = Ks + 197*65;
    float* qs  = Vs + 197*65;
    float* ss  = qs + 64;
    float* pv  = ss + 256;
    float* red = pv + 256;

    const float* base = qkv + (long)b * NTOK * (3*DD) + h * DH;
    for (int idx = tid; idx < NTOK * DH; idx += 256) {
        int j = idx >> 6, d = idx & 63;
        Ks[j*65 + d] = base[(long)j*(3*DD) + DD   + d];
        Vs[j*65 + d] = base[(long)j*(3*DD) + 2*DD + d];
    }
    __syncthreads();

    for (int i = 0; i < NTOK; i++) {
        if (tid < DH) qs[tid] = base[(long)i*(3*DD) + tid];
        __syncthreads();

        float s = -1e30f;
        if (tid < NTOK) {
            float acc = 0.f;
            #pragma unroll 16
            for (int d = 0; d < DH; d++) acc += qs[d] * Ks[tid*65 + d];
            s = acc * 0.125f;
        }
        float mx = s;
        #pragma unroll
        for (int o = 16; o; o >>= 1) mx = fmaxf(mx, __shfl_xor_sync(0xffffffffu, mx, o));
        if (lane == 0) red[warp] = mx;
        __syncthreads();
        float rowmax = red[0];
        #pragma unroll
        for (int w = 1; w < 8; w++) rowmax = fmaxf(rowmax, red[w]);

        float p = (tid < NTOK) ? expf(s - rowmax) : 0.f;
        ss[tid] = p;
        float sum = p;
        #pragma unroll
        for (int o = 16; o; o >>= 1) sum += __shfl_xor_sync(0xffffffffu, sum, o);
        if (lane == 0) red[8 + warp] = sum;
        __syncthreads();
        float tot = red[8];
        #pragma unroll
        for (int w = 1; w < 8; w++) tot += red[8 + w];
        float inv = 1.0f / tot;

        int d = tid & 63, jg = tid >> 6;
        float acc = 0.f;
        for (int j = jg; j < NTOK; j += 4) acc += ss[j] * Vs[j*65 + d];
        pv[tid] = acc;
        __syncthreads();
        if (tid < DH) {
            float ov = (pv[tid] + pv[tid+64] + pv[tid+128] + pv[tid+192]) * inv;
            out[((long)b*NTOK + i)*DD + h*DH + tid] = __float2half_rn(ov);
        }
        __syncthreads();
    }
}

// ---------------------------------------------------------------------------
// host orchestration
// ---------------------------------------------------------------------------
extern "C" void kernel_launch(void* const* d_in, const int* in_sizes, int n_in,
                              void* d_out, int out_size) {
    const float* x_in    = (const float*)d_in[0];
    const float* conv_w  = (const float*)d_in[1];
    const float* cls_tok = (const float*)d_in[2];
    const float* pos     = (const float*)d_in[3];
    const float* lnprew  = (const float*)d_in[4];
    const float* lnpreb  = (const float*)d_in[5];
    const float* ln1w    = (const float*)d_in[6];
    const float* ln1b    = (const float*)d_in[7];
    const float* qkvw    = (const float*)d_in[8];
    const float* qkvb    = (const float*)d_in[9];
    const float* pw      = (const float*)d_in[10];
    const float* pb      = (const float*)d_in[11];
    const float* ln2w    = (const float*)d_in[12];
    const float* ln2b    = (const float*)d_in[13];
    const float* fw      = (const float*)d_in[14];
    const float* fb      = (const float*)d_in[15];
    const float* cw      = (const float*)d_in[16];
    const float* cb      = (const float*)d_in[17];
    const float* lnpostw = (const float*)d_in[18];
    const float* lnpostb = (const float*)d_in[19];
    const float* projw   = (const float*)d_in[20];
    const float* headw   = (const float*)d_in[21];
    const float* headb   = (const float*)d_in[22];

    float  *gx, *gq, *gpe, *gc, *gz;
    __half *gh, *go, *gm, *gp;
    __half *wconv, *wqkv, *wproj, *wfc, *wcpr;
    cudaGetSymbolAddress((void**)&gx,  g_x);
    cudaGetSymbolAddress((void**)&gq,  g_qkv);
    cudaGetSymbolAddress((void**)&gpe, g_pe);
    cudaGetSymbolAddress((void**)&gc,  g_cls);
    cudaGetSymbolAddress((void**)&gz,  g_z);
    cudaGetSymbolAddress((void**)&gh,  g_h);
    cudaGetSymbolAddress((void**)&go,  g_o);
    cudaGetSymbolAddress((void**)&gm,  g_mlp);
    cudaGetSymbolAddress((void**)&gp,  g_pat);
    cudaGetSymbolAddress((void**)&wconv, g_wconv);
    cudaGetSymbolAddress((void**)&wqkv,  g_wqkv);
    cudaGetSymbolAddress((void**)&wproj, g_wproj);
    cudaGetSymbolAddress((void**)&wfc,   g_wfc);
    cudaGetSymbolAddress((void**)&wcpr,  g_wcpr);

    cudaFuncSetAttribute(attn_kernel, cudaFuncAttributeMaxDynamicSharedMemorySize, ATTN_SMEM);
    cudaFuncSetAttribute(gemm_h<float ,false,false>, cudaFuncAttributeMaxDynamicSharedMemorySize, GH_SMEM);
    cudaFuncSetAttribute(gemm_h<float ,false,true >, cudaFuncAttributeMaxDynamicSharedMemorySize, GH_SMEM);
    cudaFuncSetAttribute(gemm_h<__half,true ,false>, cudaFuncAttributeMaxDynamicSharedMemorySize, GH_SMEM);

    // ---- weight conversion (fp32 -> fp16) ----
    {
        int n;
        n = DD*DD/8;             f2h_kernel<<<(n+255)/256, 256>>>(conv_w, wconv, n);
        n = DEPTH*3*DD*DD/8;     f2h_kernel<<<(n+255)/256, 256>>>(qkvw,  wqkv,  n);
        n = DEPTH*DD*DD/8;       f2h_kernel<<<(n+255)/256, 256>>>(pw,    wproj, n);
        n = DEPTH*MLPD*DD/8;     f2h_kernel<<<(n+255)/256, 256>>>(fw,    wfc,   n);
        n = DEPTH*DD*MLPD/8;     f2h_kernel<<<(n+255)/256, 256>>>(cw,    wcpr,  n);
    }

    const int MB  = (MROWS + 127) / 128;   // 50
    const int MBP = (PROWS + 127) / 128;   // 49

    // ---- patch embed ----
    im2col_kernel<<<(PROWS*DD + 255)/256, 256>>>(x_in);
    gemm_h<float,false,false><<<dim3(DD/128, MBP), 256, GH_SMEM>>>(
        gp, wconv, nullptr, nullptr, gpe, PROWS, DD, DD);
    assemble_kernel<<<(MROWS*DD + 255)/256, 256>>>(gpe, cls_tok, pos);
    ln_kernel<float><<<MROWS, 256>>>(gq, gx, lnprew, lnpreb, DD, DD);

    for (int l = 0; l < DEPTH; l++) {
        // attention sub-block
        ln_kernel<__half><<<MROWS, 256>>>(gx, gh, ln1w + l*DD, ln1b + l*DD, DD, DD);
        gemm_h<float,false,false><<<dim3((3*DD)/128, MB), 256, GH_SMEM>>>(
            gh, wqkv + (size_t)l*3*DD*DD, qkvb + (long)l*3*DD, nullptr, gq, MROWS, 3*DD, DD);
        attn_kernel<<<BB*NH, 256, ATTN_SMEM>>>(gq, go);
        gemm_h<float,false,true><<<dim3(DD/128, MB), 256, GH_SMEM>>>(
            go, wproj + (size_t)l*DD*DD, pb + (long)l*DD, gx, gx, MROWS, DD, DD);
        // MLP sub-block
        ln_kernel<__half><<<MROWS, 256>>>(gx, gh, ln2w + l*DD, ln2b + l*DD, DD, DD);
        gemm_h<__half,true,false><<<dim3(MLPD/128, MB), 256, GH_SMEM>>>(
            gh, wfc + (size_t)l*MLPD*DD, fb + (long)l*MLPD, nullptr, gm, MROWS, MLPD, DD);
        gemm_h<float,false,true><<<dim3(DD/128, MB), 256, GH_SMEM>>>(
            gm, wcpr + (size_t)l*DD*MLPD, cb + (long)l*DD, gx, gx, MROWS, DD, MLPD);
    }

    // ---- head: ln_post on cls rows only, proj, classifier (tiny: SIMT fp32) ----
    ln_kernel<float><<<BB, 256>>>(gx, gc, lnpostw, lnpostb, (long)NTOK*DD, DD);
    gemm_nt<<<dim3(PROJD/64, 1), 256>>>(gc, projw, nullptr, gz, BB, PROJD, DD);
    gemm_nt<<<dim3((NCLS+63)/64, 1), 256>>>(gz, headw, headb, (float*)d_out, BB, NCLS, PROJD);
}

// round 8
// speedup vs baseline: 6.7413x; 2.2108x over previous
#include <cuda_runtime.h>
#include <cuda_fp16.h>
#include <math.h>
#include <stdint.h>

// ---------------------------------------------------------------------------
// CLIP ViT-B/16 forward. Round 7: warp-parallel attention (no in-loop block
// barriers), fp16 K/V in smem. GEMM path = R6 cp.async HMMA (at legacy ceiling).
// ---------------------------------------------------------------------------

#define BB      32
#define NTOK    197
#define NPAT    196
#define DD      768
#define DEPTH   12
#define NH      12
#define DH      64
#define MLPD    3072
#define PROJD   512
#define NCLS    1000
#define MROWS   (BB*NTOK)          // 6304
#define PROWS   (BB*NPAT)          // 6272

// fp32 buffers
__device__ __align__(128) float  g_x   [MROWS*DD];      // residual stream
__device__ __align__(128) float  g_qkv [MROWS*3*DD];    // qkv (also temp for assemble)
__device__ __align__(128) float  g_pe  [PROWS*DD];      // patch embed out
__device__ __align__(128) float  g_cls [BB*DD];
__device__ __align__(128) float  g_z   [BB*PROJD];
// fp16 buffers
__device__ __align__(128) __half g_h   [MROWS*DD];      // LN output (GEMM A)
__device__ __align__(128) __half g_o   [MROWS*DD];      // attention out (GEMM A)
__device__ __align__(128) __half g_mlp [MROWS*MLPD];    // mlp hidden (GEMM A)
__device__ __align__(128) __half g_pat [PROWS*DD];      // im2col patches (GEMM A)
// fp16 weights (converted every launch — determinism)
__device__ __align__(128) __half g_wconv [DD*DD];
__device__ __align__(128) __half g_wqkv  [DEPTH*3*DD*DD];
__device__ __align__(128) __half g_wproj [DEPTH*DD*DD];
__device__ __align__(128) __half g_wfc   [DEPTH*MLPD*DD];
__device__ __align__(128) __half g_wcpr  [DEPTH*DD*MLPD];

// ---------------------------------------------------------------------------
// fp32 -> fp16 weight conversion (8 elems/thread)
// ---------------------------------------------------------------------------
__global__ void f2h_kernel(const float* __restrict__ in, __half* __restrict__ out, int n8) {
    int i = blockIdx.x * 256 + threadIdx.x;
    if (i >= n8) return;
    const float4* p = (const float4*)in + i*2;
    float4 a = p[0], b = p[1];
    __half2 h0 = __floats2half2_rn(a.x, a.y);
    __half2 h1 = __floats2half2_rn(a.z, a.w);
    __half2 h2 = __floats2half2_rn(b.x, b.y);
    __half2 h3 = __floats2half2_rn(b.z, b.w);
    uint4 v;
    v.x = *(uint32_t*)&h0; v.y = *(uint32_t*)&h1;
    v.z = *(uint32_t*)&h2; v.w = *(uint32_t*)&h3;
    ((uint4*)out)[i] = v;
}

// ---------------------------------------------------------------------------
// im2col: gather 16x16x3 patches -> (6272, 768) fp16
// ---------------------------------------------------------------------------
__global__ void im2col_kernel(const float* __restrict__ x) {
    int idx = blockIdx.x * 256 + threadIdx.x;
    if (idx >= PROWS * DD) return;
    int k = idx % DD;
    int m = idx / DD;
    int b = m / NPAT, p = m % NPAT;
    int ph = p / 14, pw = p % 14;
    int c = k >> 8, r = (k >> 4) & 15, col = k & 15;
    g_pat[idx] = __float2half_rn(x[(((long)(b*3 + c)*224 + ph*16 + r)*224) + pw*16 + col]);
}

// ---------------------------------------------------------------------------
// assemble tokens into g_qkv (fp32 temp): cls+pos / pe+pos
// ---------------------------------------------------------------------------
__global__ void assemble_kernel(const float* __restrict__ pe,
                                const float* __restrict__ cls_tok,
                                const float* __restrict__ pos) {
    int idx = blockIdx.x * 256 + threadIdx.x;
    if (idx >= MROWS * DD) return;
    int d = idx % DD;
    int bn = idx / DD;
    int b = bn / NTOK, n = bn % NTOK;
    float v;
    if (n == 0) v = cls_tok[d] + pos[d];
    else        v = pe[((long)b*NPAT + (n-1))*DD + d] + pos[(long)n*DD + d];
    g_qkv[idx] = v;
}

// ---------------------------------------------------------------------------
// LayerNorm over 768, templated output type (float or __half)
// ---------------------------------------------------------------------------
template<typename OutT>
__global__ void ln_kernel(const float* __restrict__ in, OutT* __restrict__ out,
                          const float* __restrict__ gam, const float* __restrict__ bet,
                          long in_stride, long out_stride) {
    __shared__ float red[16];
    int row = blockIdx.x, tid = threadIdx.x;
    const float* xr = in + (long)row * in_stride;
    float v0 = xr[tid], v1 = xr[tid + 256], v2 = xr[tid + 512];
    float s = v0 + v1 + v2;
    #pragma unroll
    for (int o = 16; o; o >>= 1) s += __shfl_xor_sync(0xffffffffu, s, o);
    if ((tid & 31) == 0) red[tid >> 5] = s;
    __syncthreads();
    float tot = red[0]+red[1]+red[2]+red[3]+red[4]+red[5]+red[6]+red[7];
    float mean = tot * (1.0f / 768.0f);
    float d0 = v0 - mean, d1 = v1 - mean, d2 = v2 - mean;
    float q = d0*d0 + d1*d1 + d2*d2;
    #pragma unroll
    for (int o = 16; o; o >>= 1) q += __shfl_xor_sync(0xffffffffu, q, o);
    if ((tid & 31) == 0) red[8 + (tid >> 5)] = q;
    __syncthreads();
    float var = (red[8]+red[9]+red[10]+red[11]+red[12]+red[13]+red[14]+red[15]) * (1.0f/768.0f);
    float rs = rsqrtf(var + 1e-5f);
    OutT* orow = out + (long)row * out_stride;
    orow[tid      ] = (OutT)(d0 * rs * gam[tid      ] + bet[tid      ]);
    orow[tid + 256] = (OutT)(d1 * rs * gam[tid + 256] + bet[tid + 256]);
    orow[tid + 512] = (OutT)(d2 * rs * gam[tid + 512] + bet[tid + 512]);
}

__device__ __forceinline__ float gelu_f(float v) {
    return 0.5f * v * (1.0f + erff(v * 0.70710678118654752f));
}

// ---------------------------------------------------------------------------
// fp16 tensor-core NT GEMM, cp.async 4-stage pipeline (unchanged from R6).
// ---------------------------------------------------------------------------
__device__ __forceinline__ uint32_t smem_u32(const void* p) {
    uint32_t a;
    asm("{ .reg .u64 t; cvta.to.shared.u64 t, %1; cvt.u32.u64 %0, t; }" : "=r"(a) : "l"(p));
    return a;
}

#define LDSM_X4(r0,r1,r2,r3,addr) \
    asm volatile("ldmatrix.sync.aligned.m8n8.x4.shared.b16 {%0,%1,%2,%3}, [%4];" \
                 : "=r"(r0), "=r"(r1), "=r"(r2), "=r"(r3) : "r"(addr))

#define HMMA16816(d, a0,a1,a2,a3, b0,b1) \
    asm volatile("mma.sync.aligned.m16n8k16.row.col.f32.f16.f16.f32 " \
                 "{%0,%1,%2,%3}, {%4,%5,%6,%7}, {%8,%9}, {%0,%1,%2,%3};" \
                 : "+f"((d)[0]), "+f"((d)[1]), "+f"((d)[2]), "+f"((d)[3]) \
                 : "r"(a0), "r"(a1), "r"(a2), "r"(a3), "r"(b0), "r"(b1))

__device__ __forceinline__ void cp16(uint32_t saddr, const void* gaddr) {
    asm volatile("cp.async.cg.shared.global [%0], [%1], 16;" :: "r"(saddr), "l"(gaddr));
}
__device__ __forceinline__ void cp16z(uint32_t saddr, const void* gaddr, int sz) {
    asm volatile("cp.async.cg.shared.global [%0], [%1], 16, %2;" :: "r"(saddr), "l"(gaddr), "r"(sz));
}
#define CP_COMMIT() asm volatile("cp.async.commit_group;" ::: "memory")
#define CP_WAIT2()  asm volatile("cp.async.wait_group 2;" ::: "memory")

#define HSTAGE 20480
#define GH_SMEM (4 * HSTAGE)   // 81920

template<typename OutT, bool GELU, bool RES>
__global__ __launch_bounds__(256, 2)
void gemm_h(const __half* __restrict__ A, const __half* __restrict__ W,
            const float* __restrict__ bias, const float* __restrict__ Rs,
            OutT* __restrict__ Cp, int M, int N, int K) {
    extern __shared__ uint8_t smem[];
    const uint32_t sb = smem_u32(smem);
    const int tid = threadIdx.x, lane = tid & 31, warp = tid >> 5;
    const int wm = warp >> 2, wn = warp & 3;
    const int m0 = blockIdx.y * 128, n0 = blockIdx.x * 128;

    float acc[4][4][4];
    #pragma unroll
    for (int i=0;i<4;i++)
      #pragma unroll
      for (int j=0;j<4;j++)
        #pragma unroll
        for (int f=0;f<4;f++) acc[i][j][f]=0.f;

    const int T = K >> 5;

    const int srow = tid >> 2, sc = tid & 3;
    const int szA0 = (m0 + srow      < M) ? 16 : 0;
    const int szA1 = (m0 + srow + 64 < M) ? 16 : 0;
    const __half* Ag0 = A + (szA0 ? ((size_t)(m0 + srow     ) * K + sc*8) : 0);
    const __half* Ag1 = A + (szA1 ? ((size_t)(m0 + srow + 64) * K + sc*8) : 0);
    const __half* Bg0 = W + (size_t)(n0 + srow     ) * K + sc*8;
    const __half* Bg1 = W + (size_t)(n0 + srow + 64) * K + sc*8;
    const uint32_t sA0 = sb + (uint32_t)srow*80 + sc*16;
    const uint32_t sA1 = sb + (uint32_t)(srow+64)*80 + sc*16;

    auto issue_stage = [&](int t, int s) {
        if (t < T) {
            uint32_t so = (uint32_t)s * HSTAGE;
            int ko = t * 32;
            cp16z(sA0 + so,         Ag0 + (szA0 ? ko : 0), szA0);
            cp16z(sA1 + so,         Ag1 + (szA1 ? ko : 0), szA1);
            cp16 (sA0 + so + 10240, Bg0 + ko);
            cp16 (sA1 + so + 10240, Bg1 + ko);
        }
        CP_COMMIT();
    };

    const uint32_t aoff = (uint32_t)(wm*64 + (lane & 15)) * 80 + (lane >> 4) * 16;
    const uint32_t boff = 10240 + (uint32_t)(wn*32 + (lane & 7) + ((lane >> 4) << 3)) * 80
                        + ((lane >> 3) & 1) * 16;

    issue_stage(0, 0);
    issue_stage(1, 1);
    issue_stage(2, 2);

    for (int t = 0; t < T; t++) {
        CP_WAIT2();
        __syncthreads();
        issue_stage(t + 3, (t + 3) & 3);
        const uint32_t stb = sb + (uint32_t)(t & 3) * HSTAGE;
        #pragma unroll
        for (int kc = 0; kc < 2; kc++) {
            uint32_t af[4][4];
            #pragma unroll
            for (int mt = 0; mt < 4; mt++) {
                uint32_t addr = stb + aoff + mt*16*80 + kc*32;
                LDSM_X4(af[mt][0], af[mt][1], af[mt][2], af[mt][3], addr);
            }
            uint32_t bf[2][4];
            #pragma unroll
            for (int pr = 0; pr < 2; pr++) {
                uint32_t addr = stb + boff + pr*16*80 + kc*32;
                LDSM_X4(bf[pr][0], bf[pr][1], bf[pr][2], bf[pr][3], addr);
            }
            #pragma unroll
            for (int mt = 0; mt < 4; mt++) {
                #pragma unroll
                for (int nt = 0; nt < 4; nt++) {
                    HMMA16816(acc[mt][nt],
                              af[mt][0], af[mt][1], af[mt][2], af[mt][3],
                              bf[nt>>1][(nt&1)*2], bf[nt>>1][(nt&1)*2+1]);
                }
            }
        }
    }

    const int lr = lane >> 2, lc = lane & 3;
    #pragma unroll
    for (int mt = 0; mt < 4; mt++) {
        int r0 = m0 + wm*64 + mt*16 + lr;
        #pragma unroll
        for (int nt = 0; nt < 4; nt++) {
            int cc = n0 + wn*32 + nt*8 + lc*2;
            float v0 = acc[mt][nt][0], v1 = acc[mt][nt][1];
            float v2 = acc[mt][nt][2], v3 = acc[mt][nt][3];
            if (bias) {
                float bb0 = bias[cc], bb1 = bias[cc+1];
                v0 += bb0; v1 += bb1; v2 += bb0; v3 += bb1;
            }
            if (RES) {
                if (r0 < M) {
                    float2 rr = *(const float2*)&Rs[(size_t)r0*N + cc];
                    v0 += rr.x; v1 += rr.y;
                }
                if (r0 + 8 < M) {
                    float2 rr = *(const float2*)&Rs[(size_t)(r0+8)*N + cc];
                    v2 += rr.x; v3 += rr.y;
                }
            }
            if (GELU) { v0 = gelu_f(v0); v1 = gelu_f(v1); v2 = gelu_f(v2); v3 = gelu_f(v3); }
            if (sizeof(OutT) == 4) {
                if (r0 < M)     *(float2*)&(((float*)Cp)[(size_t)r0*N + cc])     = make_float2(v0, v1);
                if (r0 + 8 < M) *(float2*)&(((float*)Cp)[(size_t)(r0+8)*N + cc]) = make_float2(v2, v3);
            } else {
                if (r0 < M) {
                    __half2 h = __floats2half2_rn(v0, v1);
                    *(__half2*)&(((__half*)Cp)[(size_t)r0*N + cc]) = h;
                }
                if (r0 + 8 < M) {
                    __half2 h = __floats2half2_rn(v2, v3);
                    *(__half2*)&(((__half*)Cp)[(size_t)(r0+8)*N + cc]) = h;
                }
            }
        }
    }
}

// ---------------------------------------------------------------------------
// SIMT NT SGEMM for the tiny head GEMMs (M=32), fp32
// ---------------------------------------------------------------------------
__global__ void gemm_nt(const float* __restrict__ A, const float* __restrict__ W,
                        const float* __restrict__ bias, float* __restrict__ C,
                        int M, int N, int K) {
    __shared__ float As[16][64];
    __shared__ float Bs[16][64];
    int tid = threadIdx.x;
    int tx = tid & 15, ty = tid >> 4;
    int m0 = blockIdx.y * 64, n0 = blockIdx.x * 64;
    int lr = tid >> 2;
    int lc = (tid & 3) << 2;
    float acc[4][4] = {};
    const float* Aptr = A + (long)(m0 + lr) * K + lc;
    const float* Wptr = W + (long)(n0 + lr) * K + lc;
    bool am = (m0 + lr) < M;
    bool wn = (n0 + lr) < N;
    for (int k0 = 0; k0 < K; k0 += 16) {
        float4 av = am ? *(const float4*)(Aptr + k0) : make_float4(0.f,0.f,0.f,0.f);
        float4 wv = wn ? *(const float4*)(Wptr + k0) : make_float4(0.f,0.f,0.f,0.f);
        As[lc+0][lr]=av.x; As[lc+1][lr]=av.y; As[lc+2][lr]=av.z; As[lc+3][lr]=av.w;
        Bs[lc+0][lr]=wv.x; Bs[lc+1][lr]=wv.y; Bs[lc+2][lr]=wv.z; Bs[lc+3][lr]=wv.w;
        __syncthreads();
        #pragma unroll
        for (int kk = 0; kk < 16; kk++) {
            float4 a = *(const float4*)(&As[kk][ty << 2]);
            float4 b = *(const float4*)(&Bs[kk][tx << 2]);
            acc[0][0] += a.x*b.x; acc[0][1] += a.x*b.y; acc[0][2] += a.x*b.z; acc[0][3] += a.x*b.w;
            acc[1][0] += a.y*b.x; acc[1][1] += a.y*b.y; acc[1][2] += a.y*b.z; acc[1][3] += a.y*b.w;
            acc[2][0] += a.z*b.x; acc[2][1] += a.z*b.y; acc[2][2] += a.z*b.z; acc[2][3] += a.z*b.w;
            acc[3][0] += a.w*b.x; acc[3][1] += a.w*b.y; acc[3][2] += a.w*b.z; acc[3][3] += a.w*b.w;
        }
        __syncthreads();
    }
    #pragma unroll
    for (int i = 0; i < 4; i++) {
        int m = m0 + (ty << 2) + i;
        if (m >= M) continue;
        #pragma unroll
        for (int j = 0; j < 4; j++) {
            int n = n0 + (tx << 2) + j;
            if (n >= N) continue;
            float v = acc[i][j];
            if (bias) v += bias[n];
            C[(long)m * N + n] = v;
        }
    }
}

// ---------------------------------------------------------------------------
// Warp-parallel fused attention. One block per (b,h); 8 warps; each warp
// processes 2 query tokens per round, 13 rounds, no block barriers in loop.
// K/V staged as fp16 in smem, pitch 66 halves (conflict-free row reads).
// ---------------------------------------------------------------------------
#define APITCH 66
#define AROWS  224                          // 197 rounded up to 7*32
#define ATTN_SMEM (2*AROWS*APITCH*2 + 8*128*4)   // Kh+Vh fp16 + q fp32

__global__ void attn_kernel(const float* __restrict__ qkv, __half* __restrict__ out) {
    int b = blockIdx.x / NH, h = blockIdx.x % NH;
    int tid = threadIdx.x, lane = tid & 31, warp = tid >> 5;
    extern __shared__ char asm_[];
    __half* Kh = (__half*)asm_;                       // AROWS x APITCH
    __half* Vh = Kh + AROWS*APITCH;
    float*  qs = (float*)(Vh + AROWS*APITCH);         // 8 warps x 128

    const float* base = qkv + (size_t)b * NTOK * (3*DD) + h * DH;

    // stage K/V as fp16 (rows >=197 left uninitialized; masked before use)
    for (int idx = tid; idx < NTOK*32; idx += 256) {
        int j = idx >> 5, d2 = (idx & 31) << 1;
        const float* kp = base + (size_t)j*(3*DD) + DD   + d2;
        const float* vp = base + (size_t)j*(3*DD) + 2*DD + d2;
        *(__half2*)&Kh[j*APITCH + d2] = __floats2half2_rn(kp[0], kp[1]);
        *(__half2*)&Vh[j*APITCH + d2] = __floats2half2_rn(vp[0], vp[1]);
    }
    __syncthreads();

    float* qw = qs + warp*128;
    for (int r = 0; r < 13; r++) {
        int i0 = r*16 + warp*2;
        if (i0 >= NTOK) break;
        int i1 = i0 + 1;
        bool v1 = (i1 < NTOK);
        int i1c = v1 ? i1 : i0;
        // stage q0,q1 (fp32) into per-warp smem
        qw[lane]        = base[(size_t)i0*(3*DD) + lane];
        qw[lane + 32]   = base[(size_t)i0*(3*DD) + lane + 32];
        qw[64 + lane]      = base[(size_t)i1c*(3*DD) + lane];
        qw[64 + lane + 32] = base[(size_t)i1c*(3*DD) + lane + 32];
        __syncwarp();

        // dots: lane owns keys j = lane + 32g
        float a0[7], a1[7];
        #pragma unroll
        for (int g = 0; g < 7; g++) { a0[g] = 0.f; a1[g] = 0.f; }
        #pragma unroll 8
        for (int d2 = 0; d2 < 32; d2++) {
            float2 q0 = *(const float2*)&qw[d2*2];
            float2 q1 = *(const float2*)&qw[64 + d2*2];
            #pragma unroll
            for (int g = 0; g < 7; g++) {
                __half2 kv = *(const __half2*)&Kh[(lane + g*32)*APITCH + d2*2];
                float2 kf = __half22float2(kv);
                a0[g] += q0.x*kf.x + q0.y*kf.y;
                a1[g] += q1.x*kf.x + q1.y*kf.y;
            }
        }
        // mask + softmax (per query, warp-wide)
        float s0[7], s1[7];
        #pragma unroll
        for (int g = 0; g < 7; g++) {
            bool ok = (lane + g*32) < NTOK;
            s0[g] = ok ? a0[g]*0.125f : -1e30f;
            s1[g] = ok ? a1[g]*0.125f : -1e30f;
        }
        float m0 = s0[0], m1 = s1[0];
        #pragma unroll
        for (int g = 1; g < 7; g++) { m0 = fmaxf(m0, s0[g]); m1 = fmaxf(m1, s1[g]); }
        #pragma unroll
        for (int o = 16; o; o >>= 1) {
            m0 = fmaxf(m0, __shfl_xor_sync(0xffffffffu, m0, o));
            m1 = fmaxf(m1, __shfl_xor_sync(0xffffffffu, m1, o));
        }
        float p0[7], p1[7], t0 = 0.f, t1 = 0.f;
        #pragma unroll
        for (int g = 0; g < 7; g++) {
            p0[g] = expf(s0[g] - m0); t0 += p0[g];
            p1[g] = expf(s1[g] - m1); t1 += p1[g];
        }
        #pragma unroll
        for (int o = 16; o; o >>= 1) {
            t0 += __shfl_xor_sync(0xffffffffu, t0, o);
            t1 += __shfl_xor_sync(0xffffffffu, t1, o);
        }
        float inv0 = 1.f / t0, inv1 = 1.f / t1;

        // PV: lane owns output dims 2*lane, 2*lane+1
        float o00 = 0.f, o01 = 0.f, o10 = 0.f, o11 = 0.f;
        #pragma unroll
        for (int g = 0; g < 7; g++) {
            const int cnt = (g == 6) ? (NTOK - 192) : 32;
            const __half* vb = &Vh[(g*32)*APITCH + lane*2];
            for (int l = 0; l < cnt; l++) {
                float pj0 = __shfl_sync(0xffffffffu, p0[g], l);
                float pj1 = __shfl_sync(0xffffffffu, p1[g], l);
                float2 vf = __half22float2(*(const __half2*)&vb[l*APITCH]);
                o00 += pj0*vf.x; o01 += pj0*vf.y;
                o10 += pj1*vf.x; o11 += pj1*vf.y;
            }
        }
        size_t ob = ((size_t)b*NTOK + i0)*DD + h*DH + lane*2;
        *(__half2*)&out[ob] = __floats2half2_rn(o00*inv0, o01*inv0);
        if (v1) *(__half2*)&out[ob + DD] = __floats2half2_rn(o10*inv1, o11*inv1);
    }
}

// ---------------------------------------------------------------------------
// host orchestration
// ---------------------------------------------------------------------------
extern "C" void kernel_launch(void* const* d_in, const int* in_sizes, int n_in,
                              void* d_out, int out_size) {
    const float* x_in    = (const float*)d_in[0];
    const float* conv_w  = (const float*)d_in[1];
    const float* cls_tok = (const float*)d_in[2];
    const float* pos     = (const float*)d_in[3];
    const float* lnprew  = (const float*)d_in[4];
    const float* lnpreb  = (const float*)d_in[5];
    const float* ln1w    = (const float*)d_in[6];
    const float* ln1b    = (const float*)d_in[7];
    const float* qkvw    = (const float*)d_in[8];
    const float* qkvb    = (const float*)d_in[9];
    const float* pw      = (const float*)d_in[10];
    const float* pb      = (const float*)d_in[11];
    const float* ln2w    = (const float*)d_in[12];
    const float* ln2b    = (const float*)d_in[13];
    const float* fw      = (const float*)d_in[14];
    const float* fb      = (const float*)d_in[15];
    const float* cw      = (const float*)d_in[16];
    const float* cb      = (const float*)d_in[17];
    const float* lnpostw = (const float*)d_in[18];
    const float* lnpostb = (const float*)d_in[19];
    const float* projw   = (const float*)d_in[20];
    const float* headw   = (const float*)d_in[21];
    const float* headb   = (const float*)d_in[22];

    float  *gx, *gq, *gpe, *gc, *gz;
    __half *gh, *go, *gm, *gp;
    __half *wconv, *wqkv, *wproj, *wfc, *wcpr;
    cudaGetSymbolAddress((void**)&gx,  g_x);
    cudaGetSymbolAddress((void**)&gq,  g_qkv);
    cudaGetSymbolAddress((void**)&gpe, g_pe);
    cudaGetSymbolAddress((void**)&gc,  g_cls);
    cudaGetSymbolAddress((void**)&gz,  g_z);
    cudaGetSymbolAddress((void**)&gh,  g_h);
    cudaGetSymbolAddress((void**)&go,  g_o);
    cudaGetSymbolAddress((void**)&gm,  g_mlp);
    cudaGetSymbolAddress((void**)&gp,  g_pat);
    cudaGetSymbolAddress((void**)&wconv, g_wconv);
    cudaGetSymbolAddress((void**)&wqkv,  g_wqkv);
    cudaGetSymbolAddress((void**)&wproj, g_wproj);
    cudaGetSymbolAddress((void**)&wfc,   g_wfc);
    cudaGetSymbolAddress((void**)&wcpr,  g_wcpr);

    cudaFuncSetAttribute(attn_kernel, cudaFuncAttributeMaxDynamicSharedMemorySize, ATTN_SMEM);
    cudaFuncSetAttribute(gemm_h<float ,false,false>, cudaFuncAttributeMaxDynamicSharedMemorySize, GH_SMEM);
    cudaFuncSetAttribute(gemm_h<float ,false,true >, cudaFuncAttributeMaxDynamicSharedMemorySize, GH_SMEM);
    cudaFuncSetAttribute(gemm_h<__half,true ,false>, cudaFuncAttributeMaxDynamicSharedMemorySize, GH_SMEM);

    // ---- weight conversion (fp32 -> fp16) ----
    {
        int n;
        n = DD*DD/8;             f2h_kernel<<<(n+255)/256, 256>>>(conv_w, wconv, n);
        n = DEPTH*3*DD*DD/8;     f2h_kernel<<<(n+255)/256, 256>>>(qkvw,  wqkv,  n);
        n = DEPTH*DD*DD/8;       f2h_kernel<<<(n+255)/256, 256>>>(pw,    wproj, n);
        n = DEPTH*MLPD*DD/8;     f2h_kernel<<<(n+255)/256, 256>>>(fw,    wfc,   n);
        n = DEPTH*DD*MLPD/8;     f2h_kernel<<<(n+255)/256, 256>>>(cw,    wcpr,  n);
    }

    const int MB  = (MROWS + 127) / 128;   // 50
    const int MBP = (PROWS + 127) / 128;   // 49

    // ---- patch embed ----
    im2col_kernel<<<(PROWS*DD + 255)/256, 256>>>(x_in);
    gemm_h<float,false,false><<<dim3(DD/128, MBP), 256, GH_SMEM>>>(
        gp, wconv, nullptr, nullptr, gpe, PROWS, DD, DD);
    assemble_kernel<<<(MROWS*DD + 255)/256, 256>>>(gpe, cls_tok, pos);
    ln_kernel<float><<<MROWS, 256>>>(gq, gx, lnprew, lnpreb, DD, DD);

    for (int l = 0; l < DEPTH; l++) {
        // attention sub-block
        ln_kernel<__half><<<MROWS, 256>>>(gx, gh, ln1w + l*DD, ln1b + l*DD, DD, DD);
        gemm_h<float,false,false><<<dim3((3*DD)/128, MB), 256, GH_SMEM>>>(
            gh, wqkv + (size_t)l*3*DD*DD, qkvb + (long)l*3*DD, nullptr, gq, MROWS, 3*DD, DD);
        attn_kernel<<<BB*NH, 256, ATTN_SMEM>>>(gq, go);
        gemm_h<float,false,true><<<dim3(DD/128, MB), 256, GH_SMEM>>>(
            go, wproj + (size_t)l*DD*DD, pb + (long)l*DD, gx, gx, MROWS, DD, DD);
        // MLP sub-block
        ln_kernel<__half><<<MROWS, 256>>>(gx, gh, ln2w + l*DD, ln2b + l*DD, DD, DD);
        gemm_h<__half,true,false><<<dim3(MLPD/128, MB), 256, GH_SMEM>>>(
            gh, wfc + (size_t)l*MLPD*DD, fb + (long)l*MLPD, nullptr, gm, MROWS, MLPD, DD);
        gemm_h<float,false,true><<<dim3(DD/128, MB), 256, GH_SMEM>>>(
            gm, wcpr + (size_t)l*DD*MLPD, cb + (long)l*DD, gx, gx, MROWS, DD, MLPD);
    }

    // ---- head: ln_post on cls rows only, proj, classifier (tiny: SIMT fp32) ----
    ln_kernel<float><<<BB, 256>>>(gx, gc, lnpostw, lnpostb, (long)NTOK*DD, DD);
    gemm_nt<<<dim3(PROJD/64, 1), 256>>>(gc, projw, nullptr, gz, BB, PROJD, DD);
    gemm_nt<<<dim3((NCLS+63)/64, 1), 256>>>(gz, headw, headb, (float*)d_out, BB, NCLS, PROJD);
}

// round 10
// speedup vs baseline: 6.7470x; 1.0008x over previous
#include <cuda_runtime.h>
#include <cuda_fp16.h>
#include <math.h>
#include <stdint.h>

// ---------------------------------------------------------------------------
// CLIP ViT-B/16 forward. Round 9: R8 + tail-tile fix (32 rows -> mt=0,1).
// ---------------------------------------------------------------------------

#define BB      32
#define NTOK    197
#define NPAT    196
#define DD      768
#define DEPTH   12
#define NH      12
#define DH      64
#define MLPD    3072
#define PROJD   512
#define NCLS    1000
#define MROWS   (BB*NTOK)          // 6304
#define PROWS   (BB*NPAT)          // 6272

// fp32 buffers
__device__ __align__(128) float  g_x   [MROWS*DD];      // residual stream
__device__ __align__(128) float  g_pe  [PROWS*DD];      // patch embed out
__device__ __align__(128) float  g_cls [BB*DD];
__device__ __align__(128) float  g_z   [BB*PROJD];
// fp16 buffers
__device__ __align__(128) __half g_qkv [MROWS*3*DD];
__device__ __align__(128) __half g_h   [MROWS*DD];
__device__ __align__(128) __half g_o   [MROWS*DD];
__device__ __align__(128) __half g_mlp [MROWS*MLPD];
__device__ __align__(128) __half g_pat [PROWS*DD];
// fp16 weights (converted every launch — determinism)
__device__ __align__(128) __half g_wconv [DD*DD];
__device__ __align__(128) __half g_wqkv  [DEPTH*3*DD*DD];
__device__ __align__(128) __half g_wproj [DEPTH*DD*DD];
__device__ __align__(128) __half g_wfc   [DEPTH*MLPD*DD];
__device__ __align__(128) __half g_wcpr  [DEPTH*DD*MLPD];

// ---------------------------------------------------------------------------
// merged fp32 -> fp16 weight conversion (all 5 weight tensors, one launch)
// ---------------------------------------------------------------------------
#define F2H_C0 (DD*DD/8)
#define F2H_C1 (F2H_C0 + DEPTH*3*DD*DD/8)
#define F2H_C2 (F2H_C1 + DEPTH*DD*DD/8)
#define F2H_C3 (F2H_C2 + DEPTH*MLPD*DD/8)
#define F2H_C4 (F2H_C3 + DEPTH*DD*MLPD/8)

__global__ void f2h_all_kernel(const float* __restrict__ s0, __half* d0,
                               const float* __restrict__ s1, __half* d1,
                               const float* __restrict__ s2, __half* d2,
                               const float* __restrict__ s3, __half* d3,
                               const float* __restrict__ s4, __half* d4) {
    int i = blockIdx.x * 256 + threadIdx.x;
    if (i >= F2H_C4) return;
    const float* src; __half* dst; int off;
    if      (i < F2H_C0) { src = s0; dst = d0; off = i; }
    else if (i < F2H_C1) { src = s1; dst = d1; off = i - F2H_C0; }
    else if (i < F2H_C2) { src = s2; dst = d2; off = i - F2H_C1; }
    else if (i < F2H_C3) { src = s3; dst = d3; off = i - F2H_C2; }
    else                 { src = s4; dst = d4; off = i - F2H_C3; }
    const float4* p = (const float4*)src + (size_t)off*2;
    float4 a = p[0], b = p[1];
    __half2 h0 = __floats2half2_rn(a.x, a.y);
    __half2 h1 = __floats2half2_rn(a.z, a.w);
    __half2 h2 = __floats2half2_rn(b.x, b.y);
    __half2 h3 = __floats2half2_rn(b.z, b.w);
    uint4 v;
    v.x = *(uint32_t*)&h0; v.y = *(uint32_t*)&h1;
    v.z = *(uint32_t*)&h2; v.w = *(uint32_t*)&h3;
    ((uint4*)dst)[off] = v;
}

// ---------------------------------------------------------------------------
// im2col: gather 16x16x3 patches -> (6272, 768) fp16
// ---------------------------------------------------------------------------
__global__ void im2col_kernel(const float* __restrict__ x) {
    int idx = blockIdx.x * 256 + threadIdx.x;
    if (idx >= PROWS * DD) return;
    int k = idx % DD;
    int m = idx / DD;
    int b = m / NPAT, p = m % NPAT;
    int ph = p / 14, pw = p % 14;
    int c = k >> 8, r = (k >> 4) & 15, col = k & 15;
    g_pat[idx] = __float2half_rn(x[(((long)(b*3 + c)*224 + ph*16 + r)*224) + pw*16 + col]);
}

// ---------------------------------------------------------------------------
// fused assemble + ln_pre
// ---------------------------------------------------------------------------
__global__ void assemble_ln_kernel(const float* __restrict__ pe,
                                   const float* __restrict__ cls_tok,
                                   const float* __restrict__ pos,
                                   const float* __restrict__ gam,
                                   const float* __restrict__ bet,
                                   float* __restrict__ out) {
    __shared__ float red[16];
    int row = blockIdx.x, tid = threadIdx.x;
    int b = row / NTOK, n = row % NTOK;
    float v0, v1, v2;
    if (n == 0) {
        v0 = cls_tok[tid      ] + pos[tid      ];
        v1 = cls_tok[tid + 256] + pos[tid + 256];
        v2 = cls_tok[tid + 512] + pos[tid + 512];
    } else {
        const float* per = pe + ((size_t)b*NPAT + (n-1))*DD;
        const float* por = pos + (size_t)n*DD;
        v0 = per[tid      ] + por[tid      ];
        v1 = per[tid + 256] + por[tid + 256];
        v2 = per[tid + 512] + por[tid + 512];
    }
    float s = v0 + v1 + v2;
    #pragma unroll
    for (int o = 16; o; o >>= 1) s += __shfl_xor_sync(0xffffffffu, s, o);
    if ((tid & 31) == 0) red[tid >> 5] = s;
    __syncthreads();
    float tot = red[0]+red[1]+red[2]+red[3]+red[4]+red[5]+red[6]+red[7];
    float mean = tot * (1.0f / 768.0f);
    float d0 = v0 - mean, d1 = v1 - mean, d2 = v2 - mean;
    float q = d0*d0 + d1*d1 + d2*d2;
    #pragma unroll
    for (int o = 16; o; o >>= 1) q += __shfl_xor_sync(0xffffffffu, q, o);
    if ((tid & 31) == 0) red[8 + (tid >> 5)] = q;
    __syncthreads();
    float var = (red[8]+red[9]+red[10]+red[11]+red[12]+red[13]+red[14]+red[15]) * (1.0f/768.0f);
    float rs = rsqrtf(var + 1e-5f);
    float* orow = out + (size_t)row * DD;
    orow[tid      ] = d0 * rs * gam[tid      ] + bet[tid      ];
    orow[tid + 256] = d1 * rs * gam[tid + 256] + bet[tid + 256];
    orow[tid + 512] = d2 * rs * gam[tid + 512] + bet[tid + 512];
}

// ---------------------------------------------------------------------------
// LayerNorm over 768, templated output type (float or __half)
// ---------------------------------------------------------------------------
template<typename OutT>
__global__ void ln_kernel(const float* __restrict__ in, OutT* __restrict__ out,
                          const float* __restrict__ gam, const float* __restrict__ bet,
                          long in_stride, long out_stride) {
    __shared__ float red[16];
    int row = blockIdx.x, tid = threadIdx.x;
    const float* xr = in + (long)row * in_stride;
    float v0 = xr[tid], v1 = xr[tid + 256], v2 = xr[tid + 512];
    float s = v0 + v1 + v2;
    #pragma unroll
    for (int o = 16; o; o >>= 1) s += __shfl_xor_sync(0xffffffffu, s, o);
    if ((tid & 31) == 0) red[tid >> 5] = s;
    __syncthreads();
    float tot = red[0]+red[1]+red[2]+red[3]+red[4]+red[5]+red[6]+red[7];
    float mean = tot * (1.0f / 768.0f);
    float d0 = v0 - mean, d1 = v1 - mean, d2 = v2 - mean;
    float q = d0*d0 + d1*d1 + d2*d2;
    #pragma unroll
    for (int o = 16; o; o >>= 1) q += __shfl_xor_sync(0xffffffffu, q, o);
    if ((tid & 31) == 0) red[8 + (tid >> 5)] = q;
    __syncthreads();
    float var = (red[8]+red[9]+red[10]+red[11]+red[12]+red[13]+red[14]+red[15]) * (1.0f/768.0f);
    float rs = rsqrtf(var + 1e-5f);
    OutT* orow = out + (long)row * out_stride;
    orow[tid      ] = (OutT)(d0 * rs * gam[tid      ] + bet[tid      ]);
    orow[tid + 256] = (OutT)(d1 * rs * gam[tid + 256] + bet[tid + 256]);
    orow[tid + 512] = (OutT)(d2 * rs * gam[tid + 512] + bet[tid + 512]);
}

__device__ __forceinline__ float gelu_f(float v) {
    return 0.5f * v * (1.0f + erff(v * 0.70710678118654752f));
}

// ---------------------------------------------------------------------------
// fp16 tensor-core NT GEMM, cp.async 4-stage pipeline + short tail M-tile.
// blockIdx.y == 0 -> tail tile (rows floor(M/128)*128 .. M, up to 32 rows):
//   wm==0 warps compute mt=0,1 (rows 0..31 of the tile).
// blockIdx.y >= 1 -> full 128-row tile at (blockIdx.y-1)*128.
// ---------------------------------------------------------------------------
__device__ __forceinline__ uint32_t smem_u32(const void* p) {
    uint32_t a;
    asm("{ .reg .u64 t; cvta.to.shared.u64 t, %1; cvt.u32.u64 %0, t; }" : "=r"(a) : "l"(p));
    return a;
}

#define LDSM_X4(r0,r1,r2,r3,addr) \
    asm volatile("ldmatrix.sync.aligned.m8n8.x4.shared.b16 {%0,%1,%2,%3}, [%4];" \
                 : "=r"(r0), "=r"(r1), "=r"(r2), "=r"(r3) : "r"(addr))

#define HMMA16816(d, a0,a1,a2,a3, b0,b1) \
    asm volatile("mma.sync.aligned.m16n8k16.row.col.f32.f16.f16.f32 " \
                 "{%0,%1,%2,%3}, {%4,%5,%6,%7}, {%8,%9}, {%0,%1,%2,%3};" \
                 : "+f"((d)[0]), "+f"((d)[1]), "+f"((d)[2]), "+f"((d)[3]) \
                 : "r"(a0), "r"(a1), "r"(a2), "r"(a3), "r"(b0), "r"(b1))

__device__ __forceinline__ void cp16(uint32_t saddr, const void* gaddr) {
    asm volatile("cp.async.cg.shared.global [%0], [%1], 16;" :: "r"(saddr), "l"(gaddr));
}
__device__ __forceinline__ void cp16z(uint32_t saddr, const void* gaddr, int sz) {
    asm volatile("cp.async.cg.shared.global [%0], [%1], 16, %2;" :: "r"(saddr), "l"(gaddr), "r"(sz));
}
#define CP_COMMIT() asm volatile("cp.async.commit_group;" ::: "memory")
#define CP_WAIT2()  asm volatile("cp.async.wait_group 2;" ::: "memory")

#define HSTAGE 20480
#define GH_SMEM (4 * HSTAGE)   // 81920

template<typename OutT, bool GELU, bool RES>
__global__ __launch_bounds__(256, 2)
void gemm_h(const __half* __restrict__ A, const __half* __restrict__ W,
            const float* __restrict__ bias, const float* __restrict__ Rs,
            OutT* __restrict__ Cp, int M, int N, int K) {
    extern __shared__ uint8_t smem[];
    const uint32_t sb = smem_u32(smem);
    const int tid = threadIdx.x, lane = tid & 31, warp = tid >> 5;
    const int wm = warp >> 2, wn = warp & 3;
    const int by = blockIdx.y;
    const bool tail = (by == 0);
    const int m0 = tail ? ((M >> 7) << 7) : ((by - 1) << 7);
    const int n0 = blockIdx.x * 128;

    float acc[4][4][4];
    #pragma unroll
    for (int i=0;i<4;i++)
      #pragma unroll
      for (int j=0;j<4;j++)
        #pragma unroll
        for (int f=0;f<4;f++) acc[i][j][f]=0.f;

    const int T = K >> 5;

    const int srow = tid >> 2, sc = tid & 3;
    const int szA0 = (m0 + srow      < M) ? 16 : 0;
    const int szA1 = (m0 + srow + 64 < M) ? 16 : 0;
    const __half* Ag0 = A + (szA0 ? ((size_t)(m0 + srow     ) * K + sc*8) : 0);
    const __half* Ag1 = A + (szA1 ? ((size_t)(m0 + srow + 64) * K + sc*8) : 0);
    const __half* Bg0 = W + (size_t)(n0 + srow     ) * K + sc*8;
    const __half* Bg1 = W + (size_t)(n0 + srow + 64) * K + sc*8;
    const uint32_t sA0 = sb + (uint32_t)srow*80 + sc*16;
    const uint32_t sA1 = sb + (uint32_t)(srow+64)*80 + sc*16;

    auto issue_stage = [&](int t, int s) {
        if (t < T) {
            uint32_t so = (uint32_t)s * HSTAGE;
            int ko = t * 32;
            cp16z(sA0 + so,         Ag0 + (szA0 ? ko : 0), szA0);
            if (!tail) cp16z(sA1 + so, Ag1 + (szA1 ? ko : 0), szA1);
            cp16 (sA0 + so + 10240, Bg0 + ko);
            cp16 (sA1 + so + 10240, Bg1 + ko);
        }
        CP_COMMIT();
    };

    const uint32_t aoff = (uint32_t)(wm*64 + (lane & 15)) * 80 + (lane >> 4) * 16;
    const uint32_t boff = 10240 + (uint32_t)(wn*32 + (lane & 7) + ((lane >> 4) << 3)) * 80
                        + ((lane >> 3) & 1) * 16;

    issue_stage(0, 0);
    issue_stage(1, 1);
    issue_stage(2, 2);

    if (tail) {
        // tail rows <= 32: wm==0 warps compute mt=0 and mt=1 (rows 0..31)
        for (int t = 0; t < T; t++) {
            CP_WAIT2();
            __syncthreads();
            issue_stage(t + 3, (t + 3) & 3);
            const uint32_t stb = sb + (uint32_t)(t & 3) * HSTAGE;
            if (wm == 0) {
                #pragma unroll
                for (int kc = 0; kc < 2; kc++) {
                    uint32_t af[2][4];
                    #pragma unroll
                    for (int mt = 0; mt < 2; mt++) {
                        uint32_t addr = stb + aoff + mt*16*80 + kc*32;
                        LDSM_X4(af[mt][0], af[mt][1], af[mt][2], af[mt][3], addr);
                    }
                    uint32_t bf[2][4];
                    #pragma unroll
                    for (int pr = 0; pr < 2; pr++) {
                        uint32_t addr = stb + boff + pr*16*80 + kc*32;
                        LDSM_X4(bf[pr][0], bf[pr][1], bf[pr][2], bf[pr][3], addr);
                    }
                    #pragma unroll
                    for (int mt = 0; mt < 2; mt++)
                        #pragma unroll
                        for (int nt = 0; nt < 4; nt++)
                            HMMA16816(acc[mt][nt],
                                      af[mt][0], af[mt][1], af[mt][2], af[mt][3],
                                      bf[nt>>1][(nt&1)*2], bf[nt>>1][(nt&1)*2+1]);
                }
            }
        }
    } else {
        for (int t = 0; t < T; t++) {
            CP_WAIT2();
            __syncthreads();
            issue_stage(t + 3, (t + 3) & 3);
            const uint32_t stb = sb + (uint32_t)(t & 3) * HSTAGE;
            #pragma unroll
            for (int kc = 0; kc < 2; kc++) {
                uint32_t af[4][4];
                #pragma unroll
                for (int mt = 0; mt < 4; mt++) {
                    uint32_t addr = stb + aoff + mt*16*80 + kc*32;
                    LDSM_X4(af[mt][0], af[mt][1], af[mt][2], af[mt][3], addr);
                }
                uint32_t bf[2][4];
                #pragma unroll
                for (int pr = 0; pr < 2; pr++) {
                    uint32_t addr = stb + boff + pr*16*80 + kc*32;
                    LDSM_X4(bf[pr][0], bf[pr][1], bf[pr][2], bf[pr][3], addr);
                }
                #pragma unroll
                for (int mt = 0; mt < 4; mt++) {
                    #pragma unroll
                    for (int nt = 0; nt < 4; nt++) {
                        HMMA16816(acc[mt][nt],
                                  af[mt][0], af[mt][1], af[mt][2], af[mt][3],
                                  bf[nt>>1][(nt&1)*2], bf[nt>>1][(nt&1)*2+1]);
                    }
                }
            }
        }
    }

    // ---- epilogue ----
    const int lr = lane >> 2, lc = lane & 3;
    if (tail && wm != 0) return;
    const int mtN = tail ? 2 : 4;
    for (int mt = 0; mt < mtN; mt++) {
        int r0 = m0 + wm*64 + mt*16 + lr;
        #pragma unroll
        for (int nt = 0; nt < 4; nt++) {
            int cc = n0 + wn*32 + nt*8 + lc*2;
            float v0 = acc[mt][nt][0], v1 = acc[mt][nt][1];
            float v2 = acc[mt][nt][2], v3 = acc[mt][nt][3];
            if (bias) {
                float bb0 = bias[cc], bb1 = bias[cc+1];
                v0 += bb0; v1 += bb1; v2 += bb0; v3 += bb1;
            }
            if (RES) {
                if (r0 < M) {
                    float2 rr = *(const float2*)&Rs[(size_t)r0*N + cc];
                    v0 += rr.x; v1 += rr.y;
                }
                if (r0 + 8 < M) {
                    float2 rr = *(const float2*)&Rs[(size_t)(r0+8)*N + cc];
                    v2 += rr.x; v3 += rr.y;
                }
            }
            if (GELU) { v0 = gelu_f(v0); v1 = gelu_f(v1); v2 = gelu_f(v2); v3 = gelu_f(v3); }
            if (sizeof(OutT) == 4) {
                if (r0 < M)     *(float2*)&(((float*)Cp)[(size_t)r0*N + cc])     = make_float2(v0, v1);
                if (r0 + 8 < M) *(float2*)&(((float*)Cp)[(size_t)(r0+8)*N + cc]) = make_float2(v2, v3);
            } else {
                if (r0 < M) {
                    __half2 h = __floats2half2_rn(v0, v1);
                    *(__half2*)&(((__half*)Cp)[(size_t)r0*N + cc]) = h;
                }
                if (r0 + 8 < M) {
                    __half2 h = __floats2half2_rn(v2, v3);
                    *(__half2*)&(((__half*)Cp)[(size_t)(r0+8)*N + cc]) = h;
                }
            }
        }
    }
}

// ---------------------------------------------------------------------------
// SIMT NT SGEMM for the tiny head GEMMs (M=32), fp32
// ---------------------------------------------------------------------------
__global__ void gemm_nt(const float* __restrict__ A, const float* __restrict__ W,
                        const float* __restrict__ bias, float* __restrict__ C,
                        int M, int N, int K) {
    __shared__ float As[16][64];
    __shared__ float Bs[16][64];
    int tid = threadIdx.x;
    int tx = tid & 15, ty = tid >> 4;
    int m0 = blockIdx.y * 64, n0 = blockIdx.x * 64;
    int lr = tid >> 2;
    int lc = (tid & 3) << 2;
    float acc[4][4] = {};
    const float* Aptr = A + (long)(m0 + lr) * K + lc;
    const float* Wptr = W + (long)(n0 + lr) * K + lc;
    bool am = (m0 + lr) < M;
    bool wn = (n0 + lr) < N;
    for (int k0 = 0; k0 < K; k0 += 16) {
        float4 av = am ? *(const float4*)(Aptr + k0) : make_float4(0.f,0.f,0.f,0.f);
        float4 wv = wn ? *(const float4*)(Wptr + k0) : make_float4(0.f,0.f,0.f,0.f);
        As[lc+0][lr]=av.x; As[lc+1][lr]=av.y; As[lc+2][lr]=av.z; As[lc+3][lr]=av.w;
        Bs[lc+0][lr]=wv.x; Bs[lc+1][lr]=wv.y; Bs[lc+2][lr]=wv.z; Bs[lc+3][lr]=wv.w;
        __syncthreads();
        #pragma unroll
        for (int kk = 0; kk < 16; kk++) {
            float4 a = *(const float4*)(&As[kk][ty << 2]);
            float4 b = *(const float4*)(&Bs[kk][tx << 2]);
            acc[0][0] += a.x*b.x; acc[0][1] += a.x*b.y; acc[0][2] += a.x*b.z; acc[0][3] += a.x*b.w;
            acc[1][0] += a.y*b.x; acc[1][1] += a.y*b.y; acc[1][2] += a.y*b.z; acc[1][3] += a.y*b.w;
            acc[2][0] += a.z*b.x; acc[2][1] += a.z*b.y; acc[2][2] += a.z*b.z; acc[2][3] += a.z*b.w;
            acc[3][0] += a.w*b.x; acc[3][1] += a.w*b.y; acc[3][2] += a.w*b.z; acc[3][3] += a.w*b.w;
        }
        __syncthreads();
    }
    #pragma unroll
    for (int i = 0; i < 4; i++) {
        int m = m0 + (ty << 2) + i;
        if (m >= M) continue;
        #pragma unroll
        for (int j = 0; j < 4; j++) {
            int n = n0 + (tx << 2) + j;
            if (n >= N) continue;
            float v = acc[i][j];
            if (bias) v += bias[n];
            C[(long)m * N + n] = v;
        }
    }
}

// ---------------------------------------------------------------------------
// Warp-parallel fused attention (fp16 qkv input).
// ---------------------------------------------------------------------------
#define APITCH 66
#define AROWS  224
#define ATTN_SMEM (2*AROWS*APITCH*2 + 8*128*4)

__global__ void attn_kernel(const __half* __restrict__ qkv, __half* __restrict__ out) {
    int b = blockIdx.x / NH, h = blockIdx.x % NH;
    int tid = threadIdx.x, lane = tid & 31, warp = tid >> 5;
    extern __shared__ char asm_[];
    __half* Kh = (__half*)asm_;
    __half* Vh = Kh + AROWS*APITCH;
    float*  qs = (float*)(Vh + AROWS*APITCH);

    const __half* base = qkv + (size_t)b * NTOK * (3*DD) + h * DH;

    for (int idx = tid; idx < NTOK*32; idx += 256) {
        int j = idx >> 5, d2 = (idx & 31) << 1;
        *(uint32_t*)&Kh[j*APITCH + d2] = *(const uint32_t*)&base[(size_t)j*(3*DD) + DD   + d2];
        *(uint32_t*)&Vh[j*APITCH + d2] = *(const uint32_t*)&base[(size_t)j*(3*DD) + 2*DD + d2];
    }
    __syncthreads();

    float* qw = qs + warp*128;
    for (int r = 0; r < 13; r++) {
        int i0 = r*16 + warp*2;
        if (i0 >= NTOK) break;
        int i1 = i0 + 1;
        bool v1 = (i1 < NTOK);
        int i1c = v1 ? i1 : i0;
        {
            float2 q0a = __half22float2(*(const __half2*)&base[(size_t)i0 *(3*DD) + lane*2]);
            float2 q1a = __half22float2(*(const __half2*)&base[(size_t)i1c*(3*DD) + lane*2]);
            qw[lane*2]        = q0a.x; qw[lane*2+1]      = q0a.y;
            qw[64 + lane*2]   = q1a.x; qw[64 + lane*2+1] = q1a.y;
        }
        __syncwarp();

        float a0[7], a1[7];
        #pragma unroll
        for (int g = 0; g < 7; g++) { a0[g] = 0.f; a1[g] = 0.f; }
        #pragma unroll 8
        for (int d2 = 0; d2 < 32; d2++) {
            float2 q0 = *(const float2*)&qw[d2*2];
            float2 q1 = *(const float2*)&qw[64 + d2*2];
            #pragma unroll
            for (int g = 0; g < 7; g++) {
                __half2 kv = *(const __half2*)&Kh[(lane + g*32)*APITCH + d2*2];
                float2 kf = __half22float2(kv);
                a0[g] += q0.x*kf.x + q0.y*kf.y;
                a1[g] += q1.x*kf.x + q1.y*kf.y;
            }
        }
        float s0[7], s1[7];
        #pragma unroll
        for (int g = 0; g < 7; g++) {
            bool ok = (lane + g*32) < NTOK;
            s0[g] = ok ? a0[g]*0.125f : -1e30f;
            s1[g] = ok ? a1[g]*0.125f : -1e30f;
        }
        float m0 = s0[0], m1 = s1[0];
        #pragma unroll
        for (int g = 1; g < 7; g++) { m0 = fmaxf(m0, s0[g]); m1 = fmaxf(m1, s1[g]); }
        #pragma unroll
        for (int o = 16; o; o >>= 1) {
            m0 = fmaxf(m0, __shfl_xor_sync(0xffffffffu, m0, o));
            m1 = fmaxf(m1, __shfl_xor_sync(0xffffffffu, m1, o));
        }
        float p0[7], p1[7], t0 = 0.f, t1 = 0.f;
        #pragma unroll
        for (int g = 0; g < 7; g++) {
            p0[g] = expf(s0[g] - m0); t0 += p0[g];
            p1[g] = expf(s1[g] - m1); t1 += p1[g];
        }
        #pragma unroll
        for (int o = 16; o; o >>= 1) {
            t0 += __shfl_xor_sync(0xffffffffu, t0, o);
            t1 += __shfl_xor_sync(0xffffffffu, t1, o);
        }
        float inv0 = 1.f / t0, inv1 = 1.f / t1;

        float o00 = 0.f, o01 = 0.f, o10 = 0.f, o11 = 0.f;
        #pragma unroll
        for (int g = 0; g < 7; g++) {
            const int cnt = (g == 6) ? (NTOK - 192) : 32;
            const __half* vb = &Vh[(g*32)*APITCH + lane*2];
            for (int l = 0; l < cnt; l++) {
                float pj0 = __shfl_sync(0xffffffffu, p0[g], l);
                float pj1 = __shfl_sync(0xffffffffu, p1[g], l);
                float2 vf = __half22float2(*(const __half2*)&vb[l*APITCH]);
                o00 += pj0*vf.x; o01 += pj0*vf.y;
                o10 += pj1*vf.x; o11 += pj1*vf.y;
            }
        }
        size_t ob = ((size_t)b*NTOK + i0)*DD + h*DH + lane*2;
        *(__half2*)&out[ob] = __floats2half2_rn(o00*inv0, o01*inv0);
        if (v1) *(__half2*)&out[ob + DD] = __floats2half2_rn(o10*inv1, o11*inv1);
    }
}

// ---------------------------------------------------------------------------
// host orchestration
// ---------------------------------------------------------------------------
extern "C" void kernel_launch(void* const* d_in, const int* in_sizes, int n_in,
                              void* d_out, int out_size) {
    const float* x_in    = (const float*)d_in[0];
    const float* conv_w  = (const float*)d_in[1];
    const float* cls_tok = (const float*)d_in[2];
    const float* pos     = (const float*)d_in[3];
    const float* lnprew  = (const float*)d_in[4];
    const float* lnpreb  = (const float*)d_in[5];
    const float* ln1w    = (const float*)d_in[6];
    const float* ln1b    = (const float*)d_in[7];
    const float* qkvw    = (const float*)d_in[8];
    const float* qkvb    = (const float*)d_in[9];
    const float* pw      = (const float*)d_in[10];
    const float* pb      = (const float*)d_in[11];
    const float* ln2w    = (const float*)d_in[12];
    const float* ln2b    = (const float*)d_in[13];
    const float* fw      = (const float*)d_in[14];
    const float* fb      = (const float*)d_in[15];
    const float* cw      = (const float*)d_in[16];
    const float* cb      = (const float*)d_in[17];
    const float* lnpostw = (const float*)d_in[18];
    const float* lnpostb = (const float*)d_in[19];
    const float* projw   = (const float*)d_in[20];
    const float* headw   = (const float*)d_in[21];
    const float* headb   = (const float*)d_in[22];

    float  *gx, *gpe, *gc, *gz;
    __half *gq, *gh, *go, *gm, *gp;
    __half *wconv, *wqkv, *wproj, *wfc, *wcpr;
    cudaGetSymbolAddress((void**)&gx,  g_x);
    cudaGetSymbolAddress((void**)&gpe, g_pe);
    cudaGetSymbolAddress((void**)&gc,  g_cls);
    cudaGetSymbolAddress((void**)&gz,  g_z);
    cudaGetSymbolAddress((void**)&gq,  g_qkv);
    cudaGetSymbolAddress((void**)&gh,  g_h);
    cudaGetSymbolAddress((void**)&go,  g_o);
    cudaGetSymbolAddress((void**)&gm,  g_mlp);
    cudaGetSymbolAddress((void**)&gp,  g_pat);
    cudaGetSymbolAddress((void**)&wconv, g_wconv);
    cudaGetSymbolAddress((void**)&wqkv,  g_wqkv);
    cudaGetSymbolAddress((void**)&wproj, g_wproj);
    cudaGetSymbolAddress((void**)&wfc,   g_wfc);
    cudaGetSymbolAddress((void**)&wcpr,  g_wcpr);

    cudaFuncSetAttribute(attn_kernel, cudaFuncAttributeMaxDynamicSharedMemorySize, ATTN_SMEM);
    cudaFuncSetAttribute(gemm_h<float ,false,false>, cudaFuncAttributeMaxDynamicSharedMemorySize, GH_SMEM);
    cudaFuncSetAttribute(gemm_h<float ,false,true >, cudaFuncAttributeMaxDynamicSharedMemorySize, GH_SMEM);
    cudaFuncSetAttribute(gemm_h<__half,true ,false>, cudaFuncAttributeMaxDynamicSharedMemorySize, GH_SMEM);
    cudaFuncSetAttribute(gemm_h<__half,false,false>, cudaFuncAttributeMaxDynamicSharedMemorySize, GH_SMEM);

    // ---- weight conversion (single launch) ----
    f2h_all_kernel<<<(F2H_C4 + 255)/256, 256>>>(conv_w, wconv, qkvw, wqkv,
                                                pw, wproj, fw, wfc, cw, wcpr);

    const int GY  = MROWS/128 + 1;   // 50 (tail = rows 6272..6303, 32 rows)
    const int GYP = PROWS/128 + 1;   // 50 (tail empty; M=6272 divides evenly)

    // ---- patch embed ----
    im2col_kernel<<<(PROWS*DD + 255)/256, 256>>>(x_in);
    gemm_h<float,false,false><<<dim3(DD/128, GYP), 256, GH_SMEM>>>(
        gp, wconv, nullptr, nullptr, gpe, PROWS, DD, DD);
    assemble_ln_kernel<<<MROWS, 256>>>(gpe, cls_tok, pos, lnprew, lnpreb, gx);

    for (int l = 0; l < DEPTH; l++) {
        // attention sub-block
        ln_kernel<__half><<<MROWS, 256>>>(gx, gh, ln1w + l*DD, ln1b + l*DD, DD, DD);
        gemm_h<__half,false,false><<<dim3((3*DD)/128, GY), 256, GH_SMEM>>>(
            gh, wqkv + (size_t)l*3*DD*DD, qkvb + (long)l*3*DD, nullptr, gq, MROWS, 3*DD, DD);
        attn_kernel<<<BB*NH, 256, ATTN_SMEM>>>(gq, go);
        gemm_h<float,false,true><<<dim3(DD/128, GY), 256, GH_SMEM>>>(
            go, wproj + (size_t)l*DD*DD, pb + (long)l*DD, gx, gx, MROWS, DD, DD);
        // MLP sub-block
        ln_kernel<__half><<<MROWS, 256>>>(gx, gh, ln2w + l*DD, ln2b + l*DD, DD, DD);
        gemm_h<__half,true,false><<<dim3(MLPD/128, GY), 256, GH_SMEM>>>(
            gh, wfc + (size_t)l*MLPD*DD, fb + (long)l*MLPD, nullptr, gm, MROWS, MLPD, DD);
        gemm_h<float,false,true><<<dim3(DD/128, GY), 256, GH_SMEM>>>(
            gm, wcpr + (size_t)l*DD*MLPD, cb + (long)l*DD, gx, gx, MROWS, DD, MLPD);
    }

    // ---- head: ln_post on cls rows only, proj, classifier (tiny: SIMT fp32) ----
    ln_kernel<float><<<BB, 256>>>(gx, gc, lnpostw, lnpostb, (long)NTOK*DD, DD);
    gemm_nt<<<dim3(PROJD/64, 1), 256>>>(gc, projw, nullptr, gz, BB, PROJD, DD);
    gemm_nt<<<dim3((NCLS+63)/64, 1), 256>>>(gz, headw, headb, (float*)d_out, BB, NCLS, PROJD);
}

// round 11
// speedup vs baseline: 6.9253x; 1.0264x over previous
#include <cuda_runtime.h>
#include <cuda_fp16.h>
#include <math.h>
#include <stdint.h>

// ---------------------------------------------------------------------------
// CLIP ViT-B/16 forward. Round 10: BK=64 3-stage cp.async GEMM (half the
// barriers), 2-row LayerNorm blocks. Rest as R9.
// ---------------------------------------------------------------------------

#define BB      32
#define NTOK    197
#define NPAT    196
#define DD      768
#define DEPTH   12
#define NH      12
#define DH      64
#define MLPD    3072
#define PROJD   512
#define NCLS    1000
#define MROWS   (BB*NTOK)          // 6304
#define PROWS   (BB*NPAT)          // 6272

// fp32 buffers
__device__ __align__(128) float  g_x   [MROWS*DD];
__device__ __align__(128) float  g_pe  [PROWS*DD];
__device__ __align__(128) float  g_cls [BB*DD];
__device__ __align__(128) float  g_z   [BB*PROJD];
// fp16 buffers
__device__ __align__(128) __half g_qkv [MROWS*3*DD];
__device__ __align__(128) __half g_h   [MROWS*DD];
__device__ __align__(128) __half g_o   [MROWS*DD];
__device__ __align__(128) __half g_mlp [MROWS*MLPD];
__device__ __align__(128) __half g_pat [PROWS*DD];
// fp16 weights
__device__ __align__(128) __half g_wconv [DD*DD];
__device__ __align__(128) __half g_wqkv  [DEPTH*3*DD*DD];
__device__ __align__(128) __half g_wproj [DEPTH*DD*DD];
__device__ __align__(128) __half g_wfc   [DEPTH*MLPD*DD];
__device__ __align__(128) __half g_wcpr  [DEPTH*DD*MLPD];

// ---------------------------------------------------------------------------
// merged fp32 -> fp16 weight conversion
// ---------------------------------------------------------------------------
#define F2H_C0 (DD*DD/8)
#define F2H_C1 (F2H_C0 + DEPTH*3*DD*DD/8)
#define F2H_C2 (F2H_C1 + DEPTH*DD*DD/8)
#define F2H_C3 (F2H_C2 + DEPTH*MLPD*DD/8)
#define F2H_C4 (F2H_C3 + DEPTH*DD*MLPD/8)

__global__ void f2h_all_kernel(const float* __restrict__ s0, __half* d0,
                               const float* __restrict__ s1, __half* d1,
                               const float* __restrict__ s2, __half* d2,
                               const float* __restrict__ s3, __half* d3,
                               const float* __restrict__ s4, __half* d4) {
    int i = blockIdx.x * 256 + threadIdx.x;
    if (i >= F2H_C4) return;
    const float* src; __half* dst; int off;
    if      (i < F2H_C0) { src = s0; dst = d0; off = i; }
    else if (i < F2H_C1) { src = s1; dst = d1; off = i - F2H_C0; }
    else if (i < F2H_C2) { src = s2; dst = d2; off = i - F2H_C1; }
    else if (i < F2H_C3) { src = s3; dst = d3; off = i - F2H_C2; }
    else                 { src = s4; dst = d4; off = i - F2H_C3; }
    const float4* p = (const float4*)src + (size_t)off*2;
    float4 a = p[0], b = p[1];
    __half2 h0 = __floats2half2_rn(a.x, a.y);
    __half2 h1 = __floats2half2_rn(a.z, a.w);
    __half2 h2 = __floats2half2_rn(b.x, b.y);
    __half2 h3 = __floats2half2_rn(b.z, b.w);
    uint4 v;
    v.x = *(uint32_t*)&h0; v.y = *(uint32_t*)&h1;
    v.z = *(uint32_t*)&h2; v.w = *(uint32_t*)&h3;
    ((uint4*)dst)[off] = v;
}

// ---------------------------------------------------------------------------
// im2col
// ---------------------------------------------------------------------------
__global__ void im2col_kernel(const float* __restrict__ x) {
    int idx = blockIdx.x * 256 + threadIdx.x;
    if (idx >= PROWS * DD) return;
    int k = idx % DD;
    int m = idx / DD;
    int b = m / NPAT, p = m % NPAT;
    int ph = p / 14, pw = p % 14;
    int c = k >> 8, r = (k >> 4) & 15, col = k & 15;
    g_pat[idx] = __float2half_rn(x[(((long)(b*3 + c)*224 + ph*16 + r)*224) + pw*16 + col]);
}

// ---------------------------------------------------------------------------
// fused assemble + ln_pre
// ---------------------------------------------------------------------------
__global__ void assemble_ln_kernel(const float* __restrict__ pe,
                                   const float* __restrict__ cls_tok,
                                   const float* __restrict__ pos,
                                   const float* __restrict__ gam,
                                   const float* __restrict__ bet,
                                   float* __restrict__ out) {
    __shared__ float red[16];
    int row = blockIdx.x, tid = threadIdx.x;
    int b = row / NTOK, n = row % NTOK;
    float v0, v1, v2;
    if (n == 0) {
        v0 = cls_tok[tid      ] + pos[tid      ];
        v1 = cls_tok[tid + 256] + pos[tid + 256];
        v2 = cls_tok[tid + 512] + pos[tid + 512];
    } else {
        const float* per = pe + ((size_t)b*NPAT + (n-1))*DD;
        const float* por = pos + (size_t)n*DD;
        v0 = per[tid      ] + por[tid      ];
        v1 = per[tid + 256] + por[tid + 256];
        v2 = per[tid + 512] + por[tid + 512];
    }
    float s = v0 + v1 + v2;
    #pragma unroll
    for (int o = 16; o; o >>= 1) s += __shfl_xor_sync(0xffffffffu, s, o);
    if ((tid & 31) == 0) red[tid >> 5] = s;
    __syncthreads();
    float tot = red[0]+red[1]+red[2]+red[3]+red[4]+red[5]+red[6]+red[7];
    float mean = tot * (1.0f / 768.0f);
    float d0 = v0 - mean, d1 = v1 - mean, d2 = v2 - mean;
    float q = d0*d0 + d1*d1 + d2*d2;
    #pragma unroll
    for (int o = 16; o; o >>= 1) q += __shfl_xor_sync(0xffffffffu, q, o);
    if ((tid & 31) == 0) red[8 + (tid >> 5)] = q;
    __syncthreads();
    float var = (red[8]+red[9]+red[10]+red[11]+red[12]+red[13]+red[14]+red[15]) * (1.0f/768.0f);
    float rs = rsqrtf(var + 1e-5f);
    float* orow = out + (size_t)row * DD;
    orow[tid      ] = d0 * rs * gam[tid      ] + bet[tid      ];
    orow[tid + 256] = d1 * rs * gam[tid + 256] + bet[tid + 256];
    orow[tid + 512] = d2 * rs * gam[tid + 512] + bet[tid + 512];
}

// ---------------------------------------------------------------------------
// LayerNorm over 768: 2 rows per 512-thread block (halves grid latency)
// ---------------------------------------------------------------------------
template<typename OutT>
__global__ void ln_kernel(const float* __restrict__ in, OutT* __restrict__ out,
                          const float* __restrict__ gam, const float* __restrict__ bet,
                          long in_stride, long out_stride) {
    __shared__ float red[2][16];
    int sub = threadIdx.x >> 8;          // 0 or 1 (row within block)
    int tid = threadIdx.x & 255;
    int row = blockIdx.x * 2 + sub;
    const float* xr = in + (long)row * in_stride;
    float v0 = xr[tid], v1 = xr[tid + 256], v2 = xr[tid + 512];
    float s = v0 + v1 + v2;
    #pragma unroll
    for (int o = 16; o; o >>= 1) s += __shfl_xor_sync(0xffffffffu, s, o);
    if ((tid & 31) == 0) red[sub][tid >> 5] = s;
    __syncthreads();
    float* rd = red[sub];
    float tot = rd[0]+rd[1]+rd[2]+rd[3]+rd[4]+rd[5]+rd[6]+rd[7];
    float mean = tot * (1.0f / 768.0f);
    float d0 = v0 - mean, d1 = v1 - mean, d2 = v2 - mean;
    float q = d0*d0 + d1*d1 + d2*d2;
    #pragma unroll
    for (int o = 16; o; o >>= 1) q += __shfl_xor_sync(0xffffffffu, q, o);
    if ((tid & 31) == 0) red[sub][8 + (tid >> 5)] = q;
    __syncthreads();
    float var = (rd[8]+rd[9]+rd[10]+rd[11]+rd[12]+rd[13]+rd[14]+rd[15]) * (1.0f/768.0f);
    float rs = rsqrtf(var + 1e-5f);
    OutT* orow = out + (long)row * out_stride;
    orow[tid      ] = (OutT)(d0 * rs * gam[tid      ] + bet[tid      ]);
    orow[tid + 256] = (OutT)(d1 * rs * gam[tid + 256] + bet[tid + 256]);
    orow[tid + 512] = (OutT)(d2 * rs * gam[tid + 512] + bet[tid + 512]);
}

__device__ __forceinline__ float gelu_f(float v) {
    return 0.5f * v * (1.0f + erff(v * 0.70710678118654752f));
}

// ---------------------------------------------------------------------------
// fp16 tensor-core NT GEMM: BK=64, 3-stage cp.async, 128x128 tile, short tail.
// Smem/stage: A 128 rows x 144B pitch (128B payload) + B same = 36864B.
// 3 stages = 110592B/CTA, 2 CTAs/SM. Row pitch 144B: 16B-lane = row*9 mod 8
// => conflict-free STS and ldmatrix.
// Requires N % 128 == 0, K % 64 == 0.
// ---------------------------------------------------------------------------
__device__ __forceinline__ uint32_t smem_u32(const void* p) {
    uint32_t a;
    asm("{ .reg .u64 t; cvta.to.shared.u64 t, %1; cvt.u32.u64 %0, t; }" : "=r"(a) : "l"(p));
    return a;
}

#define LDSM_X4(r0,r1,r2,r3,addr) \
    asm volatile("ldmatrix.sync.aligned.m8n8.x4.shared.b16 {%0,%1,%2,%3}, [%4];" \
                 : "=r"(r0), "=r"(r1), "=r"(r2), "=r"(r3) : "r"(addr))

#define HMMA16816(d, a0,a1,a2,a3, b0,b1) \
    asm volatile("mma.sync.aligned.m16n8k16.row.col.f32.f16.f16.f32 " \
                 "{%0,%1,%2,%3}, {%4,%5,%6,%7}, {%8,%9}, {%0,%1,%2,%3};" \
                 : "+f"((d)[0]), "+f"((d)[1]), "+f"((d)[2]), "+f"((d)[3]) \
                 : "r"(a0), "r"(a1), "r"(a2), "r"(a3), "r"(b0), "r"(b1))

__device__ __forceinline__ void cp16(uint32_t saddr, const void* gaddr) {
    asm volatile("cp.async.cg.shared.global [%0], [%1], 16;" :: "r"(saddr), "l"(gaddr));
}
__device__ __forceinline__ void cp16z(uint32_t saddr, const void* gaddr, int sz) {
    asm volatile("cp.async.cg.shared.global [%0], [%1], 16, %2;" :: "r"(saddr), "l"(gaddr), "r"(sz));
}
#define CP_COMMIT() asm volatile("cp.async.commit_group;" ::: "memory")
#define CP_WAIT1()  asm volatile("cp.async.wait_group 1;" ::: "memory")

#define HPITCH  144
#define HSTAGE  (128*HPITCH*2)     // 36864 (A + B)
#define GH_SMEM (3*HSTAGE)         // 110592

template<typename OutT, bool GELU, bool RES>
__global__ __launch_bounds__(256, 2)
void gemm_h(const __half* __restrict__ A, const __half* __restrict__ W,
            const float* __restrict__ bias, const float* __restrict__ Rs,
            OutT* __restrict__ Cp, int M, int N, int K) {
    extern __shared__ uint8_t smem[];
    const uint32_t sb = smem_u32(smem);
    const int tid = threadIdx.x, lane = tid & 31, warp = tid >> 5;
    const int wm = warp >> 2, wn = warp & 3;
    const int by = blockIdx.y;
    const bool tail = (by == 0);
    const int m0 = tail ? ((M >> 7) << 7) : ((by - 1) << 7);
    const int n0 = blockIdx.x * 128;

    float acc[4][4][4];
    #pragma unroll
    for (int i=0;i<4;i++)
      #pragma unroll
      for (int j=0;j<4;j++)
        #pragma unroll
        for (int f=0;f<4;f++) acc[i][j][f]=0.f;

    const int T = K >> 6;   // BK=64

    // staging: chunk c = tid + it*256; row = (tid>>3) + it*32; ch = tid&7
    const int row0 = tid >> 3, ch = tid & 7;
    int    szA[4];
    size_t offA[4];
    #pragma unroll
    for (int it = 0; it < 4; it++) {
        int r = m0 + row0 + it*32;
        szA[it]  = (r < M) ? 16 : 0;
        offA[it] = szA[it] ? ((size_t)r * K + ch*8) : 0;
    }
    const __half* Bbase = W + (size_t)(n0 + row0) * K + ch*8;
    const uint32_t sbase = sb + (uint32_t)row0 * HPITCH + ch*16;

    auto issue_stage = [&](int t, int s) {
        if (t < T) {
            uint32_t so = sbase + (uint32_t)s * HSTAGE;
            int ko = t * 64;
            #pragma unroll
            for (int it = 0; it < 4; it++)
                cp16z(so + it*(32*HPITCH), A + offA[it] + (szA[it] ? ko : 0), szA[it]);
            #pragma unroll
            for (int it = 0; it < 4; it++)
                cp16(so + 128*HPITCH + it*(32*HPITCH), Bbase + (size_t)it*32*K + ko);
        }
        CP_COMMIT();
    };

    const uint32_t aoff = (uint32_t)(wm*64 + (lane & 15)) * HPITCH + (lane >> 4) * 16;
    const uint32_t boff = 128*HPITCH
                        + (uint32_t)(wn*32 + (lane & 7) + ((lane >> 4) << 3)) * HPITCH
                        + ((lane >> 3) & 1) * 16;

    issue_stage(0, 0);
    issue_stage(1, 1);

    int cur = 0, nxt = 2;
    for (int t = 0; t < T; t++) {
        CP_WAIT1();
        __syncthreads();
        issue_stage(t + 2, nxt);
        nxt = (nxt == 2) ? 0 : nxt + 1;
        const uint32_t stb = sb + (uint32_t)cur * HSTAGE;
        cur = (cur == 2) ? 0 : cur + 1;

        if (tail) {
            if (wm == 0) {
                #pragma unroll
                for (int kc = 0; kc < 4; kc++) {
                    uint32_t af[2][4];
                    #pragma unroll
                    for (int mt = 0; mt < 2; mt++) {
                        uint32_t addr = stb + aoff + mt*16*HPITCH + kc*32;
                        LDSM_X4(af[mt][0], af[mt][1], af[mt][2], af[mt][3], addr);
                    }
                    uint32_t bf[2][4];
                    #pragma unroll
                    for (int pr = 0; pr < 2; pr++) {
                        uint32_t addr = stb + boff + pr*16*HPITCH + kc*32;
                        LDSM_X4(bf[pr][0], bf[pr][1], bf[pr][2], bf[pr][3], addr);
                    }
                    #pragma unroll
                    for (int mt = 0; mt < 2; mt++)
                        #pragma unroll
                        for (int nt = 0; nt < 4; nt++)
                            HMMA16816(acc[mt][nt],
                                      af[mt][0], af[mt][1], af[mt][2], af[mt][3],
                                      bf[nt>>1][(nt&1)*2], bf[nt>>1][(nt&1)*2+1]);
                }
            }
        } else {
            #pragma unroll
            for (int kc = 0; kc < 4; kc++) {
                uint32_t af[4][4];
                #pragma unroll
                for (int mt = 0; mt < 4; mt++) {
                    uint32_t addr = stb + aoff + mt*16*HPITCH + kc*32;
                    LDSM_X4(af[mt][0], af[mt][1], af[mt][2], af[mt][3], addr);
                }
                uint32_t bf[2][4];
                #pragma unroll
                for (int pr = 0; pr < 2; pr++) {
                    uint32_t addr = stb + boff + pr*16*HPITCH + kc*32;
                    LDSM_X4(bf[pr][0], bf[pr][1], bf[pr][2], bf[pr][3], addr);
                }
                #pragma unroll
                for (int mt = 0; mt < 4; mt++) {
                    #pragma unroll
                    for (int nt = 0; nt < 4; nt++) {
                        HMMA16816(acc[mt][nt],
                                  af[mt][0], af[mt][1], af[mt][2], af[mt][3],
                                  bf[nt>>1][(nt&1)*2], bf[nt>>1][(nt&1)*2+1]);
                    }
                }
            }
        }
    }

    // ---- epilogue ----
    const int lr = lane >> 2, lc = lane & 3;
    if (tail && wm != 0) return;
    const int mtN = tail ? 2 : 4;
    for (int mt = 0; mt < mtN; mt++) {
        int r0 = m0 + wm*64 + mt*16 + lr;
        #pragma unroll
        for (int nt = 0; nt < 4; nt++) {
            int cc = n0 + wn*32 + nt*8 + lc*2;
            float v0 = acc[mt][nt][0], v1 = acc[mt][nt][1];
            float v2 = acc[mt][nt][2], v3 = acc[mt][nt][3];
            if (bias) {
                float bb0 = bias[cc], bb1 = bias[cc+1];
                v0 += bb0; v1 += bb1; v2 += bb0; v3 += bb1;
            }
            if (RES) {
                if (r0 < M) {
                    float2 rr = *(const float2*)&Rs[(size_t)r0*N + cc];
                    v0 += rr.x; v1 += rr.y;
                }
                if (r0 + 8 < M) {
                    float2 rr = *(const float2*)&Rs[(size_t)(r0+8)*N + cc];
                    v2 += rr.x; v3 += rr.y;
                }
            }
            if (GELU) { v0 = gelu_f(v0); v1 = gelu_f(v1); v2 = gelu_f(v2); v3 = gelu_f(v3); }
            if (sizeof(OutT) == 4) {
                if (r0 < M)     *(float2*)&(((float*)Cp)[(size_t)r0*N + cc])     = make_float2(v0, v1);
                if (r0 + 8 < M) *(float2*)&(((float*)Cp)[(size_t)(r0+8)*N + cc]) = make_float2(v2, v3);
            } else {
                if (r0 < M) {
                    __half2 h = __floats2half2_rn(v0, v1);
                    *(__half2*)&(((__half*)Cp)[(size_t)r0*N + cc]) = h;
                }
                if (r0 + 8 < M) {
                    __half2 h = __floats2half2_rn(v2, v3);
                    *(__half2*)&(((__half*)Cp)[(size_t)(r0+8)*N + cc]) = h;
                }
            }
        }
    }
}

// ---------------------------------------------------------------------------
// SIMT NT SGEMM for the tiny head GEMMs (M=32), fp32
// ---------------------------------------------------------------------------
__global__ void gemm_nt(const float* __restrict__ A, const float* __restrict__ W,
                        const float* __restrict__ bias, float* __restrict__ C,
                        int M, int N, int K) {
    __shared__ float As[16][64];
    __shared__ float Bs[16][64];
    int tid = threadIdx.x;
    int tx = tid & 15, ty = tid >> 4;
    int m0 = blockIdx.y * 64, n0 = blockIdx.x * 64;
    int lr = tid >> 2;
    int lc = (tid & 3) << 2;
    float acc[4][4] = {};
    const float* Aptr = A + (long)(m0 + lr) * K + lc;
    const float* Wptr = W + (long)(n0 + lr) * K + lc;
    bool am = (m0 + lr) < M;
    bool wn = (n0 + lr) < N;
    for (int k0 = 0; k0 < K; k0 += 16) {
        float4 av = am ? *(const float4*)(Aptr + k0) : make_float4(0.f,0.f,0.f,0.f);
        float4 wv = wn ? *(const float4*)(Wptr + k0) : make_float4(0.f,0.f,0.f,0.f);
        As[lc+0][lr]=av.x; As[lc+1][lr]=av.y; As[lc+2][lr]=av.z; As[lc+3][lr]=av.w;
        Bs[lc+0][lr]=wv.x; Bs[lc+1][lr]=wv.y; Bs[lc+2][lr]=wv.z; Bs[lc+3][lr]=wv.w;
        __syncthreads();
        #pragma unroll
        for (int kk = 0; kk < 16; kk++) {
            float4 a = *(const float4*)(&As[kk][ty << 2]);
            float4 b = *(const float4*)(&Bs[kk][tx << 2]);
            acc[0][0] += a.x*b.x; acc[0][1] += a.x*b.y; acc[0][2] += a.x*b.z; acc[0][3] += a.x*b.w;
            acc[1][0] += a.y*b.x; acc[1][1] += a.y*b.y; acc[1][2] += a.y*b.z; acc[1][3] += a.y*b.w;
            acc[2][0] += a.z*b.x; acc[2][1] += a.z*b.y; acc[2][2] += a.z*b.z; acc[2][3] += a.z*b.w;
            acc[3][0] += a.w*b.x; acc[3][1] += a.w*b.y; acc[3][2] += a.w*b.z; acc[3][3] += a.w*b.w;
        }
        __syncthreads();
    }
    #pragma unroll
    for (int i = 0; i < 4; i++) {
        int m = m0 + (ty << 2) + i;
        if (m >= M) continue;
        #pragma unroll
        for (int j = 0; j < 4; j++) {
            int n = n0 + (tx << 2) + j;
            if (n >= N) continue;
            float v = acc[i][j];
            if (bias) v += bias[n];
            C[(long)m * N + n] = v;
        }
    }
}

// ---------------------------------------------------------------------------
// Warp-parallel fused attention (fp16 qkv input).
// ---------------------------------------------------------------------------
#define APITCH 66
#define AROWS  224
#define ATTN_SMEM (2*AROWS*APITCH*2 + 8*128*4)

__global__ void attn_kernel(const __half* __restrict__ qkv, __half* __restrict__ out) {
    int b = blockIdx.x / NH, h = blockIdx.x % NH;
    int tid = threadIdx.x, lane = tid & 31, warp = tid >> 5;
    extern __shared__ char asm_[];
    __half* Kh = (__half*)asm_;
    __half* Vh = Kh + AROWS*APITCH;
    float*  qs = (float*)(Vh + AROWS*APITCH);

    const __half* base = qkv + (size_t)b * NTOK * (3*DD) + h * DH;

    for (int idx = tid; idx < NTOK*32; idx += 256) {
        int j = idx >> 5, d2 = (idx & 31) << 1;
        *(uint32_t*)&Kh[j*APITCH + d2] = *(const uint32_t*)&base[(size_t)j*(3*DD) + DD   + d2];
        *(uint32_t*)&Vh[j*APITCH + d2] = *(const uint32_t*)&base[(size_t)j*(3*DD) + 2*DD + d2];
    }
    __syncthreads();

    float* qw = qs + warp*128;
    for (int r = 0; r < 13; r++) {
        int i0 = r*16 + warp*2;
        if (i0 >= NTOK) break;
        int i1 = i0 + 1;
        bool v1 = (i1 < NTOK);
        int i1c = v1 ? i1 : i0;
        {
            float2 q0a = __half22float2(*(const __half2*)&base[(size_t)i0 *(3*DD) + lane*2]);
            float2 q1a = __half22float2(*(const __half2*)&base[(size_t)i1c*(3*DD) + lane*2]);
            qw[lane*2]        = q0a.x; qw[lane*2+1]      = q0a.y;
            qw[64 + lane*2]   = q1a.x; qw[64 + lane*2+1] = q1a.y;
        }
        __syncwarp();

        float a0[7], a1[7];
        #pragma unroll
        for (int g = 0; g < 7; g++) { a0[g] = 0.f; a1[g] = 0.f; }
        #pragma unroll 8
        for (int d2 = 0; d2 < 32; d2++) {
            float2 q0 = *(const float2*)&qw[d2*2];
            float2 q1 = *(const float2*)&qw[64 + d2*2];
            #pragma unroll
            for (int g = 0; g < 7; g++) {
                __half2 kv = *(const __half2*)&Kh[(lane + g*32)*APITCH + d2*2];
                float2 kf = __half22float2(kv);
                a0[g] += q0.x*kf.x + q0.y*kf.y;
                a1[g] += q1.x*kf.x + q1.y*kf.y;
            }
        }
        float s0[7], s1[7];
        #pragma unroll
        for (int g = 0; g < 7; g++) {
            bool ok = (lane + g*32) < NTOK;
            s0[g] = ok ? a0[g]*0.125f : -1e30f;
            s1[g] = ok ? a1[g]*0.125f : -1e30f;
        }
        float m0 = s0[0], m1 = s1[0];
        #pragma unroll
        for (int g = 1; g < 7; g++) { m0 = fmaxf(m0, s0[g]); m1 = fmaxf(m1, s1[g]); }
        #pragma unroll
        for (int o = 16; o; o >>= 1) {
            m0 = fmaxf(m0, __shfl_xor_sync(0xffffffffu, m0, o));
            m1 = fmaxf(m1, __shfl_xor_sync(0xffffffffu, m1, o));
        }
        float p0[7], p1[7], t0 = 0.f, t1 = 0.f;
        #pragma unroll
        for (int g = 0; g < 7; g++) {
            p0[g] = expf(s0[g] - m0); t0 += p0[g];
            p1[g] = expf(s1[g] - m1); t1 += p1[g];
        }
        #pragma unroll
        for (int o = 16; o; o >>= 1) {
            t0 += __shfl_xor_sync(0xffffffffu, t0, o);
            t1 += __shfl_xor_sync(0xffffffffu, t1, o);
        }
        float inv0 = 1.f / t0, inv1 = 1.f / t1;

        float o00 = 0.f, o01 = 0.f, o10 = 0.f, o11 = 0.f;
        #pragma unroll
        for (int g = 0; g < 7; g++) {
            const int cnt = (g == 6) ? (NTOK - 192) : 32;
            const __half* vb = &Vh[(g*32)*APITCH + lane*2];
            for (int l = 0; l < cnt; l++) {
                float pj0 = __shfl_sync(0xffffffffu, p0[g], l);
                float pj1 = __shfl_sync(0xffffffffu, p1[g], l);
                float2 vf = __half22float2(*(const __half2*)&vb[l*APITCH]);
                o00 += pj0*vf.x; o01 += pj0*vf.y;
                o10 += pj1*vf.x; o11 += pj1*vf.y;
            }
        }
        size_t ob = ((size_t)b*NTOK + i0)*DD + h*DH + lane*2;
        *(__half2*)&out[ob] = __floats2half2_rn(o00*inv0, o01*inv0);
        if (v1) *(__half2*)&out[ob + DD] = __floats2half2_rn(o10*inv1, o11*inv1);
    }
}

// ---------------------------------------------------------------------------
// host orchestration
// ---------------------------------------------------------------------------
extern "C" void kernel_launch(void* const* d_in, const int* in_sizes, int n_in,
                              void* d_out, int out_size) {
    const float* x_in    = (const float*)d_in[0];
    const float* conv_w  = (const float*)d_in[1];
    const float* cls_tok = (const float*)d_in[2];
    const float* pos     = (const float*)d_in[3];
    const float* lnprew  = (const float*)d_in[4];
    const float* lnpreb  = (const float*)d_in[5];
    const float* ln1w    = (const float*)d_in[6];
    const float* ln1b    = (const float*)d_in[7];
    const float* qkvw    = (const float*)d_in[8];
    const float* qkvb    = (const float*)d_in[9];
    const float* pw      = (const float*)d_in[10];
    const float* pb      = (const float*)d_in[11];
    const float* ln2w    = (const float*)d_in[12];
    const float* ln2b    = (const float*)d_in[13];
    const float* fw      = (const float*)d_in[14];
    const float* fb      = (const float*)d_in[15];
    const float* cw      = (const float*)d_in[16];
    const float* cb      = (const float*)d_in[17];
    const float* lnpostw = (const float*)d_in[18];
    const float* lnpostb = (const float*)d_in[19];
    const float* projw   = (const float*)d_in[20];
    const float* headw   = (const float*)d_in[21];
    const float* headb   = (const float*)d_in[22];

    float  *gx, *gpe, *gc, *gz;
    __half *gq, *gh, *go, *gm, *gp;
    __half *wconv, *wqkv, *wproj, *wfc, *wcpr;
    cudaGetSymbolAddress((void**)&gx,  g_x);
    cudaGetSymbolAddress((void**)&gpe, g_pe);
    cudaGetSymbolAddress((void**)&gc,  g_cls);
    cudaGetSymbolAddress((void**)&gz,  g_z);
    cudaGetSymbolAddress((void**)&gq,  g_qkv);
    cudaGetSymbolAddress((void**)&gh,  g_h);
    cudaGetSymbolAddress((void**)&go,  g_o);
    cudaGetSymbolAddress((void**)&gm,  g_mlp);
    cudaGetSymbolAddress((void**)&gp,  g_pat);
    cudaGetSymbolAddress((void**)&wconv, g_wconv);
    cudaGetSymbolAddress((void**)&wqkv,  g_wqkv);
    cudaGetSymbolAddress((void**)&wproj, g_wproj);
    cudaGetSymbolAddress((void**)&wfc,   g_wfc);
    cudaGetSymbolAddress((void**)&wcpr,  g_wcpr);

    cudaFuncSetAttribute(attn_kernel, cudaFuncAttributeMaxDynamicSharedMemorySize, ATTN_SMEM);
    cudaFuncSetAttribute(gemm_h<float ,false,false>, cudaFuncAttributeMaxDynamicSharedMemorySize, GH_SMEM);
    cudaFuncSetAttribute(gemm_h<float ,false,true >, cudaFuncAttributeMaxDynamicSharedMemorySize, GH_SMEM);
    cudaFuncSetAttribute(gemm_h<__half,true ,false>, cudaFuncAttributeMaxDynamicSharedMemorySize, GH_SMEM);
    cudaFuncSetAttribute(gemm_h<__half,false,false>, cudaFuncAttributeMaxDynamicSharedMemorySize, GH_SMEM);

    // ---- weight conversion (single launch) ----
    f2h_all_kernel<<<(F2H_C4 + 255)/256, 256>>>(conv_w, wconv, qkvw, wqkv,
                                                pw, wproj, fw, wfc, cw, wcpr);

    const int GY  = MROWS/128 + 1;   // 50 (tail = rows 6272..6303, 32 rows)
    const int GYP = PROWS/128 + 1;   // 50 (tail empty)

    // ---- patch embed ----
    im2col_kernel<<<(PROWS*DD + 255)/256, 256>>>(x_in);
    gemm_h<float,false,false><<<dim3(DD/128, GYP), 256, GH_SMEM>>>(
        gp, wconv, nullptr, nullptr, gpe, PROWS, DD, DD);
    assemble_ln_kernel<<<MROWS, 256>>>(gpe, cls_tok, pos, lnprew, lnpreb, gx);

    for (int l = 0; l < DEPTH; l++) {
        // attention sub-block
        ln_kernel<__half><<<MROWS/2, 512>>>(gx, gh, ln1w + l*DD, ln1b + l*DD, DD, DD);
        gemm_h<__half,false,false><<<dim3((3*DD)/128, GY), 256, GH_SMEM>>>(
            gh, wqkv + (size_t)l*3*DD*DD, qkvb + (long)l*3*DD, nullptr, gq, MROWS, 3*DD, DD);
        attn_kernel<<<BB*NH, 256, ATTN_SMEM>>>(gq, go);
        gemm_h<float,false,true><<<dim3(DD/128, GY), 256, GH_SMEM>>>(
            go, wproj + (size_t)l*DD*DD, pb + (long)l*DD, gx, gx, MROWS, DD, DD);
        // MLP sub-block
        ln_kernel<__half><<<MROWS/2, 512>>>(gx, gh, ln2w + l*DD, ln2b + l*DD, DD, DD);
        gemm_h<__half,true,false><<<dim3(MLPD/128, GY), 256, GH_SMEM>>>(
            gh, wfc + (size_t)l*MLPD*DD, fb + (long)l*MLPD, nullptr, gm, MROWS, MLPD, DD);
        gemm_h<float,false,true><<<dim3(DD/128, GY), 256, GH_SMEM>>>(
            gm, wcpr + (size_t)l*DD*MLPD, cb + (long)l*DD, gx, gx, MROWS, DD, MLPD);
    }

    // ---- head: ln_post on cls rows only, proj, classifier ----
    ln_kernel<float><<<BB/2, 512>>>(gx, gc, lnpostw, lnpostb, (long)NTOK*DD, DD);
    gemm_nt<<<dim3(PROJD/64, 1), 256>>>(gc, projw, nullptr, gz, BB, PROJD, DD);
    gemm_nt<<<dim3((NCLS+63)/64, 1), 256>>>(gz, headw, headb, (float*)d_out, BB, NCLS, PROJD);
}

// round 13
// speedup vs baseline: 9.8754x; 1.4260x over previous
#include <cuda_runtime.h>
#include <cuda_fp16.h>
#include <math.h>
#include <stdint.h>

// ---------------------------------------------------------------------------
// CLIP ViT-B/16 forward. Round 12: R11 HMMA flash attention with Q-staging fix
// (full 64-dim Q staged: 4 iterations, 8 chunks/row). GEMM path = R10.
// ---------------------------------------------------------------------------

#define BB      32
#define NTOK    197
#define NPAT    196
#define DD      768
#define DEPTH   12
#define NH      12
#define DH      64
#define MLPD    3072
#define PROJD   512
#define NCLS    1000
#define MROWS   (BB*NTOK)          // 6304
#define PROWS   (BB*NPAT)          // 6272

// fp32 buffers
__device__ __align__(128) float  g_x   [MROWS*DD];
__device__ __align__(128) float  g_pe  [PROWS*DD];
__device__ __align__(128) float  g_cls [BB*DD];
__device__ __align__(128) float  g_z   [BB*PROJD];
// fp16 buffers
__device__ __align__(128) __half g_qkv [MROWS*3*DD];
__device__ __align__(128) __half g_h   [MROWS*DD];
__device__ __align__(128) __half g_o   [MROWS*DD];
__device__ __align__(128) __half g_mlp [MROWS*MLPD];
__device__ __align__(128) __half g_pat [PROWS*DD];
// fp16 weights
__device__ __align__(128) __half g_wconv [DD*DD];
__device__ __align__(128) __half g_wqkv  [DEPTH*3*DD*DD];
__device__ __align__(128) __half g_wproj [DEPTH*DD*DD];
__device__ __align__(128) __half g_wfc   [DEPTH*MLPD*DD];
__device__ __align__(128) __half g_wcpr  [DEPTH*DD*MLPD];

// ---------------------------------------------------------------------------
// merged fp32 -> fp16 weight conversion
// ---------------------------------------------------------------------------
#define F2H_C0 (DD*DD/8)
#define F2H_C1 (F2H_C0 + DEPTH*3*DD*DD/8)
#define F2H_C2 (F2H_C1 + DEPTH*DD*DD/8)
#define F2H_C3 (F2H_C2 + DEPTH*MLPD*DD/8)
#define F2H_C4 (F2H_C3 + DEPTH*DD*MLPD/8)

__global__ void f2h_all_kernel(const float* __restrict__ s0, __half* d0,
                               const float* __restrict__ s1, __half* d1,
                               const float* __restrict__ s2, __half* d2,
                               const float* __restrict__ s3, __half* d3,
                               const float* __restrict__ s4, __half* d4) {
    int i = blockIdx.x * 256 + threadIdx.x;
    if (i >= F2H_C4) return;
    const float* src; __half* dst; int off;
    if      (i < F2H_C0) { src = s0; dst = d0; off = i; }
    else if (i < F2H_C1) { src = s1; dst = d1; off = i - F2H_C0; }
    else if (i < F2H_C2) { src = s2; dst = d2; off = i - F2H_C1; }
    else if (i < F2H_C3) { src = s3; dst = d3; off = i - F2H_C2; }
    else                 { src = s4; dst = d4; off = i - F2H_C3; }
    const float4* p = (const float4*)src + (size_t)off*2;
    float4 a = p[0], b = p[1];
    __half2 h0 = __floats2half2_rn(a.x, a.y);
    __half2 h1 = __floats2half2_rn(a.z, a.w);
    __half2 h2 = __floats2half2_rn(b.x, b.y);
    __half2 h3 = __floats2half2_rn(b.z, b.w);
    uint4 v;
    v.x = *(uint32_t*)&h0; v.y = *(uint32_t*)&h1;
    v.z = *(uint32_t*)&h2; v.w = *(uint32_t*)&h3;
    ((uint4*)dst)[off] = v;
}

// ---------------------------------------------------------------------------
// im2col
// ---------------------------------------------------------------------------
__global__ void im2col_kernel(const float* __restrict__ x) {
    int idx = blockIdx.x * 256 + threadIdx.x;
    if (idx >= PROWS * DD) return;
    int k = idx % DD;
    int m = idx / DD;
    int b = m / NPAT, p = m % NPAT;
    int ph = p / 14, pw = p % 14;
    int c = k >> 8, r = (k >> 4) & 15, col = k & 15;
    g_pat[idx] = __float2half_rn(x[(((long)(b*3 + c)*224 + ph*16 + r)*224) + pw*16 + col]);
}

// ---------------------------------------------------------------------------
// fused assemble + ln_pre
// ---------------------------------------------------------------------------
__global__ void assemble_ln_kernel(const float* __restrict__ pe,
                                   const float* __restrict__ cls_tok,
                                   const float* __restrict__ pos,
                                   const float* __restrict__ gam,
                                   const float* __restrict__ bet,
                                   float* __restrict__ out) {
    __shared__ float red[16];
    int row = blockIdx.x, tid = threadIdx.x;
    int b = row / NTOK, n = row % NTOK;
    float v0, v1, v2;
    if (n == 0) {
        v0 = cls_tok[tid      ] + pos[tid      ];
        v1 = cls_tok[tid + 256] + pos[tid + 256];
        v2 = cls_tok[tid + 512] + pos[tid + 512];
    } else {
        const float* per = pe + ((size_t)b*NPAT + (n-1))*DD;
        const float* por = pos + (size_t)n*DD;
        v0 = per[tid      ] + por[tid      ];
        v1 = per[tid + 256] + por[tid + 256];
        v2 = per[tid + 512] + por[tid + 512];
    }
    float s = v0 + v1 + v2;
    #pragma unroll
    for (int o = 16; o; o >>= 1) s += __shfl_xor_sync(0xffffffffu, s, o);
    if ((tid & 31) == 0) red[tid >> 5] = s;
    __syncthreads();
    float tot = red[0]+red[1]+red[2]+red[3]+red[4]+red[5]+red[6]+red[7];
    float mean = tot * (1.0f / 768.0f);
    float d0 = v0 - mean, d1 = v1 - mean, d2 = v2 - mean;
    float q = d0*d0 + d1*d1 + d2*d2;
    #pragma unroll
    for (int o = 16; o; o >>= 1) q += __shfl_xor_sync(0xffffffffu, q, o);
    if ((tid & 31) == 0) red[8 + (tid >> 5)] = q;
    __syncthreads();
    float var = (red[8]+red[9]+red[10]+red[11]+red[12]+red[13]+red[14]+red[15]) * (1.0f/768.0f);
    float rs = rsqrtf(var + 1e-5f);
    float* orow = out + (size_t)row * DD;
    orow[tid      ] = d0 * rs * gam[tid      ] + bet[tid      ];
    orow[tid + 256] = d1 * rs * gam[tid + 256] + bet[tid + 256];
    orow[tid + 512] = d2 * rs * gam[tid + 512] + bet[tid + 512];
}

// ---------------------------------------------------------------------------
// LayerNorm over 768: 2 rows per 512-thread block
// ---------------------------------------------------------------------------
template<typename OutT>
__global__ void ln_kernel(const float* __restrict__ in, OutT* __restrict__ out,
                          const float* __restrict__ gam, const float* __restrict__ bet,
                          long in_stride, long out_stride) {
    __shared__ float red[2][16];
    int sub = threadIdx.x >> 8;
    int tid = threadIdx.x & 255;
    int row = blockIdx.x * 2 + sub;
    const float* xr = in + (long)row * in_stride;
    float v0 = xr[tid], v1 = xr[tid + 256], v2 = xr[tid + 512];
    float s = v0 + v1 + v2;
    #pragma unroll
    for (int o = 16; o; o >>= 1) s += __shfl_xor_sync(0xffffffffu, s, o);
    if ((tid & 31) == 0) red[sub][tid >> 5] = s;
    __syncthreads();
    float* rd = red[sub];
    float tot = rd[0]+rd[1]+rd[2]+rd[3]+rd[4]+rd[5]+rd[6]+rd[7];
    float mean = tot * (1.0f / 768.0f);
    float d0 = v0 - mean, d1 = v1 - mean, d2 = v2 - mean;
    float q = d0*d0 + d1*d1 + d2*d2;
    #pragma unroll
    for (int o = 16; o; o >>= 1) q += __shfl_xor_sync(0xffffffffu, q, o);
    if ((tid & 31) == 0) red[sub][8 + (tid >> 5)] = q;
    __syncthreads();
    float var = (rd[8]+rd[9]+rd[10]+rd[11]+rd[12]+rd[13]+rd[14]+rd[15]) * (1.0f/768.0f);
    float rs = rsqrtf(var + 1e-5f);
    OutT* orow = out + (long)row * out_stride;
    orow[tid      ] = (OutT)(d0 * rs * gam[tid      ] + bet[tid      ]);
    orow[tid + 256] = (OutT)(d1 * rs * gam[tid + 256] + bet[tid + 256]);
    orow[tid + 512] = (OutT)(d2 * rs * gam[tid + 512] + bet[tid + 512]);
}

__device__ __forceinline__ float gelu_f(float v) {
    return 0.5f * v * (1.0f + erff(v * 0.70710678118654752f));
}

// ---------------------------------------------------------------------------
// common PTX helpers
// ---------------------------------------------------------------------------
__device__ __forceinline__ uint32_t smem_u32(const void* p) {
    uint32_t a;
    asm("{ .reg .u64 t; cvta.to.shared.u64 t, %1; cvt.u32.u64 %0, t; }" : "=r"(a) : "l"(p));
    return a;
}

#define LDSM_X4(r0,r1,r2,r3,addr) \
    asm volatile("ldmatrix.sync.aligned.m8n8.x4.shared.b16 {%0,%1,%2,%3}, [%4];" \
                 : "=r"(r0), "=r"(r1), "=r"(r2), "=r"(r3) : "r"(addr))

#define HMMA16816(d, a0,a1,a2,a3, b0,b1) \
    asm volatile("mma.sync.aligned.m16n8k16.row.col.f32.f16.f16.f32 " \
                 "{%0,%1,%2,%3}, {%4,%5,%6,%7}, {%8,%9}, {%0,%1,%2,%3};" \
                 : "+f"((d)[0]), "+f"((d)[1]), "+f"((d)[2]), "+f"((d)[3]) \
                 : "r"(a0), "r"(a1), "r"(a2), "r"(a3), "r"(b0), "r"(b1))

__device__ __forceinline__ void cp16(uint32_t saddr, const void* gaddr) {
    asm volatile("cp.async.cg.shared.global [%0], [%1], 16;" :: "r"(saddr), "l"(gaddr));
}
__device__ __forceinline__ void cp16z(uint32_t saddr, const void* gaddr, int sz) {
    asm volatile("cp.async.cg.shared.global [%0], [%1], 16, %2;" :: "r"(saddr), "l"(gaddr), "r"(sz));
}
#define CP_COMMIT() asm volatile("cp.async.commit_group;" ::: "memory")
#define CP_WAIT1()  asm volatile("cp.async.wait_group 1;" ::: "memory")

// ---------------------------------------------------------------------------
// fp16 tensor-core NT GEMM: BK=64, 3-stage cp.async (unchanged from R10)
// ---------------------------------------------------------------------------
#define HPITCH  144
#define HSTAGE  (128*HPITCH*2)
#define GH_SMEM (3*HSTAGE)

template<typename OutT, bool GELU, bool RES>
__global__ __launch_bounds__(256, 2)
void gemm_h(const __half* __restrict__ A, const __half* __restrict__ W,
            const float* __restrict__ bias, const float* __restrict__ Rs,
            OutT* __restrict__ Cp, int M, int N, int K) {
    extern __shared__ uint8_t smem[];
    const uint32_t sb = smem_u32(smem);
    const int tid = threadIdx.x, lane = tid & 31, warp = tid >> 5;
    const int wm = warp >> 2, wn = warp & 3;
    const int by = blockIdx.y;
    const bool tail = (by == 0);
    const int m0 = tail ? ((M >> 7) << 7) : ((by - 1) << 7);
    const int n0 = blockIdx.x * 128;

    float acc[4][4][4];
    #pragma unroll
    for (int i=0;i<4;i++)
      #pragma unroll
      for (int j=0;j<4;j++)
        #pragma unroll
        for (int f=0;f<4;f++) acc[i][j][f]=0.f;

    const int T = K >> 6;

    const int row0 = tid >> 3, ch = tid & 7;
    int    szA[4];
    size_t offA[4];
    #pragma unroll
    for (int it = 0; it < 4; it++) {
        int r = m0 + row0 + it*32;
        szA[it]  = (r < M) ? 16 : 0;
        offA[it] = szA[it] ? ((size_t)r * K + ch*8) : 0;
    }
    const __half* Bbase = W + (size_t)(n0 + row0) * K + ch*8;
    const uint32_t sbase = sb + (uint32_t)row0 * HPITCH + ch*16;

    auto issue_stage = [&](int t, int s) {
        if (t < T) {
            uint32_t so = sbase + (uint32_t)s * HSTAGE;
            int ko = t * 64;
            #pragma unroll
            for (int it = 0; it < 4; it++)
                cp16z(so + it*(32*HPITCH), A + offA[it] + (szA[it] ? ko : 0), szA[it]);
            #pragma unroll
            for (int it = 0; it < 4; it++)
                cp16(so + 128*HPITCH + it*(32*HPITCH), Bbase + (size_t)it*32*K + ko);
        }
        CP_COMMIT();
    };

    const uint32_t aoff = (uint32_t)(wm*64 + (lane & 15)) * HPITCH + (lane >> 4) * 16;
    const uint32_t boff = 128*HPITCH
                        + (uint32_t)(wn*32 + (lane & 7) + ((lane >> 4) << 3)) * HPITCH
                        + ((lane >> 3) & 1) * 16;

    issue_stage(0, 0);
    issue_stage(1, 1);

    int cur = 0, nxt = 2;
    for (int t = 0; t < T; t++) {
        CP_WAIT1();
        __syncthreads();
        issue_stage(t + 2, nxt);
        nxt = (nxt == 2) ? 0 : nxt + 1;
        const uint32_t stb = sb + (uint32_t)cur * HSTAGE;
        cur = (cur == 2) ? 0 : cur + 1;

        if (tail) {
            if (wm == 0) {
                #pragma unroll
                for (int kc = 0; kc < 4; kc++) {
                    uint32_t af[2][4];
                    #pragma unroll
                    for (int mt = 0; mt < 2; mt++) {
                        uint32_t addr = stb + aoff + mt*16*HPITCH + kc*32;
                        LDSM_X4(af[mt][0], af[mt][1], af[mt][2], af[mt][3], addr);
                    }
                    uint32_t bf[2][4];
                    #pragma unroll
                    for (int pr = 0; pr < 2; pr++) {
                        uint32_t addr = stb + boff + pr*16*HPITCH + kc*32;
                        LDSM_X4(bf[pr][0], bf[pr][1], bf[pr][2], bf[pr][3], addr);
                    }
                    #pragma unroll
                    for (int mt = 0; mt < 2; mt++)
                        #pragma unroll
                        for (int nt = 0; nt < 4; nt++)
                            HMMA16816(acc[mt][nt],
                                      af[mt][0], af[mt][1], af[mt][2], af[mt][3],
                                      bf[nt>>1][(nt&1)*2], bf[nt>>1][(nt&1)*2+1]);
                }
            }
        } else {
            #pragma unroll
            for (int kc = 0; kc < 4; kc++) {
                uint32_t af[4][4];
                #pragma unroll
                for (int mt = 0; mt < 4; mt++) {
                    uint32_t addr = stb + aoff + mt*16*HPITCH + kc*32;
                    LDSM_X4(af[mt][0], af[mt][1], af[mt][2], af[mt][3], addr);
                }
                uint32_t bf[2][4];
                #pragma unroll
                for (int pr = 0; pr < 2; pr++) {
                    uint32_t addr = stb + boff + pr*16*HPITCH + kc*32;
                    LDSM_X4(bf[pr][0], bf[pr][1], bf[pr][2], bf[pr][3], addr);
                }
                #pragma unroll
                for (int mt = 0; mt < 4; mt++) {
                    #pragma unroll
                    for (int nt = 0; nt < 4; nt++) {
                        HMMA16816(acc[mt][nt],
                                  af[mt][0], af[mt][1], af[mt][2], af[mt][3],
                                  bf[nt>>1][(nt&1)*2], bf[nt>>1][(nt&1)*2+1]);
                    }
                }
            }
        }
    }

    const int lr = lane >> 2, lc = lane & 3;
    if (tail && wm != 0) return;
    const int mtN = tail ? 2 : 4;
    for (int mt = 0; mt < mtN; mt++) {
        int r0 = m0 + wm*64 + mt*16 + lr;
        #pragma unroll
        for (int nt = 0; nt < 4; nt++) {
            int cc = n0 + wn*32 + nt*8 + lc*2;
            float v0 = acc[mt][nt][0], v1 = acc[mt][nt][1];
            float v2 = acc[mt][nt][2], v3 = acc[mt][nt][3];
            if (bias) {
                float bb0 = bias[cc], bb1 = bias[cc+1];
                v0 += bb0; v1 += bb1; v2 += bb0; v3 += bb1;
            }
            if (RES) {
                if (r0 < M) {
                    float2 rr = *(const float2*)&Rs[(size_t)r0*N + cc];
                    v0 += rr.x; v1 += rr.y;
                }
                if (r0 + 8 < M) {
                    float2 rr = *(const float2*)&Rs[(size_t)(r0+8)*N + cc];
                    v2 += rr.x; v3 += rr.y;
                }
            }
            if (GELU) { v0 = gelu_f(v0); v1 = gelu_f(v1); v2 = gelu_f(v2); v3 = gelu_f(v3); }
            if (sizeof(OutT) == 4) {
                if (r0 < M)     *(float2*)&(((float*)Cp)[(size_t)r0*N + cc])     = make_float2(v0, v1);
                if (r0 + 8 < M) *(float2*)&(((float*)Cp)[(size_t)(r0+8)*N + cc]) = make_float2(v2, v3);
            } else {
                if (r0 < M) {
                    __half2 h = __floats2half2_rn(v0, v1);
                    *(__half2*)&(((__half*)Cp)[(size_t)r0*N + cc]) = h;
                }
                if (r0 + 8 < M) {
                    __half2 h = __floats2half2_rn(v2, v3);
                    *(__half2*)&(((__half*)Cp)[(size_t)(r0+8)*N + cc]) = h;
                }
            }
        }
    }
}

// ---------------------------------------------------------------------------
// SIMT NT SGEMM for the tiny head GEMMs (M=32), fp32
// ---------------------------------------------------------------------------
__global__ void gemm_nt(const float* __restrict__ A, const float* __restrict__ W,
                        const float* __restrict__ bias, float* __restrict__ C,
                        int M, int N, int K) {
    __shared__ float As[16][64];
    __shared__ float Bs[16][64];
    int tid = threadIdx.x;
    int tx = tid & 15, ty = tid >> 4;
    int m0 = blockIdx.y * 64, n0 = blockIdx.x * 64;
    int lr = tid >> 2;
    int lc = (tid & 3) << 2;
    float acc[4][4] = {};
    const float* Aptr = A + (long)(m0 + lr) * K + lc;
    const float* Wptr = W + (long)(n0 + lr) * K + lc;
    bool am = (m0 + lr) < M;
    bool wn = (n0 + lr) < N;
    for (int k0 = 0; k0 < K; k0 += 16) {
        float4 av = am ? *(const float4*)(Aptr + k0) : make_float4(0.f,0.f,0.f,0.f);
        float4 wv = wn ? *(const float4*)(Wptr + k0) : make_float4(0.f,0.f,0.f,0.f);
        As[lc+0][lr]=av.x; As[lc+1][lr]=av.y; As[lc+2][lr]=av.z; As[lc+3][lr]=av.w;
        Bs[lc+0][lr]=wv.x; Bs[lc+1][lr]=wv.y; Bs[lc+2][lr]=wv.z; Bs[lc+3][lr]=wv.w;
        __syncthreads();
        #pragma unroll
        for (int kk = 0; kk < 16; kk++) {
            float4 a = *(const float4*)(&As[kk][ty << 2]);
            float4 b = *(const float4*)(&Bs[kk][tx << 2]);
            acc[0][0] += a.x*b.x; acc[0][1] += a.x*b.y; acc[0][2] += a.x*b.z; acc[0][3] += a.x*b.w;
            acc[1][0] += a.y*b.x; acc[1][1] += a.y*b.y; acc[1][2] += a.y*b.z; acc[1][3] += a.y*b.w;
            acc[2][0] += a.z*b.x; acc[2][1] += a.z*b.y; acc[2][2] += a.z*b.z; acc[2][3] += a.z*b.w;
            acc[3][0] += a.w*b.x; acc[3][1] += a.w*b.y; acc[3][2] += a.w*b.z; acc[3][3] += a.w*b.w;
        }
        __syncthreads();
    }
    #pragma unroll
    for (int i = 0; i < 4; i++) {
        int m = m0 + (ty << 2) + i;
        if (m >= M) continue;
        #pragma unroll
        for (int j = 0; j < 4; j++) {
            int n = n0 + (tx << 2) + j;
            if (n >= N) continue;
            float v = acc[i][j];
            if (bias) v += bias[n];
            C[(long)m * N + n] = v;
        }
    }
}

// ---------------------------------------------------------------------------
// HMMA flash-style attention. One block per (b,h), 8 warps.
// K: [208][72h] smem (keys, pitch 144B). V: transposed [64][216h] (pitch 432B).
// P per warp: [16][216h] (pitch 432B), doubles as Q staging.
// Warp w handles 16-query strips s = w, w+8 (13 strips total).
// ---------------------------------------------------------------------------
#define SEQP    208
#define KPITCH  72              // halves
#define VPITCH  216             // halves
#define PPITCH  216             // halves
#define ATTN_SMEM ((SEQP*KPITCH + 64*VPITCH + 8*16*PPITCH) * 2)   // 112896

__global__ __launch_bounds__(256)
void attn_kernel(const __half* __restrict__ qkv, __half* __restrict__ out) {
    int b = blockIdx.x / NH, h = blockIdx.x % NH;
    int tid = threadIdx.x, lane = tid & 31, warp = tid >> 5;
    extern __shared__ __half sh[];
    __half* Ks = sh;
    __half* Vt = Ks + SEQP*KPITCH;
    __half* Pw = Vt + 64*VPITCH + warp*16*PPITCH;

    const __half* base = qkv + (size_t)b * NTOK * (3*DD) + h * DH;

    // stage K (16B chunks), zero pad rows 197..207
    for (int idx = tid; idx < NTOK*8; idx += 256) {
        int j = idx >> 3, c = idx & 7;
        *(uint4*)&Ks[j*KPITCH + c*8] = *(const uint4*)&base[(size_t)j*(3*DD) + DD + c*8];
    }
    for (int idx = tid; idx < (SEQP-NTOK)*KPITCH; idx += 256) {
        Ks[(NTOK + idx/KPITCH)*KPITCH + (idx % KPITCH)] = __half(0.0f);
    }
    // stage V transposed [d][key], zero pad cols 197..215
    for (int idx = tid; idx < NTOK*64; idx += 256) {
        int j = idx >> 6, d = idx & 63;
        Vt[d*VPITCH + j] = base[(size_t)j*(3*DD) + 2*DD + d];
    }
    for (int idx = tid; idx < 64*(VPITCH-NTOK); idx += 256) {
        int d = idx / (VPITCH-NTOK), c = NTOK + idx % (VPITCH-NTOK);
        Vt[d*VPITCH + c] = __half(0.0f);
    }
    __syncthreads();

    const uint32_t KsB = smem_u32(Ks);
    const uint32_t VtB = smem_u32(Vt);
    const uint32_t PwB = smem_u32(Pw);
    const int lr = lane >> 2, lc = lane & 3;
    const uint32_t browoff = ((lane & 7) + ((lane >> 4) << 3));
    const uint32_t bcol = ((lane >> 3) & 1) * 16;
    const uint32_t aoff = PwB + (uint32_t)(lane & 15) * (PPITCH*2) + (lane >> 4) * 16;

    for (int s = warp; s < 13; s += 8) {
        const int m0 = s * 16;
        // ---- stage FULL Q strip (16 rows x 64 halves) into Pw ----
        #pragma unroll
        for (int t = 0; t < 4; t++) {
            int idx = lane + t*32;            // 0..127
            int r = idx >> 3, c = idx & 7;    // 16 rows x 8 chunks of 8 halves
            int q = m0 + r;
            uint4 v = make_uint4(0u,0u,0u,0u);
            if (q < NTOK) v = *(const uint4*)&base[(size_t)q*(3*DD) + c*8];
            *(uint4*)&Pw[r*PPITCH + c*8] = v;
        }
        __syncwarp();
        // ---- Q A-fragments (4 k-chunks of 16) ----
        uint32_t af[4][4];
        #pragma unroll
        for (int kc = 0; kc < 4; kc++)
            LDSM_X4(af[kc][0], af[kc][1], af[kc][2], af[kc][3], aoff + kc*32);

        // ---- S = Q @ K^T : 26 n-tiles of 8 keys ----
        float acc[26][4];
        #pragma unroll
        for (int nt = 0; nt < 26; nt++) {
            acc[nt][0]=0.f; acc[nt][1]=0.f; acc[nt][2]=0.f; acc[nt][3]=0.f;
        }
        #pragma unroll
        for (int kc = 0; kc < 4; kc++) {
            #pragma unroll
            for (int g = 0; g < 13; g++) {
                uint32_t b0,b1,b2,b3;
                LDSM_X4(b0,b1,b2,b3,
                        KsB + (g*16 + browoff)*(KPITCH*2) + bcol + kc*32);
                HMMA16816(acc[2*g  ], af[kc][0],af[kc][1],af[kc][2],af[kc][3], b0, b1);
                HMMA16816(acc[2*g+1], af[kc][0],af[kc][1],af[kc][2],af[kc][3], b2, b3);
            }
        }

        // ---- softmax: rows r1=lr, r2=lr+8; cols nt*8 + lc*2 + e ----
        float mx1 = -1e30f, mx2 = -1e30f;
        #pragma unroll
        for (int nt = 0; nt < 26; nt++) {
            #pragma unroll
            for (int e = 0; e < 2; e++) {
                int col = nt*8 + lc*2 + e;
                bool ok = col < NTOK;
                float s1 = ok ? acc[nt][e]   * 0.125f : -1e30f;
                float s2 = ok ? acc[nt][2+e] * 0.125f : -1e30f;
                acc[nt][e] = s1; acc[nt][2+e] = s2;
                mx1 = fmaxf(mx1, s1); mx2 = fmaxf(mx2, s2);
            }
        }
        #pragma unroll
        for (int o = 1; o <= 2; o <<= 1) {
            mx1 = fmaxf(mx1, __shfl_xor_sync(0xffffffffu, mx1, o));
            mx2 = fmaxf(mx2, __shfl_xor_sync(0xffffffffu, mx2, o));
        }
        float sum1 = 0.f, sum2 = 0.f;
        #pragma unroll
        for (int nt = 0; nt < 26; nt++) {
            #pragma unroll
            for (int e = 0; e < 2; e++) {
                float p1 = expf(acc[nt][e]   - mx1);
                float p2 = expf(acc[nt][2+e] - mx2);
                acc[nt][e] = p1; acc[nt][2+e] = p2;
                sum1 += p1; sum2 += p2;
            }
        }
        #pragma unroll
        for (int o = 1; o <= 2; o <<= 1) {
            sum1 += __shfl_xor_sync(0xffffffffu, sum1, o);
            sum2 += __shfl_xor_sync(0xffffffffu, sum2, o);
        }
        // write P (fp16) into Pw
        #pragma unroll
        for (int nt = 0; nt < 26; nt++) {
            int col = nt*8 + lc*2;
            __half2 p1 = __floats2half2_rn(acc[nt][0], acc[nt][1]);
            __half2 p2 = __floats2half2_rn(acc[nt][2], acc[nt][3]);
            *(__half2*)&Pw[ lr   *PPITCH + col] = p1;
            *(__half2*)&Pw[(lr+8)*PPITCH + col] = p2;
        }
        __syncwarp();

        // ---- O = P @ V : 8 n-tiles of 8 dh, 13 k-steps of 16 keys ----
        float oacc[8][4];
        #pragma unroll
        for (int nt = 0; nt < 8; nt++) {
            oacc[nt][0]=0.f; oacc[nt][1]=0.f; oacc[nt][2]=0.f; oacc[nt][3]=0.f;
        }
        for (int kt = 0; kt < 13; kt++) {
            uint32_t pa0,pa1,pa2,pa3;
            LDSM_X4(pa0,pa1,pa2,pa3, aoff + kt*32);
            #pragma unroll
            for (int g = 0; g < 4; g++) {
                uint32_t b0,b1,b2,b3;
                LDSM_X4(b0,b1,b2,b3,
                        VtB + (g*16 + browoff)*(VPITCH*2) + bcol + kt*32);
                HMMA16816(oacc[2*g  ], pa0,pa1,pa2,pa3, b0, b1);
                HMMA16816(oacc[2*g+1], pa0,pa1,pa2,pa3, b2, b3);
            }
        }

        // ---- write O ----
        float inv1 = 1.0f / sum1, inv2 = 1.0f / sum2;
        int q1 = m0 + lr, q2 = m0 + lr + 8;
        #pragma unroll
        for (int nt = 0; nt < 8; nt++) {
            int col = nt*8 + lc*2;
            if (q1 < NTOK) {
                __half2 hv = __floats2half2_rn(oacc[nt][0]*inv1, oacc[nt][1]*inv1);
                *(__half2*)&out[((size_t)b*NTOK + q1)*DD + h*DH + col] = hv;
            }
            if (q2 < NTOK) {
                __half2 hv = __floats2half2_rn(oacc[nt][2]*inv2, oacc[nt][3]*inv2);
                *(__half2*)&out[((size_t)b*NTOK + q2)*DD + h*DH + col] = hv;
            }
        }
        __syncwarp();   // Pw reuse safety for next strip
    }
}

// ---------------------------------------------------------------------------
// host orchestration
// ---------------------------------------------------------------------------
extern "C" void kernel_launch(void* const* d_in, const int* in_sizes, int n_in,
                              void* d_out, int out_size) {
    const float* x_in    = (const float*)d_in[0];
    const float* conv_w  = (const float*)d_in[1];
    const float* cls_tok = (const float*)d_in[2];
    const float* pos     = (const float*)d_in[3];
    const float* lnprew  = (const float*)d_in[4];
    const float* lnpreb  = (const float*)d_in[5];
    const float* ln1w    = (const float*)d_in[6];
    const float* ln1b    = (const float*)d_in[7];
    const float* qkvw    = (const float*)d_in[8];
    const float* qkvb    = (const float*)d_in[9];
    const float* pw      = (const float*)d_in[10];
    const float* pb      = (const float*)d_in[11];
    const float* ln2w    = (const float*)d_in[12];
    const float* ln2b    = (const float*)d_in[13];
    const float* fw      = (const float*)d_in[14];
    const float* fb      = (const float*)d_in[15];
    const float* cw      = (const float*)d_in[16];
    const float* cb      = (const float*)d_in[17];
    const float* lnpostw = (const float*)d_in[18];
    const float* lnpostb = (const float*)d_in[19];
    const float* projw   = (const float*)d_in[20];
    const float* headw   = (const float*)d_in[21];
    const float* headb   = (const float*)d_in[22];

    float  *gx, *gpe, *gc, *gz;
    __half *gq, *gh, *go, *gm, *gp;
    __half *wconv, *wqkv, *wproj, *wfc, *wcpr;
    cudaGetSymbolAddress((void**)&gx,  g_x);
    cudaGetSymbolAddress((void**)&gpe, g_pe);
    cudaGetSymbolAddress((void**)&gc,  g_cls);
    cudaGetSymbolAddress((void**)&gz,  g_z);
    cudaGetSymbolAddress((void**)&gq,  g_qkv);
    cudaGetSymbolAddress((void**)&gh,  g_h);
    cudaGetSymbolAddress((void**)&go,  g_o);
    cudaGetSymbolAddress((void**)&gm,  g_mlp);
    cudaGetSymbolAddress((void**)&gp,  g_pat);
    cudaGetSymbolAddress((void**)&wconv, g_wconv);
    cudaGetSymbolAddress((void**)&wqkv,  g_wqkv);
    cudaGetSymbolAddress((void**)&wproj, g_wproj);
    cudaGetSymbolAddress((void**)&wfc,   g_wfc);
    cudaGetSymbolAddress((void**)&wcpr,  g_wcpr);

    cudaFuncSetAttribute(attn_kernel, cudaFuncAttributeMaxDynamicSharedMemorySize, ATTN_SMEM);
    cudaFuncSetAttribute(gemm_h<float ,false,false>, cudaFuncAttributeMaxDynamicSharedMemorySize, GH_SMEM);
    cudaFuncSetAttribute(gemm_h<float ,false,true >, cudaFuncAttributeMaxDynamicSharedMemorySize, GH_SMEM);
    cudaFuncSetAttribute(gemm_h<__half,true ,false>, cudaFuncAttributeMaxDynamicSharedMemorySize, GH_SMEM);
    cudaFuncSetAttribute(gemm_h<__half,false,false>, cudaFuncAttributeMaxDynamicSharedMemorySize, GH_SMEM);

    // ---- weight conversion (single launch) ----
    f2h_all_kernel<<<(F2H_C4 + 255)/256, 256>>>(conv_w, wconv, qkvw, wqkv,
                                                pw, wproj, fw, wfc, cw, wcpr);

    const int GY  = MROWS/128 + 1;   // 50
    const int GYP = PROWS/128 + 1;   // 50

    // ---- patch embed ----
    im2col_kernel<<<(PROWS*DD + 255)/256, 256>>>(x_in);
    gemm_h<float,false,false><<<dim3(DD/128, GYP), 256, GH_SMEM>>>(
        gp, wconv, nullptr, nullptr, gpe, PROWS, DD, DD);
    assemble_ln_kernel<<<MROWS, 256>>>(gpe, cls_tok, pos, lnprew, lnpreb, gx);

    for (int l = 0; l < DEPTH; l++) {
        // attention sub-block
        ln_kernel<__half><<<MROWS/2, 512>>>(gx, gh, ln1w + l*DD, ln1b + l*DD, DD, DD);
        gemm_h<__half,false,false><<<dim3((3*DD)/128, GY), 256, GH_SMEM>>>(
            gh, wqkv + (size_t)l*3*DD*DD, qkvb + (long)l*3*DD, nullptr, gq, MROWS, 3*DD, DD);
        attn_kernel<<<BB*NH, 256, ATTN_SMEM>>>(gq, go);
        gemm_h<float,false,true><<<dim3(DD/128, GY), 256, GH_SMEM>>>(
            go, wproj + (size_t)l*DD*DD, pb + (long)l*DD, gx, gx, MROWS, DD, DD);
        // MLP sub-block
        ln_kernel<__half><<<MROWS/2, 512>>>(gx, gh, ln2w + l*DD, ln2b + l*DD, DD, DD);
        gemm_h<__half,true,false><<<dim3(MLPD/128, GY), 256, GH_SMEM>>>(
            gh, wfc + (size_t)l*MLPD*DD, fb + (long)l*MLPD, nullptr, gm, MROWS, MLPD, DD);
        gemm_h<float,false,true><<<dim3(DD/128, GY), 256, GH_SMEM>>>(
            gm, wcpr + (size_t)l*DD*MLPD, cb + (long)l*DD, gx, gx, MROWS, DD, MLPD);
    }

    // ---- head ----
    ln_kernel<float><<<BB/2, 512>>>(gx, gc, lnpostw, lnpostb, (long)NTOK*DD, DD);
    gemm_nt<<<dim3(PROJD/64, 1), 256>>>(gc, projw, nullptr, gz, BB, PROJD, DD);
    gemm_nt<<<dim3((NCLS+63)/64, 1), 256>>>(gz, headw, headb, (float*)d_out, BB, NCLS, PROJD);
}

// round 14
// speedup vs baseline: 9.9485x; 1.0074x over previous
#include <cuda_runtime.h>
#include <cuda_fp16.h>
#include <math.h>
#include <stdint.h>

// ---------------------------------------------------------------------------
// CLIP ViT-B/16 forward. Round 13: R12 + tail tiles moved to HIGHEST block ids
// so straggler waves consist of quarter-cost tiles.
// ---------------------------------------------------------------------------

#define BB      32
#define NTOK    197
#define NPAT    196
#define DD      768
#define DEPTH   12
#define NH      12
#define DH      64
#define MLPD    3072
#define PROJD   512
#define NCLS    1000
#define MROWS   (BB*NTOK)          // 6304
#define PROWS   (BB*NPAT)          // 6272

// fp32 buffers
__device__ __align__(128) float  g_x   [MROWS*DD];
__device__ __align__(128) float  g_pe  [PROWS*DD];
__device__ __align__(128) float  g_cls [BB*DD];
__device__ __align__(128) float  g_z   [BB*PROJD];
// fp16 buffers
__device__ __align__(128) __half g_qkv [MROWS*3*DD];
__device__ __align__(128) __half g_h   [MROWS*DD];
__device__ __align__(128) __half g_o   [MROWS*DD];
__device__ __align__(128) __half g_mlp [MROWS*MLPD];
__device__ __align__(128) __half g_pat [PROWS*DD];
// fp16 weights
__device__ __align__(128) __half g_wconv [DD*DD];
__device__ __align__(128) __half g_wqkv  [DEPTH*3*DD*DD];
__device__ __align__(128) __half g_wproj [DEPTH*DD*DD];
__device__ __align__(128) __half g_wfc   [DEPTH*MLPD*DD];
__device__ __align__(128) __half g_wcpr  [DEPTH*DD*MLPD];

// ---------------------------------------------------------------------------
// merged fp32 -> fp16 weight conversion
// ---------------------------------------------------------------------------
#define F2H_C0 (DD*DD/8)
#define F2H_C1 (F2H_C0 + DEPTH*3*DD*DD/8)
#define F2H_C2 (F2H_C1 + DEPTH*DD*DD/8)
#define F2H_C3 (F2H_C2 + DEPTH*MLPD*DD/8)
#define F2H_C4 (F2H_C3 + DEPTH*DD*MLPD/8)

__global__ void f2h_all_kernel(const float* __restrict__ s0, __half* d0,
                               const float* __restrict__ s1, __half* d1,
                               const float* __restrict__ s2, __half* d2,
                               const float* __restrict__ s3, __half* d3,
                               const float* __restrict__ s4, __half* d4) {
    int i = blockIdx.x * 256 + threadIdx.x;
    if (i >= F2H_C4) return;
    const float* src; __half* dst; int off;
    if      (i < F2H_C0) { src = s0; dst = d0; off = i; }
    else if (i < F2H_C1) { src = s1; dst = d1; off = i - F2H_C0; }
    else if (i < F2H_C2) { src = s2; dst = d2; off = i - F2H_C1; }
    else if (i < F2H_C3) { src = s3; dst = d3; off = i - F2H_C2; }
    else                 { src = s4; dst = d4; off = i - F2H_C3; }
    const float4* p = (const float4*)src + (size_t)off*2;
    float4 a = p[0], b = p[1];
    __half2 h0 = __floats2half2_rn(a.x, a.y);
    __half2 h1 = __floats2half2_rn(a.z, a.w);
    __half2 h2 = __floats2half2_rn(b.x, b.y);
    __half2 h3 = __floats2half2_rn(b.z, b.w);
    uint4 v;
    v.x = *(uint32_t*)&h0; v.y = *(uint32_t*)&h1;
    v.z = *(uint32_t*)&h2; v.w = *(uint32_t*)&h3;
    ((uint4*)dst)[off] = v;
}

// ---------------------------------------------------------------------------
// im2col
// ---------------------------------------------------------------------------
__global__ void im2col_kernel(const float* __restrict__ x) {
    int idx = blockIdx.x * 256 + threadIdx.x;
    if (idx >= PROWS * DD) return;
    int k = idx % DD;
    int m = idx / DD;
    int b = m / NPAT, p = m % NPAT;
    int ph = p / 14, pw = p % 14;
    int c = k >> 8, r = (k >> 4) & 15, col = k & 15;
    g_pat[idx] = __float2half_rn(x[(((long)(b*3 + c)*224 + ph*16 + r)*224) + pw*16 + col]);
}

// ---------------------------------------------------------------------------
// fused assemble + ln_pre
// ---------------------------------------------------------------------------
__global__ void assemble_ln_kernel(const float* __restrict__ pe,
                                   const float* __restrict__ cls_tok,
                                   const float* __restrict__ pos,
                                   const float* __restrict__ gam,
                                   const float* __restrict__ bet,
                                   float* __restrict__ out) {
    __shared__ float red[16];
    int row = blockIdx.x, tid = threadIdx.x;
    int b = row / NTOK, n = row % NTOK;
    float v0, v1, v2;
    if (n == 0) {
        v0 = cls_tok[tid      ] + pos[tid      ];
        v1 = cls_tok[tid + 256] + pos[tid + 256];
        v2 = cls_tok[tid + 512] + pos[tid + 512];
    } else {
        const float* per = pe + ((size_t)b*NPAT + (n-1))*DD;
        const float* por = pos + (size_t)n*DD;
        v0 = per[tid      ] + por[tid      ];
        v1 = per[tid + 256] + por[tid + 256];
        v2 = per[tid + 512] + por[tid + 512];
    }
    float s = v0 + v1 + v2;
    #pragma unroll
    for (int o = 16; o; o >>= 1) s += __shfl_xor_sync(0xffffffffu, s, o);
    if ((tid & 31) == 0) red[tid >> 5] = s;
    __syncthreads();
    float tot = red[0]+red[1]+red[2]+red[3]+red[4]+red[5]+red[6]+red[7];
    float mean = tot * (1.0f / 768.0f);
    float d0 = v0 - mean, d1 = v1 - mean, d2 = v2 - mean;
    float q = d0*d0 + d1*d1 + d2*d2;
    #pragma unroll
    for (int o = 16; o; o >>= 1) q += __shfl_xor_sync(0xffffffffu, q, o);
    if ((tid & 31) == 0) red[8 + (tid >> 5)] = q;
    __syncthreads();
    float var = (red[8]+red[9]+red[10]+red[11]+red[12]+red[13]+red[14]+red[15]) * (1.0f/768.0f);
    float rs = rsqrtf(var + 1e-5f);
    float* orow = out + (size_t)row * DD;
    orow[tid      ] = d0 * rs * gam[tid      ] + bet[tid      ];
    orow[tid + 256] = d1 * rs * gam[tid + 256] + bet[tid + 256];
    orow[tid + 512] = d2 * rs * gam[tid + 512] + bet[tid + 512];
}

// ---------------------------------------------------------------------------
// LayerNorm over 768: 2 rows per 512-thread block
// ---------------------------------------------------------------------------
template<typename OutT>
__global__ void ln_kernel(const float* __restrict__ in, OutT* __restrict__ out,
                          const float* __restrict__ gam, const float* __restrict__ bet,
                          long in_stride, long out_stride) {
    __shared__ float red[2][16];
    int sub = threadIdx.x >> 8;
    int tid = threadIdx.x & 255;
    int row = blockIdx.x * 2 + sub;
    const float* xr = in + (long)row * in_stride;
    float v0 = xr[tid], v1 = xr[tid + 256], v2 = xr[tid + 512];
    float s = v0 + v1 + v2;
    #pragma unroll
    for (int o = 16; o; o >>= 1) s += __shfl_xor_sync(0xffffffffu, s, o);
    if ((tid & 31) == 0) red[sub][tid >> 5] = s;
    __syncthreads();
    float* rd = red[sub];
    float tot = rd[0]+rd[1]+rd[2]+rd[3]+rd[4]+rd[5]+rd[6]+rd[7];
    float mean = tot * (1.0f / 768.0f);
    float d0 = v0 - mean, d1 = v1 - mean, d2 = v2 - mean;
    float q = d0*d0 + d1*d1 + d2*d2;
    #pragma unroll
    for (int o = 16; o; o >>= 1) q += __shfl_xor_sync(0xffffffffu, q, o);
    if ((tid & 31) == 0) red[sub][8 + (tid >> 5)] = q;
    __syncthreads();
    float var = (rd[8]+rd[9]+rd[10]+rd[11]+rd[12]+rd[13]+rd[14]+rd[15]) * (1.0f/768.0f);
    float rs = rsqrtf(var + 1e-5f);
    OutT* orow = out + (long)row * out_stride;
    orow[tid      ] = (OutT)(d0 * rs * gam[tid      ] + bet[tid      ]);
    orow[tid + 256] = (OutT)(d1 * rs * gam[tid + 256] + bet[tid + 256]);
    orow[tid + 512] = (OutT)(d2 * rs * gam[tid + 512] + bet[tid + 512]);
}

__device__ __forceinline__ float gelu_f(float v) {
    return 0.5f * v * (1.0f + erff(v * 0.70710678118654752f));
}

// ---------------------------------------------------------------------------
// common PTX helpers
// ---------------------------------------------------------------------------
__device__ __forceinline__ uint32_t smem_u32(const void* p) {
    uint32_t a;
    asm("{ .reg .u64 t; cvta.to.shared.u64 t, %1; cvt.u32.u64 %0, t; }" : "=r"(a) : "l"(p));
    return a;
}

#define LDSM_X4(r0,r1,r2,r3,addr) \
    asm volatile("ldmatrix.sync.aligned.m8n8.x4.shared.b16 {%0,%1,%2,%3}, [%4];" \
                 : "=r"(r0), "=r"(r1), "=r"(r2), "=r"(r3) : "r"(addr))

#define HMMA16816(d, a0,a1,a2,a3, b0,b1) \
    asm volatile("mma.sync.aligned.m16n8k16.row.col.f32.f16.f16.f32 " \
                 "{%0,%1,%2,%3}, {%4,%5,%6,%7}, {%8,%9}, {%0,%1,%2,%3};" \
                 : "+f"((d)[0]), "+f"((d)[1]), "+f"((d)[2]), "+f"((d)[3]) \
                 : "r"(a0), "r"(a1), "r"(a2), "r"(a3), "r"(b0), "r"(b1))

__device__ __forceinline__ void cp16(uint32_t saddr, const void* gaddr) {
    asm volatile("cp.async.cg.shared.global [%0], [%1], 16;" :: "r"(saddr), "l"(gaddr));
}
__device__ __forceinline__ void cp16z(uint32_t saddr, const void* gaddr, int sz) {
    asm volatile("cp.async.cg.shared.global [%0], [%1], 16, %2;" :: "r"(saddr), "l"(gaddr), "r"(sz));
}
#define CP_COMMIT() asm volatile("cp.async.commit_group;" ::: "memory")
#define CP_WAIT1()  asm volatile("cp.async.wait_group 1;" ::: "memory")

// ---------------------------------------------------------------------------
// fp16 tensor-core NT GEMM: BK=64, 3-stage cp.async. TAIL TILE IS THE LAST
// y-block (highest bids -> straggler waves are quarter-cost).
// ---------------------------------------------------------------------------
#define HPITCH  144
#define HSTAGE  (128*HPITCH*2)
#define GH_SMEM (3*HSTAGE)

template<typename OutT, bool GELU, bool RES>
__global__ __launch_bounds__(256, 2)
void gemm_h(const __half* __restrict__ A, const __half* __restrict__ W,
            const float* __restrict__ bias, const float* __restrict__ Rs,
            OutT* __restrict__ Cp, int M, int N, int K) {
    extern __shared__ uint8_t smem[];
    const uint32_t sb = smem_u32(smem);
    const int tid = threadIdx.x, lane = tid & 31, warp = tid >> 5;
    const int wm = warp >> 2, wn = warp & 3;
    const int by = blockIdx.y;
    const bool tail = (by == gridDim.y - 1);       // tail LAST
    const int m0 = tail ? ((M >> 7) << 7) : (by << 7);
    const int n0 = blockIdx.x * 128;

    float acc[4][4][4];
    #pragma unroll
    for (int i=0;i<4;i++)
      #pragma unroll
      for (int j=0;j<4;j++)
        #pragma unroll
        for (int f=0;f<4;f++) acc[i][j][f]=0.f;

    const int T = K >> 6;

    const int row0 = tid >> 3, ch = tid & 7;
    int    szA[4];
    size_t offA[4];
    #pragma unroll
    for (int it = 0; it < 4; it++) {
        int r = m0 + row0 + it*32;
        szA[it]  = (r < M) ? 16 : 0;
        offA[it] = szA[it] ? ((size_t)r * K + ch*8) : 0;
    }
    const __half* Bbase = W + (size_t)(n0 + row0) * K + ch*8;
    const uint32_t sbase = sb + (uint32_t)row0 * HPITCH + ch*16;

    auto issue_stage = [&](int t, int s) {
        if (t < T) {
            uint32_t so = sbase + (uint32_t)s * HSTAGE;
            int ko = t * 64;
            #pragma unroll
            for (int it = 0; it < 4; it++)
                cp16z(so + it*(32*HPITCH), A + offA[it] + (szA[it] ? ko : 0), szA[it]);
            #pragma unroll
            for (int it = 0; it < 4; it++)
                cp16(so + 128*HPITCH + it*(32*HPITCH), Bbase + (size_t)it*32*K + ko);
        }
        CP_COMMIT();
    };

    const uint32_t aoff = (uint32_t)(wm*64 + (lane & 15)) * HPITCH + (lane >> 4) * 16;
    const uint32_t boff = 128*HPITCH
                        + (uint32_t)(wn*32 + (lane & 7) + ((lane >> 4) << 3)) * HPITCH
                        + ((lane >> 3) & 1) * 16;

    issue_stage(0, 0);
    issue_stage(1, 1);

    int cur = 0, nxt = 2;
    for (int t = 0; t < T; t++) {
        CP_WAIT1();
        __syncthreads();
        issue_stage(t + 2, nxt);
        nxt = (nxt == 2) ? 0 : nxt + 1;
        const uint32_t stb = sb + (uint32_t)cur * HSTAGE;
        cur = (cur == 2) ? 0 : cur + 1;

        if (tail) {
            if (wm == 0) {
                #pragma unroll
                for (int kc = 0; kc < 4; kc++) {
                    uint32_t af[2][4];
                    #pragma unroll
                    for (int mt = 0; mt < 2; mt++) {
                        uint32_t addr = stb + aoff + mt*16*HPITCH + kc*32;
                        LDSM_X4(af[mt][0], af[mt][1], af[mt][2], af[mt][3], addr);
                    }
                    uint32_t bf[2][4];
                    #pragma unroll
                    for (int pr = 0; pr < 2; pr++) {
                        uint32_t addr = stb + boff + pr*16*HPITCH + kc*32;
                        LDSM_X4(bf[pr][0], bf[pr][1], bf[pr][2], bf[pr][3], addr);
                    }
                    #pragma unroll
                    for (int mt = 0; mt < 2; mt++)
                        #pragma unroll
                        for (int nt = 0; nt < 4; nt++)
                            HMMA16816(acc[mt][nt],
                                      af[mt][0], af[mt][1], af[mt][2], af[mt][3],
                                      bf[nt>>1][(nt&1)*2], bf[nt>>1][(nt&1)*2+1]);
                }
            }
        } else {
            #pragma unroll
            for (int kc = 0; kc < 4; kc++) {
                uint32_t af[4][4];
                #pragma unroll
                for (int mt = 0; mt < 4; mt++) {
                    uint32_t addr = stb + aoff + mt*16*HPITCH + kc*32;
                    LDSM_X4(af[mt][0], af[mt][1], af[mt][2], af[mt][3], addr);
                }
                uint32_t bf[2][4];
                #pragma unroll
                for (int pr = 0; pr < 2; pr++) {
                    uint32_t addr = stb + boff + pr*16*HPITCH + kc*32;
                    LDSM_X4(bf[pr][0], bf[pr][1], bf[pr][2], bf[pr][3], addr);
                }
                #pragma unroll
                for (int mt = 0; mt < 4; mt++) {
                    #pragma unroll
                    for (int nt = 0; nt < 4; nt++) {
                        HMMA16816(acc[mt][nt],
                                  af[mt][0], af[mt][1], af[mt][2], af[mt][3],
                                  bf[nt>>1][(nt&1)*2], bf[nt>>1][(nt&1)*2+1]);
                    }
                }
            }
        }
    }

    const int lr = lane >> 2, lc = lane & 3;
    if (tail && wm != 0) return;
    const int mtN = tail ? 2 : 4;
    for (int mt = 0; mt < mtN; mt++) {
        int r0 = m0 + wm*64 + mt*16 + lr;
        #pragma unroll
        for (int nt = 0; nt < 4; nt++) {
            int cc = n0 + wn*32 + nt*8 + lc*2;
            float v0 = acc[mt][nt][0], v1 = acc[mt][nt][1];
            float v2 = acc[mt][nt][2], v3 = acc[mt][nt][3];
            if (bias) {
                float bb0 = bias[cc], bb1 = bias[cc+1];
                v0 += bb0; v1 += bb1; v2 += bb0; v3 += bb1;
            }
            if (RES) {
                if (r0 < M) {
                    float2 rr = *(const float2*)&Rs[(size_t)r0*N + cc];
                    v0 += rr.x; v1 += rr.y;
                }
                if (r0 + 8 < M) {
                    float2 rr = *(const float2*)&Rs[(size_t)(r0+8)*N + cc];
                    v2 += rr.x; v3 += rr.y;
                }
            }
            if (GELU) { v0 = gelu_f(v0); v1 = gelu_f(v1); v2 = gelu_f(v2); v3 = gelu_f(v3); }
            if (sizeof(OutT) == 4) {
                if (r0 < M)     *(float2*)&(((float*)Cp)[(size_t)r0*N + cc])     = make_float2(v0, v1);
                if (r0 + 8 < M) *(float2*)&(((float*)Cp)[(size_t)(r0+8)*N + cc]) = make_float2(v2, v3);
            } else {
                if (r0 < M) {
                    __half2 h = __floats2half2_rn(v0, v1);
                    *(__half2*)&(((__half*)Cp)[(size_t)r0*N + cc]) = h;
                }
                if (r0 + 8 < M) {
                    __half2 h = __floats2half2_rn(v2, v3);
                    *(__half2*)&(((__half*)Cp)[(size_t)(r0+8)*N + cc]) = h;
                }
            }
        }
    }
}

// ---------------------------------------------------------------------------
// SIMT NT SGEMM for the tiny head GEMMs (M=32), fp32
// ---------------------------------------------------------------------------
__global__ void gemm_nt(const float* __restrict__ A, const float* __restrict__ W,
                        const float* __restrict__ bias, float* __restrict__ C,
                        int M, int N, int K) {
    __shared__ float As[16][64];
    __shared__ float Bs[16][64];
    int tid = threadIdx.x;
    int tx = tid & 15, ty = tid >> 4;
    int m0 = blockIdx.y * 64, n0 = blockIdx.x * 64;
    int lr = tid >> 2;
    int lc = (tid & 3) << 2;
    float acc[4][4] = {};
    const float* Aptr = A + (long)(m0 + lr) * K + lc;
    const float* Wptr = W + (long)(n0 + lr) * K + lc;
    bool am = (m0 + lr) < M;
    bool wn = (n0 + lr) < N;
    for (int k0 = 0; k0 < K; k0 += 16) {
        float4 av = am ? *(const float4*)(Aptr + k0) : make_float4(0.f,0.f,0.f,0.f);
        float4 wv = wn ? *(const float4*)(Wptr + k0) : make_float4(0.f,0.f,0.f,0.f);
        As[lc+0][lr]=av.x; As[lc+1][lr]=av.y; As[lc+2][lr]=av.z; As[lc+3][lr]=av.w;
        Bs[lc+0][lr]=wv.x; Bs[lc+1][lr]=wv.y; Bs[lc+2][lr]=wv.z; Bs[lc+3][lr]=wv.w;
        __syncthreads();
        #pragma unroll
        for (int kk = 0; kk < 16; kk++) {
            float4 a = *(const float4*)(&As[kk][ty << 2]);
            float4 b = *(const float4*)(&Bs[kk][tx << 2]);
            acc[0][0] += a.x*b.x; acc[0][1] += a.x*b.y; acc[0][2] += a.x*b.z; acc[0][3] += a.x*b.w;
            acc[1][0] += a.y*b.x; acc[1][1] += a.y*b.y; acc[1][2] += a.y*b.z; acc[1][3] += a.y*b.w;
            acc[2][0] += a.z*b.x; acc[2][1] += a.z*b.y; acc[2][2] += a.z*b.z; acc[2][3] += a.z*b.w;
            acc[3][0] += a.w*b.x; acc[3][1] += a.w*b.y; acc[3][2] += a.w*b.z; acc[3][3] += a.w*b.w;
        }
        __syncthreads();
    }
    #pragma unroll
    for (int i = 0; i < 4; i++) {
        int m = m0 + (ty << 2) + i;
        if (m >= M) continue;
        #pragma unroll
        for (int j = 0; j < 4; j++) {
            int n = n0 + (tx << 2) + j;
            if (n >= N) continue;
            float v = acc[i][j];
            if (bias) v += bias[n];
            C[(long)m * N + n] = v;
        }
    }
}

// ---------------------------------------------------------------------------
// HMMA flash-style attention (unchanged from R12 — verified).
// ---------------------------------------------------------------------------
#define SEQP    208
#define KPITCH  72
#define VPITCH  216
#define PPITCH  216
#define ATTN_SMEM ((SEQP*KPITCH + 64*VPITCH + 8*16*PPITCH) * 2)   // 112896

__global__ __launch_bounds__(256)
void attn_kernel(const __half* __restrict__ qkv, __half* __restrict__ out) {
    int b = blockIdx.x / NH, h = blockIdx.x % NH;
    int tid = threadIdx.x, lane = tid & 31, warp = tid >> 5;
    extern __shared__ __half sh[];
    __half* Ks = sh;
    __half* Vt = Ks + SEQP*KPITCH;
    __half* Pw = Vt + 64*VPITCH + warp*16*PPITCH;

    const __half* base = qkv + (size_t)b * NTOK * (3*DD) + h * DH;

    for (int idx = tid; idx < NTOK*8; idx += 256) {
        int j = idx >> 3, c = idx & 7;
        *(uint4*)&Ks[j*KPITCH + c*8] = *(const uint4*)&base[(size_t)j*(3*DD) + DD + c*8];
    }
    for (int idx = tid; idx < (SEQP-NTOK)*KPITCH; idx += 256) {
        Ks[(NTOK + idx/KPITCH)*KPITCH + (idx % KPITCH)] = __half(0.0f);
    }
    for (int idx = tid; idx < NTOK*64; idx += 256) {
        int j = idx >> 6, d = idx & 63;
        Vt[d*VPITCH + j] = base[(size_t)j*(3*DD) + 2*DD + d];
    }
    for (int idx = tid; idx < 64*(VPITCH-NTOK); idx += 256) {
        int d = idx / (VPITCH-NTOK), c = NTOK + idx % (VPITCH-NTOK);
        Vt[d*VPITCH + c] = __half(0.0f);
    }
    __syncthreads();

    const uint32_t KsB = smem_u32(Ks);
    const uint32_t VtB = smem_u32(Vt);
    const uint32_t PwB = smem_u32(Pw);
    const int lr = lane >> 2, lc = lane & 3;
    const uint32_t browoff = ((lane & 7) + ((lane >> 4) << 3));
    const uint32_t bcol = ((lane >> 3) & 1) * 16;
    const uint32_t aoff = PwB + (uint32_t)(lane & 15) * (PPITCH*2) + (lane >> 4) * 16;

    for (int s = warp; s < 13; s += 8) {
        const int m0 = s * 16;
        #pragma unroll
        for (int t = 0; t < 4; t++) {
            int idx = lane + t*32;
            int r = idx >> 3, c = idx & 7;
            int q = m0 + r;
            uint4 v = make_uint4(0u,0u,0u,0u);
            if (q < NTOK) v = *(const uint4*)&base[(size_t)q*(3*DD) + c*8];
            *(uint4*)&Pw[r*PPITCH + c*8] = v;
        }
        __syncwarp();
        uint32_t af[4][4];
        #pragma unroll
        for (int kc = 0; kc < 4; kc++)
            LDSM_X4(af[kc][0], af[kc][1], af[kc][2], af[kc][3], aoff + kc*32);

        float acc[26][4];
        #pragma unroll
        for (int nt = 0; nt < 26; nt++) {
            acc[nt][0]=0.f; acc[nt][1]=0.f; acc[nt][2]=0.f; acc[nt][3]=0.f;
        }
        #pragma unroll
        for (int kc = 0; kc < 4; kc++) {
            #pragma unroll
            for (int g = 0; g < 13; g++) {
                uint32_t b0,b1,b2,b3;
                LDSM_X4(b0,b1,b2,b3,
                        KsB + (g*16 + browoff)*(KPITCH*2) + bcol + kc*32);
                HMMA16816(acc[2*g  ], af[kc][0],af[kc][1],af[kc][2],af[kc][3], b0, b1);
                HMMA16816(acc[2*g+1], af[kc][0],af[kc][1],af[kc][2],af[kc][3], b2, b3);
            }
        }

        float mx1 = -1e30f, mx2 = -1e30f;
        #pragma unroll
        for (int nt = 0; nt < 26; nt++) {
            #pragma unroll
            for (int e = 0; e < 2; e++) {
                int col = nt*8 + lc*2 + e;
                bool ok = col < NTOK;
                float s1 = ok ? acc[nt][e]   * 0.125f : -1e30f;
                float s2 = ok ? acc[nt][2+e] * 0.125f : -1e30f;
                acc[nt][e] = s1; acc[nt][2+e] = s2;
                mx1 = fmaxf(mx1, s1); mx2 = fmaxf(mx2, s2);
            }
        }
        #pragma unroll
        for (int o = 1; o <= 2; o <<= 1) {
            mx1 = fmaxf(mx1, __shfl_xor_sync(0xffffffffu, mx1, o));
            mx2 = fmaxf(mx2, __shfl_xor_sync(0xffffffffu, mx2, o));
        }
        float sum1 = 0.f, sum2 = 0.f;
        #pragma unroll
        for (int nt = 0; nt < 26; nt++) {
            #pragma unroll
            for (int e = 0; e < 2; e++) {
                float p1 = expf(acc[nt][e]   - mx1);
                float p2 = expf(acc[nt][2+e] - mx2);
                acc[nt][e] = p1; acc[nt][2+e] = p2;
                sum1 += p1; sum2 += p2;
            }
        }
        #pragma unroll
        for (int o = 1; o <= 2; o <<= 1) {
            sum1 += __shfl_xor_sync(0xffffffffu, sum1, o);
            sum2 += __shfl_xor_sync(0xffffffffu, sum2, o);
        }
        #pragma unroll
        for (int nt = 0; nt < 26; nt++) {
            int col = nt*8 + lc*2;
            __half2 p1 = __floats2half2_rn(acc[nt][0], acc[nt][1]);
            __half2 p2 = __floats2half2_rn(acc[nt][2], acc[nt][3]);
            *(__half2*)&Pw[ lr   *PPITCH + col] = p1;
            *(__half2*)&Pw[(lr+8)*PPITCH + col] = p2;
        }
        __syncwarp();

        float oacc[8][4];
        #pragma unroll
        for (int nt = 0; nt < 8; nt++) {
            oacc[nt][0]=0.f; oacc[nt][1]=0.f; oacc[nt][2]=0.f; oacc[nt][3]=0.f;
        }
        for (int kt = 0; kt < 13; kt++) {
            uint32_t pa0,pa1,pa2,pa3;
            LDSM_X4(pa0,pa1,pa2,pa3, aoff + kt*32);
            #pragma unroll
            for (int g = 0; g < 4; g++) {
                uint32_t b0,b1,b2,b3;
                LDSM_X4(b0,b1,b2,b3,
                        VtB + (g*16 + browoff)*(VPITCH*2) + bcol + kt*32);
                HMMA16816(oacc[2*g  ], pa0,pa1,pa2,pa3, b0, b1);
                HMMA16816(oacc[2*g+1], pa0,pa1,pa2,pa3, b2, b3);
            }
        }

        float inv1 = 1.0f / sum1, inv2 = 1.0f / sum2;
        int q1 = m0 + lr, q2 = m0 + lr + 8;
        #pragma unroll
        for (int nt = 0; nt < 8; nt++) {
            int col = nt*8 + lc*2;
            if (q1 < NTOK) {
                __half2 hv = __floats2half2_rn(oacc[nt][0]*inv1, oacc[nt][1]*inv1);
                *(__half2*)&out[((size_t)b*NTOK + q1)*DD + h*DH + col] = hv;
            }
            if (q2 < NTOK) {
                __half2 hv = __floats2half2_rn(oacc[nt][2]*inv2, oacc[nt][3]*inv2);
                *(__half2*)&out[((size_t)b*NTOK + q2)*DD + h*DH + col] = hv;
            }
        }
        __syncwarp();
    }
}

// ---------------------------------------------------------------------------
// host orchestration
// ---------------------------------------------------------------------------
extern "C" void kernel_launch(void* const* d_in, const int* in_sizes, int n_in,
                              void* d_out, int out_size) {
    const float* x_in    = (const float*)d_in[0];
    const float* conv_w  = (const float*)d_in[1];
    const float* cls_tok = (const float*)d_in[2];
    const float* pos     = (const float*)d_in[3];
    const float* lnprew  = (const float*)d_in[4];
    const float* lnpreb  = (const float*)d_in[5];
    const float* ln1w    = (const float*)d_in[6];
    const float* ln1b    = (const float*)d_in[7];
    const float* qkvw    = (const float*)d_in[8];
    const float* qkvb    = (const float*)d_in[9];
    const float* pw      = (const float*)d_in[10];
    const float* pb      = (const float*)d_in[11];
    const float* ln2w    = (const float*)d_in[12];
    const float* ln2b    = (const float*)d_in[13];
    const float* fw      = (const float*)d_in[14];
    const float* fb      = (const float*)d_in[15];
    const float* cw      = (const float*)d_in[16];
    const float* cb      = (const float*)d_in[17];
    const float* lnpostw = (const float*)d_in[18];
    const float* lnpostb = (const float*)d_in[19];
    const float* projw   = (const float*)d_in[20];
    const float* headw   = (const float*)d_in[21];
    const float* headb   = (const float*)d_in[22];

    float  *gx, *gpe, *gc, *gz;
    __half *gq, *gh, *go, *gm, *gp;
    __half *wconv, *wqkv, *wproj, *wfc, *wcpr;
    cudaGetSymbolAddress((void**)&gx,  g_x);
    cudaGetSymbolAddress((void**)&gpe, g_pe);
    cudaGetSymbolAddress((void**)&gc,  g_cls);
    cudaGetSymbolAddress((void**)&gz,  g_z);
    cudaGetSymbolAddress((void**)&gq,  g_qkv);
    cudaGetSymbolAddress((void**)&gh,  g_h);
    cudaGetSymbolAddress((void**)&go,  g_o);
    cudaGetSymbolAddress((void**)&gm,  g_mlp);
    cudaGetSymbolAddress((void**)&gp,  g_pat);
    cudaGetSymbolAddress((void**)&wconv, g_wconv);
    cudaGetSymbolAddress((void**)&wqkv,  g_wqkv);
    cudaGetSymbolAddress((void**)&wproj, g_wproj);
    cudaGetSymbolAddress((void**)&wfc,   g_wfc);
    cudaGetSymbolAddress((void**)&wcpr,  g_wcpr);

    cudaFuncSetAttribute(attn_kernel, cudaFuncAttributeMaxDynamicSharedMemorySize, ATTN_SMEM);
    cudaFuncSetAttribute(gemm_h<float ,false,false>, cudaFuncAttributeMaxDynamicSharedMemorySize, GH_SMEM);
    cudaFuncSetAttribute(gemm_h<float ,false,true >, cudaFuncAttributeMaxDynamicSharedMemorySize, GH_SMEM);
    cudaFuncSetAttribute(gemm_h<__half,true ,false>, cudaFuncAttributeMaxDynamicSharedMemorySize, GH_SMEM);
    cudaFuncSetAttribute(gemm_h<__half,false,false>, cudaFuncAttributeMaxDynamicSharedMemorySize, GH_SMEM);

    // ---- weight conversion (single launch) ----
    f2h_all_kernel<<<(F2H_C4 + 255)/256, 256>>>(conv_w, wconv, qkvw, wqkv,
                                                pw, wproj, fw, wfc, cw, wcpr);

    const int GY  = MROWS/128 + 1;   // 50 (last block = 32-row tail)
    const int GYP = PROWS/128 + 1;   // 50 (last block = empty tail)

    // ---- patch embed ----
    im2col_kernel<<<(PROWS*DD + 255)/256, 256>>>(x_in);
    gemm_h<float,false,false><<<dim3(DD/128, GYP), 256, GH_SMEM>>>(
        gp, wconv, nullptr, nullptr, gpe, PROWS, DD, DD);
    assemble_ln_kernel<<<MROWS, 256>>>(gpe, cls_tok, pos, lnprew, lnpreb, gx);

    for (int l = 0; l < DEPTH; l++) {
        // attention sub-block
        ln_kernel<__half><<<MROWS/2, 512>>>(gx, gh, ln1w + l*DD, ln1b + l*DD, DD, DD);
        gemm_h<__half,false,false><<<dim3((3*DD)/128, GY), 256, GH_SMEM>>>(
            gh, wqkv + (size_t)l*3*DD*DD, qkvb + (long)l*3*DD, nullptr, gq, MROWS, 3*DD, DD);
        attn_kernel<<<BB*NH, 256, ATTN_SMEM>>>(gq, go);
        gemm_h<float,false,true><<<dim3(DD/128, GY), 256, GH_SMEM>>>(
            go, wproj + (size_t)l*DD*DD, pb + (long)l*DD, gx, gx, MROWS, DD, DD);
        // MLP sub-block
        ln_kernel<__half><<<MROWS/2, 512>>>(gx, gh, ln2w + l*DD, ln2b + l*DD, DD, DD);
        gemm_h<__half,true,false><<<dim3(MLPD/128, GY), 256, GH_SMEM>>>(
            gh, wfc + (size_t)l*MLPD*DD, fb + (long)l*MLPD, nullptr, gm, MROWS, MLPD, DD);
        gemm_h<float,false,true><<<dim3(DD/128, GY), 256, GH_SMEM>>>(
            gm, wcpr + (size_t)l*DD*MLPD, cb + (long)l*DD, gx, gx, MROWS, DD, MLPD);
    }

    // ---- head ----
    ln_kernel<float><<<BB/2, 512>>>(gx, gc, lnpostw, lnpostb, (long)NTOK*DD, DD);
    gemm_nt<<<dim3(PROJD/64, 1), 256>>>(gc, projw, nullptr, gz, BB, PROJD, DD);
    gemm_nt<<<dim3((NCLS+63)/64, 1), 256>>>(gz, headw, headb, (float*)d_out, BB, NCLS, PROJD);
}

// round 15
// speedup vs baseline: 10.5109x; 1.0565x over previous
#include <cuda_runtime.h>
#include <cuda_fp16.h>
#include <math.h>
#include <stdint.h>

// ---------------------------------------------------------------------------
// CLIP ViT-B/16 forward. Round 14: last-layer dead-work elimination (MLP only
// on 32 cls rows) + warp-per-row LayerNorm. GEMM/attention = verified R13.
// ---------------------------------------------------------------------------

#define BB      32
#define NTOK    197
#define NPAT    196
#define DD      768
#define DEPTH   12
#define NH      12
#define DH      64
#define MLPD    3072
#define PROJD   512
#define NCLS    1000
#define MROWS   (BB*NTOK)          // 6304
#define PROWS   (BB*NPAT)          // 6272

// fp32 buffers
__device__ __align__(128) float  g_x   [MROWS*DD];
__device__ __align__(128) float  g_pe  [PROWS*DD];
__device__ __align__(128) float  g_cls [BB*DD];
__device__ __align__(128) float  g_cr  [BB*DD];      // gathered cls residual
__device__ __align__(128) float  g_cx2 [BB*DD];      // cls after attn-proj
__device__ __align__(128) float  g_cx3 [BB*DD];      // cls after c-proj
__device__ __align__(128) float  g_z   [BB*PROJD];
// fp16 buffers
__device__ __align__(128) __half g_qkv [MROWS*3*DD];
__device__ __align__(128) __half g_h   [MROWS*DD];
__device__ __align__(128) __half g_o   [MROWS*DD];
__device__ __align__(128) __half g_mlp [MROWS*MLPD];
__device__ __align__(128) __half g_pat [PROWS*DD];
__device__ __align__(128) __half g_ca  [BB*DD];      // gathered cls fp16 (A operand)
// fp16 weights
__device__ __align__(128) __half g_wconv [DD*DD];
__device__ __align__(128) __half g_wqkv  [DEPTH*3*DD*DD];
__device__ __align__(128) __half g_wproj [DEPTH*DD*DD];
__device__ __align__(128) __half g_wfc   [DEPTH*MLPD*DD];
__device__ __align__(128) __half g_wcpr  [DEPTH*DD*MLPD];

// ---------------------------------------------------------------------------
// merged fp32 -> fp16 weight conversion
// ---------------------------------------------------------------------------
#define F2H_C0 (DD*DD/8)
#define F2H_C1 (F2H_C0 + DEPTH*3*DD*DD/8)
#define F2H_C2 (F2H_C1 + DEPTH*DD*DD/8)
#define F2H_C3 (F2H_C2 + DEPTH*MLPD*DD/8)
#define F2H_C4 (F2H_C3 + DEPTH*DD*MLPD/8)

__global__ void f2h_all_kernel(const float* __restrict__ s0, __half* d0,
                               const float* __restrict__ s1, __half* d1,
                               const float* __restrict__ s2, __half* d2,
                               const float* __restrict__ s3, __half* d3,
                               const float* __restrict__ s4, __half* d4) {
    int i = blockIdx.x * 256 + threadIdx.x;
    if (i >= F2H_C4) return;
    const float* src; __half* dst; int off;
    if      (i < F2H_C0) { src = s0; dst = d0; off = i; }
    else if (i < F2H_C1) { src = s1; dst = d1; off = i - F2H_C0; }
    else if (i < F2H_C2) { src = s2; dst = d2; off = i - F2H_C1; }
    else if (i < F2H_C3) { src = s3; dst = d3; off = i - F2H_C2; }
    else                 { src = s4; dst = d4; off = i - F2H_C3; }
    const float4* p = (const float4*)src + (size_t)off*2;
    float4 a = p[0], b = p[1];
    __half2 h0 = __floats2half2_rn(a.x, a.y);
    __half2 h1 = __floats2half2_rn(a.z, a.w);
    __half2 h2 = __floats2half2_rn(b.x, b.y);
    __half2 h3 = __floats2half2_rn(b.z, b.w);
    uint4 v;
    v.x = *(uint32_t*)&h0; v.y = *(uint32_t*)&h1;
    v.z = *(uint32_t*)&h2; v.w = *(uint32_t*)&h3;
    ((uint4*)dst)[off] = v;
}

// ---------------------------------------------------------------------------
// im2col
// ---------------------------------------------------------------------------
__global__ void im2col_kernel(const float* __restrict__ x) {
    int idx = blockIdx.x * 256 + threadIdx.x;
    if (idx >= PROWS * DD) return;
    int k = idx % DD;
    int m = idx / DD;
    int b = m / NPAT, p = m % NPAT;
    int ph = p / 14, pw = p % 14;
    int c = k >> 8, r = (k >> 4) & 15, col = k & 15;
    g_pat[idx] = __float2half_rn(x[(((long)(b*3 + c)*224 + ph*16 + r)*224) + pw*16 + col]);
}

// ---------------------------------------------------------------------------
// fused assemble + ln_pre (unchanged)
// ---------------------------------------------------------------------------
__global__ void assemble_ln_kernel(const float* __restrict__ pe,
                                   const float* __restrict__ cls_tok,
                                   const float* __restrict__ pos,
                                   const float* __restrict__ gam,
                                   const float* __restrict__ bet,
                                   float* __restrict__ out) {
    __shared__ float red[16];
    int row = blockIdx.x, tid = threadIdx.x;
    int b = row / NTOK, n = row % NTOK;
    float v0, v1, v2;
    if (n == 0) {
        v0 = cls_tok[tid      ] + pos[tid      ];
        v1 = cls_tok[tid + 256] + pos[tid + 256];
        v2 = cls_tok[tid + 512] + pos[tid + 512];
    } else {
        const float* per = pe + ((size_t)b*NPAT + (n-1))*DD;
        const float* por = pos + (size_t)n*DD;
        v0 = per[tid      ] + por[tid      ];
        v1 = per[tid + 256] + por[tid + 256];
        v2 = per[tid + 512] + por[tid + 512];
    }
    float s = v0 + v1 + v2;
    #pragma unroll
    for (int o = 16; o; o >>= 1) s += __shfl_xor_sync(0xffffffffu, s, o);
    if ((tid & 31) == 0) red[tid >> 5] = s;
    __syncthreads();
    float tot = red[0]+red[1]+red[2]+red[3]+red[4]+red[5]+red[6]+red[7];
    float mean = tot * (1.0f / 768.0f);
    float d0 = v0 - mean, d1 = v1 - mean, d2 = v2 - mean;
    float q = d0*d0 + d1*d1 + d2*d2;
    #pragma unroll
    for (int o = 16; o; o >>= 1) q += __shfl_xor_sync(0xffffffffu, q, o);
    if ((tid & 31) == 0) red[8 + (tid >> 5)] = q;
    __syncthreads();
    float var = (red[8]+red[9]+red[10]+red[11]+red[12]+red[13]+red[14]+red[15]) * (1.0f/768.0f);
    float rs = rsqrtf(var + 1e-5f);
    float* orow = out + (size_t)row * DD;
    orow[tid      ] = d0 * rs * gam[tid      ] + bet[tid      ];
    orow[tid + 256] = d1 * rs * gam[tid + 256] + bet[tid + 256];
    orow[tid + 512] = d2 * rs * gam[tid + 512] + bet[tid + 512];
}

// ---------------------------------------------------------------------------
// LayerNorm over 768: warp-per-row, no barriers. 256 threads = 8 rows/block.
// ---------------------------------------------------------------------------
template<typename OutT>
__global__ void ln_warp(const float* __restrict__ in, OutT* __restrict__ out,
                        const float* __restrict__ gam, const float* __restrict__ bet,
                        long in_stride, long out_stride) {
    int warp = threadIdx.x >> 5, lane = threadIdx.x & 31;
    int row = blockIdx.x * 8 + warp;
    const float4* xr = (const float4*)(in + (size_t)row * in_stride);
    float4 v[6];
    float s = 0.f;
    #pragma unroll
    for (int j = 0; j < 6; j++) {
        v[j] = xr[lane + 32*j];
        s += (v[j].x + v[j].y) + (v[j].z + v[j].w);
    }
    #pragma unroll
    for (int o = 16; o; o >>= 1) s += __shfl_xor_sync(0xffffffffu, s, o);
    float mean = s * (1.0f/768.0f);
    float q = 0.f;
    #pragma unroll
    for (int j = 0; j < 6; j++) {
        v[j].x -= mean; v[j].y -= mean; v[j].z -= mean; v[j].w -= mean;
        q += (v[j].x*v[j].x + v[j].y*v[j].y) + (v[j].z*v[j].z + v[j].w*v[j].w);
    }
    #pragma unroll
    for (int o = 16; o; o >>= 1) q += __shfl_xor_sync(0xffffffffu, q, o);
    float rs = rsqrtf(q * (1.0f/768.0f) + 1e-5f);
    const float4* g4 = (const float4*)gam;
    const float4* b4 = (const float4*)bet;
    if (sizeof(OutT) == 2) {
        __half* orow = (__half*)out + (size_t)row * out_stride;
        #pragma unroll
        for (int j = 0; j < 6; j++) {
            float4 g = g4[lane + 32*j], bb = b4[lane + 32*j];
            __half2 h0 = __floats2half2_rn(v[j].x*rs*g.x + bb.x, v[j].y*rs*g.y + bb.y);
            __half2 h1 = __floats2half2_rn(v[j].z*rs*g.z + bb.z, v[j].w*rs*g.w + bb.w);
            uint2 u; u.x = *(uint32_t*)&h0; u.y = *(uint32_t*)&h1;
            *(uint2*)&orow[(lane + 32*j)*4] = u;
        }
    } else {
        float* orow = (float*)out + (size_t)row * out_stride;
        #pragma unroll
        for (int j = 0; j < 6; j++) {
            float4 g = g4[lane + 32*j], bb = b4[lane + 32*j];
            float4 o4;
            o4.x = v[j].x*rs*g.x + bb.x; o4.y = v[j].y*rs*g.y + bb.y;
            o4.z = v[j].z*rs*g.z + bb.z; o4.w = v[j].w*rs*g.w + bb.w;
            ((float4*)orow)[lane + 32*j] = o4;
        }
    }
}

__device__ __forceinline__ float gelu_f(float v) {
    return 0.5f * v * (1.0f + erff(v * 0.70710678118654752f));
}

// ---------------------------------------------------------------------------
// gather cls rows: attn-out (fp16) and residual (fp32) -> compact 32-row bufs
// ---------------------------------------------------------------------------
__global__ void gather_cls_kernel(const __half* __restrict__ go,
                                  const float* __restrict__ gx,
                                  __half* __restrict__ a16,
                                  float* __restrict__ r32) {
    int idx = blockIdx.x * 256 + threadIdx.x;
    if (idx >= BB*DD) return;
    int b = idx / DD, d = idx % DD;
    size_t src = (size_t)b * NTOK * DD + d;
    a16[idx] = go[src];
    r32[idx] = gx[src];
}

// ---------------------------------------------------------------------------
// common PTX helpers
// ---------------------------------------------------------------------------
__device__ __forceinline__ uint32_t smem_u32(const void* p) {
    uint32_t a;
    asm("{ .reg .u64 t; cvta.to.shared.u64 t, %1; cvt.u32.u64 %0, t; }" : "=r"(a) : "l"(p));
    return a;
}

#define LDSM_X4(r0,r1,r2,r3,addr) \
    asm volatile("ldmatrix.sync.aligned.m8n8.x4.shared.b16 {%0,%1,%2,%3}, [%4];" \
                 : "=r"(r0), "=r"(r1), "=r"(r2), "=r"(r3) : "r"(addr))

#define HMMA16816(d, a0,a1,a2,a3, b0,b1) \
    asm volatile("mma.sync.aligned.m16n8k16.row.col.f32.f16.f16.f32 " \
                 "{%0,%1,%2,%3}, {%4,%5,%6,%7}, {%8,%9}, {%0,%1,%2,%3};" \
                 : "+f"((d)[0]), "+f"((d)[1]), "+f"((d)[2]), "+f"((d)[3]) \
                 : "r"(a0), "r"(a1), "r"(a2), "r"(a3), "r"(b0), "r"(b1))

__device__ __forceinline__ void cp16(uint32_t saddr, const void* gaddr) {
    asm volatile("cp.async.cg.shared.global [%0], [%1], 16;" :: "r"(saddr), "l"(gaddr));
}
__device__ __forceinline__ void cp16z(uint32_t saddr, const void* gaddr, int sz) {
    asm volatile("cp.async.cg.shared.global [%0], [%1], 16, %2;" :: "r"(saddr), "l"(gaddr), "r"(sz));
}
#define CP_COMMIT() asm volatile("cp.async.commit_group;" ::: "memory")
#define CP_WAIT1()  asm volatile("cp.async.wait_group 1;" ::: "memory")

// ---------------------------------------------------------------------------
// fp16 tensor-core NT GEMM: BK=64, 3-stage cp.async; tail tile = LAST y-block
// (with gridDim.y==1 the whole launch is one 32-row tail tile).
// ---------------------------------------------------------------------------
#define HPITCH  144
#define HSTAGE  (128*HPITCH*2)
#define GH_SMEM (3*HSTAGE)

template<typename OutT, bool GELU, bool RES>
__global__ __launch_bounds__(256, 2)
void gemm_h(const __half* __restrict__ A, const __half* __restrict__ W,
            const float* __restrict__ bias, const float* __restrict__ Rs,
            OutT* __restrict__ Cp, int M, int N, int K) {
    extern __shared__ uint8_t smem[];
    const uint32_t sb = smem_u32(smem);
    const int tid = threadIdx.x, lane = tid & 31, warp = tid >> 5;
    const int wm = warp >> 2, wn = warp & 3;
    const int by = blockIdx.y;
    const bool tail = (by == gridDim.y - 1);
    const int m0 = tail ? ((M >> 7) << 7) : (by << 7);
    const int n0 = blockIdx.x * 128;

    float acc[4][4][4];
    #pragma unroll
    for (int i=0;i<4;i++)
      #pragma unroll
      for (int j=0;j<4;j++)
        #pragma unroll
        for (int f=0;f<4;f++) acc[i][j][f]=0.f;

    const int T = K >> 6;

    const int row0 = tid >> 3, ch = tid & 7;
    int    szA[4];
    size_t offA[4];
    #pragma unroll
    for (int it = 0; it < 4; it++) {
        int r = m0 + row0 + it*32;
        szA[it]  = (r < M) ? 16 : 0;
        offA[it] = szA[it] ? ((size_t)r * K + ch*8) : 0;
    }
    const __half* Bbase = W + (size_t)(n0 + row0) * K + ch*8;
    const uint32_t sbase = sb + (uint32_t)row0 * HPITCH + ch*16;

    auto issue_stage = [&](int t, int s) {
        if (t < T) {
            uint32_t so = sbase + (uint32_t)s * HSTAGE;
            int ko = t * 64;
            #pragma unroll
            for (int it = 0; it < 4; it++)
                cp16z(so + it*(32*HPITCH), A + offA[it] + (szA[it] ? ko : 0), szA[it]);
            #pragma unroll
            for (int it = 0; it < 4; it++)
                cp16(so + 128*HPITCH + it*(32*HPITCH), Bbase + (size_t)it*32*K + ko);
        }
        CP_COMMIT();
    };

    const uint32_t aoff = (uint32_t)(wm*64 + (lane & 15)) * HPITCH + (lane >> 4) * 16;
    const uint32_t boff = 128*HPITCH
                        + (uint32_t)(wn*32 + (lane & 7) + ((lane >> 4) << 3)) * HPITCH
                        + ((lane >> 3) & 1) * 16;

    issue_stage(0, 0);
    issue_stage(1, 1);

    int cur = 0, nxt = 2;
    for (int t = 0; t < T; t++) {
        CP_WAIT1();
        __syncthreads();
        issue_stage(t + 2, nxt);
        nxt = (nxt == 2) ? 0 : nxt + 1;
        const uint32_t stb = sb + (uint32_t)cur * HSTAGE;
        cur = (cur == 2) ? 0 : cur + 1;

        if (tail) {
            if (wm == 0) {
                #pragma unroll
                for (int kc = 0; kc < 4; kc++) {
                    uint32_t af[2][4];
                    #pragma unroll
                    for (int mt = 0; mt < 2; mt++) {
                        uint32_t addr = stb + aoff + mt*16*HPITCH + kc*32;
                        LDSM_X4(af[mt][0], af[mt][1], af[mt][2], af[mt][3], addr);
                    }
                    uint32_t bf[2][4];
                    #pragma unroll
                    for (int pr = 0; pr < 2; pr++) {
                        uint32_t addr = stb + boff + pr*16*HPITCH + kc*32;
                        LDSM_X4(bf[pr][0], bf[pr][1], bf[pr][2], bf[pr][3], addr);
                    }
                    #pragma unroll
                    for (int mt = 0; mt < 2; mt++)
                        #pragma unroll
                        for (int nt = 0; nt < 4; nt++)
                            HMMA16816(acc[mt][nt],
                                      af[mt][0], af[mt][1], af[mt][2], af[mt][3],
                                      bf[nt>>1][(nt&1)*2], bf[nt>>1][(nt&1)*2+1]);
                }
            }
        } else {
            #pragma unroll
            for (int kc = 0; kc < 4; kc++) {
                uint32_t af[4][4];
                #pragma unroll
                for (int mt = 0; mt < 4; mt++) {
                    uint32_t addr = stb + aoff + mt*16*HPITCH + kc*32;
                    LDSM_X4(af[mt][0], af[mt][1], af[mt][2], af[mt][3], addr);
                }
                uint32_t bf[2][4];
                #pragma unroll
                for (int pr = 0; pr < 2; pr++) {
                    uint32_t addr = stb + boff + pr*16*HPITCH + kc*32;
                    LDSM_X4(bf[pr][0], bf[pr][1], bf[pr][2], bf[pr][3], addr);
                }
                #pragma unroll
                for (int mt = 0; mt < 4; mt++) {
                    #pragma unroll
                    for (int nt = 0; nt < 4; nt++) {
                        HMMA16816(acc[mt][nt],
                                  af[mt][0], af[mt][1], af[mt][2], af[mt][3],
                                  bf[nt>>1][(nt&1)*2], bf[nt>>1][(nt&1)*2+1]);
                    }
                }
            }
        }
    }

    const int lr = lane >> 2, lc = lane & 3;
    if (tail && wm != 0) return;
    const int mtN = tail ? 2 : 4;
    for (int mt = 0; mt < mtN; mt++) {
        int r0 = m0 + wm*64 + mt*16 + lr;
        #pragma unroll
        for (int nt = 0; nt < 4; nt++) {
            int cc = n0 + wn*32 + nt*8 + lc*2;
            float v0 = acc[mt][nt][0], v1 = acc[mt][nt][1];
            float v2 = acc[mt][nt][2], v3 = acc[mt][nt][3];
            if (bias) {
                float bb0 = bias[cc], bb1 = bias[cc+1];
                v0 += bb0; v1 += bb1; v2 += bb0; v3 += bb1;
            }
            if (RES) {
                if (r0 < M) {
                    float2 rr = *(const float2*)&Rs[(size_t)r0*N + cc];
                    v0 += rr.x; v1 += rr.y;
                }
                if (r0 + 8 < M) {
                    float2 rr = *(const float2*)&Rs[(size_t)(r0+8)*N + cc];
                    v2 += rr.x; v3 += rr.y;
                }
            }
            if (GELU) { v0 = gelu_f(v0); v1 = gelu_f(v1); v2 = gelu_f(v2); v3 = gelu_f(v3); }
            if (sizeof(OutT) == 4) {
                if (r0 < M)     *(float2*)&(((float*)Cp)[(size_t)r0*N + cc])     = make_float2(v0, v1);
                if (r0 + 8 < M) *(float2*)&(((float*)Cp)[(size_t)(r0+8)*N + cc]) = make_float2(v2, v3);
            } else {
                if (r0 < M) {
                    __half2 h = __floats2half2_rn(v0, v1);
                    *(__half2*)&(((__half*)Cp)[(size_t)r0*N + cc]) = h;
                }
                if (r0 + 8 < M) {
                    __half2 h = __floats2half2_rn(v2, v3);
                    *(__half2*)&(((__half*)Cp)[(size_t)(r0+8)*N + cc]) = h;
                }
            }
        }
    }
}

// ---------------------------------------------------------------------------
// SIMT NT SGEMM for the tiny head GEMMs (M=32), fp32
// ---------------------------------------------------------------------------
__global__ void gemm_nt(const float* __restrict__ A, const float* __restrict__ W,
                        const float* __restrict__ bias, float* __restrict__ C,
                        int M, int N, int K) {
    __shared__ float As[16][64];
    __shared__ float Bs[16][64];
    int tid = threadIdx.x;
    int tx = tid & 15, ty = tid >> 4;
    int m0 = blockIdx.y * 64, n0 = blockIdx.x * 64;
    int lr = tid >> 2;
    int lc = (tid & 3) << 2;
    float acc[4][4] = {};
    const float* Aptr = A + (long)(m0 + lr) * K + lc;
    const float* Wptr = W + (long)(n0 + lr) * K + lc;
    bool am = (m0 + lr) < M;
    bool wn = (n0 + lr) < N;
    for (int k0 = 0; k0 < K; k0 += 16) {
        float4 av = am ? *(const float4*)(Aptr + k0) : make_float4(0.f,0.f,0.f,0.f);
        float4 wv = wn ? *(const float4*)(Wptr + k0) : make_float4(0.f,0.f,0.f,0.f);
        As[lc+0][lr]=av.x; As[lc+1][lr]=av.y; As[lc+2][lr]=av.z; As[lc+3][lr]=av.w;
        Bs[lc+0][lr]=wv.x; Bs[lc+1][lr]=wv.y; Bs[lc+2][lr]=wv.z; Bs[lc+3][lr]=wv.w;
        __syncthreads();
        #pragma unroll
        for (int kk = 0; kk < 16; kk++) {
            float4 a = *(const float4*)(&As[kk][ty << 2]);
            float4 b = *(const float4*)(&Bs[kk][tx << 2]);
            acc[0][0] += a.x*b.x; acc[0][1] += a.x*b.y; acc[0][2] += a.x*b.z; acc[0][3] += a.x*b.w;
            acc[1][0] += a.y*b.x; acc[1][1] += a.y*b.y; acc[1][2] += a.y*b.z; acc[1][3] += a.y*b.w;
            acc[2][0] += a.z*b.x; acc[2][1] += a.z*b.y; acc[2][2] += a.z*b.z; acc[2][3] += a.z*b.w;
            acc[3][0] += a.w*b.x; acc[3][1] += a.w*b.y; acc[3][2] += a.w*b.z; acc[3][3] += a.w*b.w;
        }
        __syncthreads();
    }
    #pragma unroll
    for (int i = 0; i < 4; i++) {
        int m = m0 + (ty << 2) + i;
        if (m >= M) continue;
        #pragma unroll
        for (int j = 0; j < 4; j++) {
            int n = n0 + (tx << 2) + j;
            if (n >= N) continue;
            float v = acc[i][j];
            if (bias) v += bias[n];
            C[(long)m * N + n] = v;
        }
    }
}

// ---------------------------------------------------------------------------
// HMMA flash-style attention (unchanged from R12 — verified).
// ---------------------------------------------------------------------------
#define SEQP    208
#define KPITCH  72
#define VPITCH  216
#define PPITCH  216
#define ATTN_SMEM ((SEQP*KPITCH + 64*VPITCH + 8*16*PPITCH) * 2)   // 112896

__global__ __launch_bounds__(256)
void attn_kernel(const __half* __restrict__ qkv, __half* __restrict__ out) {
    int b = blockIdx.x / NH, h = blockIdx.x % NH;
    int tid = threadIdx.x, lane = tid & 31, warp = tid >> 5;
    extern __shared__ __half sh[];
    __half* Ks = sh;
    __half* Vt = Ks + SEQP*KPITCH;
    __half* Pw = Vt + 64*VPITCH + warp*16*PPITCH;

    const __half* base = qkv + (size_t)b * NTOK * (3*DD) + h * DH;

    for (int idx = tid; idx < NTOK*8; idx += 256) {
        int j = idx >> 3, c = idx & 7;
        *(uint4*)&Ks[j*KPITCH + c*8] = *(const uint4*)&base[(size_t)j*(3*DD) + DD + c*8];
    }
    for (int idx = tid; idx < (SEQP-NTOK)*KPITCH; idx += 256) {
        Ks[(NTOK + idx/KPITCH)*KPITCH + (idx % KPITCH)] = __half(0.0f);
    }
    for (int idx = tid; idx < NTOK*64; idx += 256) {
        int j = idx >> 6, d = idx & 63;
        Vt[d*VPITCH + j] = base[(size_t)j*(3*DD) + 2*DD + d];
    }
    for (int idx = tid; idx < 64*(VPITCH-NTOK); idx += 256) {
        int d = idx / (VPITCH-NTOK), c = NTOK + idx % (VPITCH-NTOK);
        Vt[d*VPITCH + c] = __half(0.0f);
    }
    __syncthreads();

    const uint32_t KsB = smem_u32(Ks);
    const uint32_t VtB = smem_u32(Vt);
    const uint32_t PwB = smem_u32(Pw);
    const int lr = lane >> 2, lc = lane & 3;
    const uint32_t browoff = ((lane & 7) + ((lane >> 4) << 3));
    const uint32_t bcol = ((lane >> 3) & 1) * 16;
    const uint32_t aoff = PwB + (uint32_t)(lane & 15) * (PPITCH*2) + (lane >> 4) * 16;

    for (int s = warp; s < 13; s += 8) {
        const int m0 = s * 16;
        #pragma unroll
        for (int t = 0; t < 4; t++) {
            int idx = lane + t*32;
            int r = idx >> 3, c = idx & 7;
            int q = m0 + r;
            uint4 v = make_uint4(0u,0u,0u,0u);
            if (q < NTOK) v = *(const uint4*)&base[(size_t)q*(3*DD) + c*8];
            *(uint4*)&Pw[r*PPITCH + c*8] = v;
        }
        __syncwarp();
        uint32_t af[4][4];
        #pragma unroll
        for (int kc = 0; kc < 4; kc++)
            LDSM_X4(af[kc][0], af[kc][1], af[kc][2], af[kc][3], aoff + kc*32);

        float acc[26][4];
        #pragma unroll
        for (int nt = 0; nt < 26; nt++) {
            acc[nt][0]=0.f; acc[nt][1]=0.f; acc[nt][2]=0.f; acc[nt][3]=0.f;
        }
        #pragma unroll
        for (int kc = 0; kc < 4; kc++) {
            #pragma unroll
            for (int g = 0; g < 13; g++) {
                uint32_t b0,b1,b2,b3;
                LDSM_X4(b0,b1,b2,b3,
                        KsB + (g*16 + browoff)*(KPITCH*2) + bcol + kc*32);
                HMMA16816(acc[2*g  ], af[kc][0],af[kc][1],af[kc][2],af[kc][3], b0, b1);
                HMMA16816(acc[2*g+1], af[kc][0],af[kc][1],af[kc][2],af[kc][3], b2, b3);
            }
        }

        float mx1 = -1e30f, mx2 = -1e30f;
        #pragma unroll
        for (int nt = 0; nt < 26; nt++) {
            #pragma unroll
            for (int e = 0; e < 2; e++) {
                int col = nt*8 + lc*2 + e;
                bool ok = col < NTOK;
                float s1 = ok ? acc[nt][e]   * 0.125f : -1e30f;
                float s2 = ok ? acc[nt][2+e] * 0.125f : -1e30f;
                acc[nt][e] = s1; acc[nt][2+e] = s2;
                mx1 = fmaxf(mx1, s1); mx2 = fmaxf(mx2, s2);
            }
        }
        #pragma unroll
        for (int o = 1; o <= 2; o <<= 1) {
            mx1 = fmaxf(mx1, __shfl_xor_sync(0xffffffffu, mx1, o));
            mx2 = fmaxf(mx2, __shfl_xor_sync(0xffffffffu, mx2, o));
        }
        float sum1 = 0.f, sum2 = 0.f;
        #pragma unroll
        for (int nt = 0; nt < 26; nt++) {
            #pragma unroll
            for (int e = 0; e < 2; e++) {
                float p1 = expf(acc[nt][e]   - mx1);
                float p2 = expf(acc[nt][2+e] - mx2);
                acc[nt][e] = p1; acc[nt][2+e] = p2;
                sum1 += p1; sum2 += p2;
            }
        }
        #pragma unroll
        for (int o = 1; o <= 2; o <<= 1) {
            sum1 += __shfl_xor_sync(0xffffffffu, sum1, o);
            sum2 += __shfl_xor_sync(0xffffffffu, sum2, o);
        }
        #pragma unroll
        for (int nt = 0; nt < 26; nt++) {
            int col = nt*8 + lc*2;
            __half2 p1 = __floats2half2_rn(acc[nt][0], acc[nt][1]);
            __half2 p2 = __floats2half2_rn(acc[nt][2], acc[nt][3]);
            *(__half2*)&Pw[ lr   *PPITCH + col] = p1;
            *(__half2*)&Pw[(lr+8)*PPITCH + col] = p2;
        }
        __syncwarp();

        float oacc[8][4];
        #pragma unroll
        for (int nt = 0; nt < 8; nt++) {
            oacc[nt][0]=0.f; oacc[nt][1]=0.f; oacc[nt][2]=0.f; oacc[nt][3]=0.f;
        }
        for (int kt = 0; kt < 13; kt++) {
            uint32_t pa0,pa1,pa2,pa3;
            LDSM_X4(pa0,pa1,pa2,pa3, aoff + kt*32);
            #pragma unroll
            for (int g = 0; g < 4; g++) {
                uint32_t b0,b1,b2,b3;
                LDSM_X4(b0,b1,b2,b3,
                        VtB + (g*16 + browoff)*(VPITCH*2) + bcol + kt*32);
                HMMA16816(oacc[2*g  ], pa0,pa1,pa2,pa3, b0, b1);
                HMMA16816(oacc[2*g+1], pa0,pa1,pa2,pa3, b2, b3);
            }
        }

        float inv1 = 1.0f / sum1, inv2 = 1.0f / sum2;
        int q1 = m0 + lr, q2 = m0 + lr + 8;
        #pragma unroll
        for (int nt = 0; nt < 8; nt++) {
            int col = nt*8 + lc*2;
            if (q1 < NTOK) {
                __half2 hv = __floats2half2_rn(oacc[nt][0]*inv1, oacc[nt][1]*inv1);
                *(__half2*)&out[((size_t)b*NTOK + q1)*DD + h*DH + col] = hv;
            }
            if (q2 < NTOK) {
                __half2 hv = __floats2half2_rn(oacc[nt][2]*inv2, oacc[nt][3]*inv2);
                *(__half2*)&out[((size_t)b*NTOK + q2)*DD + h*DH + col] = hv;
            }
        }
        __syncwarp();
    }
}

// ---------------------------------------------------------------------------
// host orchestration
// ---------------------------------------------------------------------------
extern "C" void kernel_launch(void* const* d_in, const int* in_sizes, int n_in,
                              void* d_out, int out_size) {
    const float* x_in    = (const float*)d_in[0];
    const float* conv_w  = (const float*)d_in[1];
    const float* cls_tok = (const float*)d_in[2];
    const float* pos     = (const float*)d_in[3];
    const float* lnprew  = (const float*)d_in[4];
    const float* lnpreb  = (const float*)d_in[5];
    const float* ln1w    = (const float*)d_in[6];
    const float* ln1b    = (const float*)d_in[7];
    const float* qkvw    = (const float*)d_in[8];
    const float* qkvb    = (const float*)d_in[9];
    const float* pw      = (const float*)d_in[10];
    const float* pb      = (const float*)d_in[11];
    const float* ln2w    = (const float*)d_in[12];
    const float* ln2b    = (const float*)d_in[13];
    const float* fw      = (const float*)d_in[14];
    const float* fb      = (const float*)d_in[15];
    const float* cw      = (const float*)d_in[16];
    const float* cb      = (const float*)d_in[17];
    const float* lnpostw = (const float*)d_in[18];
    const float* lnpostb = (const float*)d_in[19];
    const float* projw   = (const float*)d_in[20];
    const float* headw   = (const float*)d_in[21];
    const float* headb   = (const float*)d_in[22];

    float  *gx, *gpe, *gc, *gcr, *gcx2, *gcx3, *gz;
    __half *gq, *gh, *go, *gm, *gp, *gca;
    __half *wconv, *wqkv, *wproj, *wfc, *wcpr;
    cudaGetSymbolAddress((void**)&gx,   g_x);
    cudaGetSymbolAddress((void**)&gpe,  g_pe);
    cudaGetSymbolAddress((void**)&gc,   g_cls);
    cudaGetSymbolAddress((void**)&gcr,  g_cr);
    cudaGetSymbolAddress((void**)&gcx2, g_cx2);
    cudaGetSymbolAddress((void**)&gcx3, g_cx3);
    cudaGetSymbolAddress((void**)&gz,   g_z);
    cudaGetSymbolAddress((void**)&gq,   g_qkv);
    cudaGetSymbolAddress((void**)&gh,   g_h);
    cudaGetSymbolAddress((void**)&go,   g_o);
    cudaGetSymbolAddress((void**)&gm,   g_mlp);
    cudaGetSymbolAddress((void**)&gp,   g_pat);
    cudaGetSymbolAddress((void**)&gca,  g_ca);
    cudaGetSymbolAddress((void**)&wconv, g_wconv);
    cudaGetSymbolAddress((void**)&wqkv,  g_wqkv);
    cudaGetSymbolAddress((void**)&wproj, g_wproj);
    cudaGetSymbolAddress((void**)&wfc,   g_wfc);
    cudaGetSymbolAddress((void**)&wcpr,  g_wcpr);

    cudaFuncSetAttribute(attn_kernel, cudaFuncAttributeMaxDynamicSharedMemorySize, ATTN_SMEM);
    cudaFuncSetAttribute(gemm_h<float ,false,false>, cudaFuncAttributeMaxDynamicSharedMemorySize, GH_SMEM);
    cudaFuncSetAttribute(gemm_h<float ,false,true >, cudaFuncAttributeMaxDynamicSharedMemorySize, GH_SMEM);
    cudaFuncSetAttribute(gemm_h<__half,true ,false>, cudaFuncAttributeMaxDynamicSharedMemorySize, GH_SMEM);
    cudaFuncSetAttribute(gemm_h<__half,false,false>, cudaFuncAttributeMaxDynamicSharedMemorySize, GH_SMEM);

    // ---- weight conversion (single launch) ----
    f2h_all_kernel<<<(F2H_C4 + 255)/256, 256>>>(conv_w, wconv, qkvw, wqkv,
                                                pw, wproj, fw, wfc, cw, wcpr);

    const int GY  = MROWS/128 + 1;   // 50 (last block = 32-row tail)
    const int GYP = PROWS/128 + 1;   // 50 (last block = empty tail)

    // ---- patch embed ----
    im2col_kernel<<<(PROWS*DD + 255)/256, 256>>>(x_in);
    gemm_h<float,false,false><<<dim3(DD/128, GYP), 256, GH_SMEM>>>(
        gp, wconv, nullptr, nullptr, gpe, PROWS, DD, DD);
    assemble_ln_kernel<<<MROWS, 256>>>(gpe, cls_tok, pos, lnprew, lnpreb, gx);

    // ---- layers 0..10: full ----
    for (int l = 0; l < DEPTH - 1; l++) {
        ln_warp<__half><<<MROWS/8, 256>>>(gx, gh, ln1w + l*DD, ln1b + l*DD, DD, DD);
        gemm_h<__half,false,false><<<dim3((3*DD)/128, GY), 256, GH_SMEM>>>(
            gh, wqkv + (size_t)l*3*DD*DD, qkvb + (long)l*3*DD, nullptr, gq, MROWS, 3*DD, DD);
        attn_kernel<<<BB*NH, 256, ATTN_SMEM>>>(gq, go);
        gemm_h<float,false,true><<<dim3(DD/128, GY), 256, GH_SMEM>>>(
            go, wproj + (size_t)l*DD*DD, pb + (long)l*DD, gx, gx, MROWS, DD, DD);
        ln_warp<__half><<<MROWS/8, 256>>>(gx, gh, ln2w + l*DD, ln2b + l*DD, DD, DD);
        gemm_h<__half,true,false><<<dim3(MLPD/128, GY), 256, GH_SMEM>>>(
            gh, wfc + (size_t)l*MLPD*DD, fb + (long)l*MLPD, nullptr, gm, MROWS, MLPD, DD);
        gemm_h<float,false,true><<<dim3(DD/128, GY), 256, GH_SMEM>>>(
            gm, wcpr + (size_t)l*DD*MLPD, cb + (long)l*DD, gx, gx, MROWS, DD, MLPD);
    }

    // ---- layer 11 (last): full ln1/QKV/attn, then cls-only (32 rows) ----
    {
        const int l = DEPTH - 1;
        ln_warp<__half><<<MROWS/8, 256>>>(gx, gh, ln1w + l*DD, ln1b + l*DD, DD, DD);
        gemm_h<__half,false,false><<<dim3((3*DD)/128, GY), 256, GH_SMEM>>>(
            gh, wqkv + (size_t)l*3*DD*DD, qkvb + (long)l*3*DD, nullptr, gq, MROWS, 3*DD, DD);
        attn_kernel<<<BB*NH, 256, ATTN_SMEM>>>(gq, go);
        // gather cls rows (attn-out fp16, residual fp32)
        gather_cls_kernel<<<(BB*DD + 255)/256, 256>>>(go, gx, gca, gcr);
        // attn-proj on 32 rows: gcx2 = gca @ Wp^T + pb + gcr
        gemm_h<float,false,true><<<dim3(DD/128, 1), 256, GH_SMEM>>>(
            gca, wproj + (size_t)l*DD*DD, pb + (long)l*DD, gcr, gcx2, BB, DD, DD);
        // ln2 on 32 rows -> gca (fp16)
        ln_warp<__half><<<BB/8, 256>>>(gcx2, gca, ln2w + l*DD, ln2b + l*DD, DD, DD);
        // FC + GELU on 32 rows -> gm (compact 32x3072 fp16)
        gemm_h<__half,true,false><<<dim3(MLPD/128, 1), 256, GH_SMEM>>>(
            gca, wfc + (size_t)l*MLPD*DD, fb + (long)l*MLPD, nullptr, gm, BB, MLPD, DD);
        // c-proj on 32 rows: gcx3 = gm @ Wc^T + cb + gcx2
        gemm_h<float,false,true><<<dim3(DD/128, 1), 256, GH_SMEM>>>(
            gm, wcpr + (size_t)l*DD*MLPD, cb + (long)l*DD, gcx2, gcx3, BB, DD, MLPD);
    }

    // ---- head: ln_post on 32 compact rows, proj, classifier ----
    ln_warp<float><<<BB/8, 256>>>(gcx3, gc, lnpostw, lnpostb, DD, DD);
    gemm_nt<<<dim3(PROJD/64, 1), 256>>>(gc, projw, nullptr, gz, BB, PROJD, DD);
    gemm_nt<<<dim3((NCLS+63)/64, 1), 256>>>(gz, headw, headb, (float*)d_out, BB, NCLS, PROJD);
}

// round 16
// speedup vs baseline: 10.8246x; 1.0298x over previous
#include <cuda_runtime.h>
#include <cuda_fp16.h>
#include <math.h>
#include <stdint.h>

// ---------------------------------------------------------------------------
// CLIP ViT-B/16 forward. Round 15: single-round 13-warp attention (one warp
// per query strip) + last-layer attention computes only the cls strip.
// GEMM path and everything else = verified R14.
// ---------------------------------------------------------------------------

#define BB      32
#define NTOK    197
#define NPAT    196
#define DD      768
#define DEPTH   12
#define NH      12
#define DH      64
#define MLPD    3072
#define PROJD   512
#define NCLS    1000
#define MROWS   (BB*NTOK)          // 6304
#define PROWS   (BB*NPAT)          // 6272

// fp32 buffers
__device__ __align__(128) float  g_x   [MROWS*DD];
__device__ __align__(128) float  g_pe  [PROWS*DD];
__device__ __align__(128) float  g_cls [BB*DD];
__device__ __align__(128) float  g_cr  [BB*DD];
__device__ __align__(128) float  g_cx2 [BB*DD];
__device__ __align__(128) float  g_cx3 [BB*DD];
__device__ __align__(128) float  g_z   [BB*PROJD];
// fp16 buffers
__device__ __align__(128) __half g_qkv [MROWS*3*DD];
__device__ __align__(128) __half g_h   [MROWS*DD];
__device__ __align__(128) __half g_o   [MROWS*DD];
__device__ __align__(128) __half g_mlp [MROWS*MLPD];
__device__ __align__(128) __half g_pat [PROWS*DD];
__device__ __align__(128) __half g_ca  [BB*DD];
// fp16 weights
__device__ __align__(128) __half g_wconv [DD*DD];
__device__ __align__(128) __half g_wqkv  [DEPTH*3*DD*DD];
__device__ __align__(128) __half g_wproj [DEPTH*DD*DD];
__device__ __align__(128) __half g_wfc   [DEPTH*MLPD*DD];
__device__ __align__(128) __half g_wcpr  [DEPTH*DD*MLPD];

// ---------------------------------------------------------------------------
// merged fp32 -> fp16 weight conversion
// ---------------------------------------------------------------------------
#define F2H_C0 (DD*DD/8)
#define F2H_C1 (F2H_C0 + DEPTH*3*DD*DD/8)
#define F2H_C2 (F2H_C1 + DEPTH*DD*DD/8)
#define F2H_C3 (F2H_C2 + DEPTH*MLPD*DD/8)
#define F2H_C4 (F2H_C3 + DEPTH*DD*MLPD/8)

__global__ void f2h_all_kernel(const float* __restrict__ s0, __half* d0,
                               const float* __restrict__ s1, __half* d1,
                               const float* __restrict__ s2, __half* d2,
                               const float* __restrict__ s3, __half* d3,
                               const float* __restrict__ s4, __half* d4) {
    int i = blockIdx.x * 256 + threadIdx.x;
    if (i >= F2H_C4) return;
    const float* src; __half* dst; int off;
    if      (i < F2H_C0) { src = s0; dst = d0; off = i; }
    else if (i < F2H_C1) { src = s1; dst = d1; off = i - F2H_C0; }
    else if (i < F2H_C2) { src = s2; dst = d2; off = i - F2H_C1; }
    else if (i < F2H_C3) { src = s3; dst = d3; off = i - F2H_C2; }
    else                 { src = s4; dst = d4; off = i - F2H_C3; }
    const float4* p = (const float4*)src + (size_t)off*2;
    float4 a = p[0], b = p[1];
    __half2 h0 = __floats2half2_rn(a.x, a.y);
    __half2 h1 = __floats2half2_rn(a.z, a.w);
    __half2 h2 = __floats2half2_rn(b.x, b.y);
    __half2 h3 = __floats2half2_rn(b.z, b.w);
    uint4 v;
    v.x = *(uint32_t*)&h0; v.y = *(uint32_t*)&h1;
    v.z = *(uint32_t*)&h2; v.w = *(uint32_t*)&h3;
    ((uint4*)dst)[off] = v;
}

// ---------------------------------------------------------------------------
// im2col
// ---------------------------------------------------------------------------
__global__ void im2col_kernel(const float* __restrict__ x) {
    int idx = blockIdx.x * 256 + threadIdx.x;
    if (idx >= PROWS * DD) return;
    int k = idx % DD;
    int m = idx / DD;
    int b = m / NPAT, p = m % NPAT;
    int ph = p / 14, pw = p % 14;
    int c = k >> 8, r = (k >> 4) & 15, col = k & 15;
    g_pat[idx] = __float2half_rn(x[(((long)(b*3 + c)*224 + ph*16 + r)*224) + pw*16 + col]);
}

// ---------------------------------------------------------------------------
// fused assemble + ln_pre
// ---------------------------------------------------------------------------
__global__ void assemble_ln_kernel(const float* __restrict__ pe,
                                   const float* __restrict__ cls_tok,
                                   const float* __restrict__ pos,
                                   const float* __restrict__ gam,
                                   const float* __restrict__ bet,
                                   float* __restrict__ out) {
    __shared__ float red[16];
    int row = blockIdx.x, tid = threadIdx.x;
    int b = row / NTOK, n = row % NTOK;
    float v0, v1, v2;
    if (n == 0) {
        v0 = cls_tok[tid      ] + pos[tid      ];
        v1 = cls_tok[tid + 256] + pos[tid + 256];
        v2 = cls_tok[tid + 512] + pos[tid + 512];
    } else {
        const float* per = pe + ((size_t)b*NPAT + (n-1))*DD;
        const float* por = pos + (size_t)n*DD;
        v0 = per[tid      ] + por[tid      ];
        v1 = per[tid + 256] + por[tid + 256];
        v2 = per[tid + 512] + por[tid + 512];
    }
    float s = v0 + v1 + v2;
    #pragma unroll
    for (int o = 16; o; o >>= 1) s += __shfl_xor_sync(0xffffffffu, s, o);
    if ((tid & 31) == 0) red[tid >> 5] = s;
    __syncthreads();
    float tot = red[0]+red[1]+red[2]+red[3]+red[4]+red[5]+red[6]+red[7];
    float mean = tot * (1.0f / 768.0f);
    float d0 = v0 - mean, d1 = v1 - mean, d2 = v2 - mean;
    float q = d0*d0 + d1*d1 + d2*d2;
    #pragma unroll
    for (int o = 16; o; o >>= 1) q += __shfl_xor_sync(0xffffffffu, q, o);
    if ((tid & 31) == 0) red[8 + (tid >> 5)] = q;
    __syncthreads();
    float var = (red[8]+red[9]+red[10]+red[11]+red[12]+red[13]+red[14]+red[15]) * (1.0f/768.0f);
    float rs = rsqrtf(var + 1e-5f);
    float* orow = out + (size_t)row * DD;
    orow[tid      ] = d0 * rs * gam[tid      ] + bet[tid      ];
    orow[tid + 256] = d1 * rs * gam[tid + 256] + bet[tid + 256];
    orow[tid + 512] = d2 * rs * gam[tid + 512] + bet[tid + 512];
}

// ---------------------------------------------------------------------------
// LayerNorm over 768: warp-per-row, no barriers. 256 threads = 8 rows/block.
// ---------------------------------------------------------------------------
template<typename OutT>
__global__ void ln_warp(const float* __restrict__ in, OutT* __restrict__ out,
                        const float* __restrict__ gam, const float* __restrict__ bet,
                        long in_stride, long out_stride) {
    int warp = threadIdx.x >> 5, lane = threadIdx.x & 31;
    int row = blockIdx.x * 8 + warp;
    const float4* xr = (const float4*)(in + (size_t)row * in_stride);
    float4 v[6];
    float s = 0.f;
    #pragma unroll
    for (int j = 0; j < 6; j++) {
        v[j] = xr[lane + 32*j];
        s += (v[j].x + v[j].y) + (v[j].z + v[j].w);
    }
    #pragma unroll
    for (int o = 16; o; o >>= 1) s += __shfl_xor_sync(0xffffffffu, s, o);
    float mean = s * (1.0f/768.0f);
    float q = 0.f;
    #pragma unroll
    for (int j = 0; j < 6; j++) {
        v[j].x -= mean; v[j].y -= mean; v[j].z -= mean; v[j].w -= mean;
        q += (v[j].x*v[j].x + v[j].y*v[j].y) + (v[j].z*v[j].z + v[j].w*v[j].w);
    }
    #pragma unroll
    for (int o = 16; o; o >>= 1) q += __shfl_xor_sync(0xffffffffu, q, o);
    float rs = rsqrtf(q * (1.0f/768.0f) + 1e-5f);
    const float4* g4 = (const float4*)gam;
    const float4* b4 = (const float4*)bet;
    if (sizeof(OutT) == 2) {
        __half* orow = (__half*)out + (size_t)row * out_stride;
        #pragma unroll
        for (int j = 0; j < 6; j++) {
            float4 g = g4[lane + 32*j], bb = b4[lane + 32*j];
            __half2 h0 = __floats2half2_rn(v[j].x*rs*g.x + bb.x, v[j].y*rs*g.y + bb.y);
            __half2 h1 = __floats2half2_rn(v[j].z*rs*g.z + bb.z, v[j].w*rs*g.w + bb.w);
            uint2 u; u.x = *(uint32_t*)&h0; u.y = *(uint32_t*)&h1;
            *(uint2*)&orow[(lane + 32*j)*4] = u;
        }
    } else {
        float* orow = (float*)out + (size_t)row * out_stride;
        #pragma unroll
        for (int j = 0; j < 6; j++) {
            float4 g = g4[lane + 32*j], bb = b4[lane + 32*j];
            float4 o4;
            o4.x = v[j].x*rs*g.x + bb.x; o4.y = v[j].y*rs*g.y + bb.y;
            o4.z = v[j].z*rs*g.z + bb.z; o4.w = v[j].w*rs*g.w + bb.w;
            ((float4*)orow)[lane + 32*j] = o4;
        }
    }
}

__device__ __forceinline__ float gelu_f(float v) {
    return 0.5f * v * (1.0f + erff(v * 0.70710678118654752f));
}

// ---------------------------------------------------------------------------
// gather cls rows
// ---------------------------------------------------------------------------
__global__ void gather_cls_kernel(const __half* __restrict__ go,
                                  const float* __restrict__ gx,
                                  __half* __restrict__ a16,
                                  float* __restrict__ r32) {
    int idx = blockIdx.x * 256 + threadIdx.x;
    if (idx >= BB*DD) return;
    int b = idx / DD, d = idx % DD;
    size_t src = (size_t)b * NTOK * DD + d;
    a16[idx] = go[src];
    r32[idx] = gx[src];
}

// ---------------------------------------------------------------------------
// common PTX helpers
// ---------------------------------------------------------------------------
__device__ __forceinline__ uint32_t smem_u32(const void* p) {
    uint32_t a;
    asm("{ .reg .u64 t; cvta.to.shared.u64 t, %1; cvt.u32.u64 %0, t; }" : "=r"(a) : "l"(p));
    return a;
}

#define LDSM_X4(r0,r1,r2,r3,addr) \
    asm volatile("ldmatrix.sync.aligned.m8n8.x4.shared.b16 {%0,%1,%2,%3}, [%4];" \
                 : "=r"(r0), "=r"(r1), "=r"(r2), "=r"(r3) : "r"(addr))

#define HMMA16816(d, a0,a1,a2,a3, b0,b1) \
    asm volatile("mma.sync.aligned.m16n8k16.row.col.f32.f16.f16.f32 " \
                 "{%0,%1,%2,%3}, {%4,%5,%6,%7}, {%8,%9}, {%0,%1,%2,%3};" \
                 : "+f"((d)[0]), "+f"((d)[1]), "+f"((d)[2]), "+f"((d)[3]) \
                 : "r"(a0), "r"(a1), "r"(a2), "r"(a3), "r"(b0), "r"(b1))

__device__ __forceinline__ void cp16(uint32_t saddr, const void* gaddr) {
    asm volatile("cp.async.cg.shared.global [%0], [%1], 16;" :: "r"(saddr), "l"(gaddr));
}
__device__ __forceinline__ void cp16z(uint32_t saddr, const void* gaddr, int sz) {
    asm volatile("cp.async.cg.shared.global [%0], [%1], 16, %2;" :: "r"(saddr), "l"(gaddr), "r"(sz));
}
#define CP_COMMIT() asm volatile("cp.async.commit_group;" ::: "memory")
#define CP_WAIT1()  asm volatile("cp.async.wait_group 1;" ::: "memory")

// ---------------------------------------------------------------------------
// fp16 tensor-core NT GEMM: BK=64, 3-stage cp.async; tail tile = LAST y-block.
// ---------------------------------------------------------------------------
#define HPITCH  144
#define HSTAGE  (128*HPITCH*2)
#define GH_SMEM (3*HSTAGE)

template<typename OutT, bool GELU, bool RES>
__global__ __launch_bounds__(256, 2)
void gemm_h(const __half* __restrict__ A, const __half* __restrict__ W,
            const float* __restrict__ bias, const float* __restrict__ Rs,
            OutT* __restrict__ Cp, int M, int N, int K) {
    extern __shared__ uint8_t smem[];
    const uint32_t sb = smem_u32(smem);
    const int tid = threadIdx.x, lane = tid & 31, warp = tid >> 5;
    const int wm = warp >> 2, wn = warp & 3;
    const int by = blockIdx.y;
    const bool tail = (by == gridDim.y - 1);
    const int m0 = tail ? ((M >> 7) << 7) : (by << 7);
    const int n0 = blockIdx.x * 128;

    float acc[4][4][4];
    #pragma unroll
    for (int i=0;i<4;i++)
      #pragma unroll
      for (int j=0;j<4;j++)
        #pragma unroll
        for (int f=0;f<4;f++) acc[i][j][f]=0.f;

    const int T = K >> 6;

    const int row0 = tid >> 3, ch = tid & 7;
    int    szA[4];
    size_t offA[4];
    #pragma unroll
    for (int it = 0; it < 4; it++) {
        int r = m0 + row0 + it*32;
        szA[it]  = (r < M) ? 16 : 0;
        offA[it] = szA[it] ? ((size_t)r * K + ch*8) : 0;
    }
    const __half* Bbase = W + (size_t)(n0 + row0) * K + ch*8;
    const uint32_t sbase = sb + (uint32_t)row0 * HPITCH + ch*16;

    auto issue_stage = [&](int t, int s) {
        if (t < T) {
            uint32_t so = sbase + (uint32_t)s * HSTAGE;
            int ko = t * 64;
            #pragma unroll
            for (int it = 0; it < 4; it++)
                cp16z(so + it*(32*HPITCH), A + offA[it] + (szA[it] ? ko : 0), szA[it]);
            #pragma unroll
            for (int it = 0; it < 4; it++)
                cp16(so + 128*HPITCH + it*(32*HPITCH), Bbase + (size_t)it*32*K + ko);
        }
        CP_COMMIT();
    };

    const uint32_t aoff = (uint32_t)(wm*64 + (lane & 15)) * HPITCH + (lane >> 4) * 16;
    const uint32_t boff = 128*HPITCH
                        + (uint32_t)(wn*32 + (lane & 7) + ((lane >> 4) << 3)) * HPITCH
                        + ((lane >> 3) & 1) * 16;

    issue_stage(0, 0);
    issue_stage(1, 1);

    int cur = 0, nxt = 2;
    for (int t = 0; t < T; t++) {
        CP_WAIT1();
        __syncthreads();
        issue_stage(t + 2, nxt);
        nxt = (nxt == 2) ? 0 : nxt + 1;
        const uint32_t stb = sb + (uint32_t)cur * HSTAGE;
        cur = (cur == 2) ? 0 : cur + 1;

        if (tail) {
            if (wm == 0) {
                #pragma unroll
                for (int kc = 0; kc < 4; kc++) {
                    uint32_t af[2][4];
                    #pragma unroll
                    for (int mt = 0; mt < 2; mt++) {
                        uint32_t addr = stb + aoff + mt*16*HPITCH + kc*32;
                        LDSM_X4(af[mt][0], af[mt][1], af[mt][2], af[mt][3], addr);
                    }
                    uint32_t bf[2][4];
                    #pragma unroll
                    for (int pr = 0; pr < 2; pr++) {
                        uint32_t addr = stb + boff + pr*16*HPITCH + kc*32;
                        LDSM_X4(bf[pr][0], bf[pr][1], bf[pr][2], bf[pr][3], addr);
                    }
                    #pragma unroll
                    for (int mt = 0; mt < 2; mt++)
                        #pragma unroll
                        for (int nt = 0; nt < 4; nt++)
                            HMMA16816(acc[mt][nt],
                                      af[mt][0], af[mt][1], af[mt][2], af[mt][3],
                                      bf[nt>>1][(nt&1)*2], bf[nt>>1][(nt&1)*2+1]);
                }
            }
        } else {
            #pragma unroll
            for (int kc = 0; kc < 4; kc++) {
                uint32_t af[4][4];
                #pragma unroll
                for (int mt = 0; mt < 4; mt++) {
                    uint32_t addr = stb + aoff + mt*16*HPITCH + kc*32;
                    LDSM_X4(af[mt][0], af[mt][1], af[mt][2], af[mt][3], addr);
                }
                uint32_t bf[2][4];
                #pragma unroll
                for (int pr = 0; pr < 2; pr++) {
                    uint32_t addr = stb + boff + pr*16*HPITCH + kc*32;
                    LDSM_X4(bf[pr][0], bf[pr][1], bf[pr][2], bf[pr][3], addr);
                }
                #pragma unroll
                for (int mt = 0; mt < 4; mt++) {
                    #pragma unroll
                    for (int nt = 0; nt < 4; nt++) {
                        HMMA16816(acc[mt][nt],
                                  af[mt][0], af[mt][1], af[mt][2], af[mt][3],
                                  bf[nt>>1][(nt&1)*2], bf[nt>>1][(nt&1)*2+1]);
                    }
                }
            }
        }
    }

    const int lr = lane >> 2, lc = lane & 3;
    if (tail && wm != 0) return;
    const int mtN = tail ? 2 : 4;
    for (int mt = 0; mt < mtN; mt++) {
        int r0 = m0 + wm*64 + mt*16 + lr;
        #pragma unroll
        for (int nt = 0; nt < 4; nt++) {
            int cc = n0 + wn*32 + nt*8 + lc*2;
            float v0 = acc[mt][nt][0], v1 = acc[mt][nt][1];
            float v2 = acc[mt][nt][2], v3 = acc[mt][nt][3];
            if (bias) {
                float bb0 = bias[cc], bb1 = bias[cc+1];
                v0 += bb0; v1 += bb1; v2 += bb0; v3 += bb1;
            }
            if (RES) {
                if (r0 < M) {
                    float2 rr = *(const float2*)&Rs[(size_t)r0*N + cc];
                    v0 += rr.x; v1 += rr.y;
                }
                if (r0 + 8 < M) {
                    float2 rr = *(const float2*)&Rs[(size_t)(r0+8)*N + cc];
                    v2 += rr.x; v3 += rr.y;
                }
            }
            if (GELU) { v0 = gelu_f(v0); v1 = gelu_f(v1); v2 = gelu_f(v2); v3 = gelu_f(v3); }
            if (sizeof(OutT) == 4) {
                if (r0 < M)     *(float2*)&(((float*)Cp)[(size_t)r0*N + cc])     = make_float2(v0, v1);
                if (r0 + 8 < M) *(float2*)&(((float*)Cp)[(size_t)(r0+8)*N + cc]) = make_float2(v2, v3);
            } else {
                if (r0 < M) {
                    __half2 h = __floats2half2_rn(v0, v1);
                    *(__half2*)&(((__half*)Cp)[(size_t)r0*N + cc]) = h;
                }
                if (r0 + 8 < M) {
                    __half2 h = __floats2half2_rn(v2, v3);
                    *(__half2*)&(((__half*)Cp)[(size_t)(r0+8)*N + cc]) = h;
                }
            }
        }
    }
}

// ---------------------------------------------------------------------------
// SIMT NT SGEMM for the tiny head GEMMs (M=32), fp32
// ---------------------------------------------------------------------------
__global__ void gemm_nt(const float* __restrict__ A, const float* __restrict__ W,
                        const float* __restrict__ bias, float* __restrict__ C,
                        int M, int N, int K) {
    __shared__ float As[16][64];
    __shared__ float Bs[16][64];
    int tid = threadIdx.x;
    int tx = tid & 15, ty = tid >> 4;
    int m0 = blockIdx.y * 64, n0 = blockIdx.x * 64;
    int lr = tid >> 2;
    int lc = (tid & 3) << 2;
    float acc[4][4] = {};
    const float* Aptr = A + (long)(m0 + lr) * K + lc;
    const float* Wptr = W + (long)(n0 + lr) * K + lc;
    bool am = (m0 + lr) < M;
    bool wn = (n0 + lr) < N;
    for (int k0 = 0; k0 < K; k0 += 16) {
        float4 av = am ? *(const float4*)(Aptr + k0) : make_float4(0.f,0.f,0.f,0.f);
        float4 wv = wn ? *(const float4*)(Wptr + k0) : make_float4(0.f,0.f,0.f,0.f);
        As[lc+0][lr]=av.x; As[lc+1][lr]=av.y; As[lc+2][lr]=av.z; As[lc+3][lr]=av.w;
        Bs[lc+0][lr]=wv.x; Bs[lc+1][lr]=wv.y; Bs[lc+2][lr]=wv.z; Bs[lc+3][lr]=wv.w;
        __syncthreads();
        #pragma unroll
        for (int kk = 0; kk < 16; kk++) {
            float4 a = *(const float4*)(&As[kk][ty << 2]);
            float4 b = *(const float4*)(&Bs[kk][tx << 2]);
            acc[0][0] += a.x*b.x; acc[0][1] += a.x*b.y; acc[0][2] += a.x*b.z; acc[0][3] += a.x*b.w;
            acc[1][0] += a.y*b.x; acc[1][1] += a.y*b.y; acc[1][2] += a.y*b.z; acc[1][3] += a.y*b.w;
            acc[2][0] += a.z*b.x; acc[2][1] += a.z*b.y; acc[2][2] += a.z*b.z; acc[2][3] += a.z*b.w;
            acc[3][0] += a.w*b.x; acc[3][1] += a.w*b.y; acc[3][2] += a.w*b.z; acc[3][3] += a.w*b.w;
        }
        __syncthreads();
    }
    #pragma unroll
    for (int i = 0; i < 4; i++) {
        int m = m0 + (ty << 2) + i;
        if (m >= M) continue;
        #pragma unroll
        for (int j = 0; j < 4; j++) {
            int n = n0 + (tx << 2) + j;
            if (n >= N) continue;
            float v = acc[i][j];
            if (bias) v += bias[n];
            C[(long)m * N + n] = v;
        }
    }
}

// ---------------------------------------------------------------------------
// HMMA flash-style attention, 13 warps (416 threads), one warp per 16-query
// strip, single round. ns = number of strips to compute (13 normal, 1 for
// the last layer where only the cls query is consumed).
// ---------------------------------------------------------------------------
#define SEQP    208
#define KPITCH  72
#define VPITCH  216
#define PPITCH  216
#define ATTN_T  416
#define ATTN_SMEM ((SEQP*KPITCH + 64*VPITCH + 13*16*PPITCH) * 2)   // 147456

__global__ __launch_bounds__(ATTN_T, 1)
void attn_kernel(const __half* __restrict__ qkv, __half* __restrict__ out, int ns) {
    int b = blockIdx.x / NH, h = blockIdx.x % NH;
    int tid = threadIdx.x, lane = tid & 31, warp = tid >> 5;
    extern __shared__ __half sh[];
    __half* Ks = sh;
    __half* Vt = Ks + SEQP*KPITCH;
    __half* Pw = Vt + 64*VPITCH + warp*16*PPITCH;

    const __half* base = qkv + (size_t)b * NTOK * (3*DD) + h * DH;

    for (int idx = tid; idx < NTOK*8; idx += ATTN_T) {
        int j = idx >> 3, c = idx & 7;
        *(uint4*)&Ks[j*KPITCH + c*8] = *(const uint4*)&base[(size_t)j*(3*DD) + DD + c*8];
    }
    for (int idx = tid; idx < (SEQP-NTOK)*KPITCH; idx += ATTN_T) {
        Ks[(NTOK + idx/KPITCH)*KPITCH + (idx % KPITCH)] = __half(0.0f);
    }
    for (int idx = tid; idx < NTOK*64; idx += ATTN_T) {
        int j = idx >> 6, d = idx & 63;
        Vt[d*VPITCH + j] = base[(size_t)j*(3*DD) + 2*DD + d];
    }
    for (int idx = tid; idx < 64*(VPITCH-NTOK); idx += ATTN_T) {
        int d = idx / (VPITCH-NTOK), c = NTOK + idx % (VPITCH-NTOK);
        Vt[d*VPITCH + c] = __half(0.0f);
    }
    __syncthreads();

    const int s = warp;          // one strip per warp
    if (s >= ns) return;

    const uint32_t KsB = smem_u32(Ks);
    const uint32_t VtB = smem_u32(Vt);
    const uint32_t PwB = smem_u32(Pw);
    const int lr = lane >> 2, lc = lane & 3;
    const uint32_t browoff = ((lane & 7) + ((lane >> 4) << 3));
    const uint32_t bcol = ((lane >> 3) & 1) * 16;
    const uint32_t aoff = PwB + (uint32_t)(lane & 15) * (PPITCH*2) + (lane >> 4) * 16;

    const int m0 = s * 16;
    // ---- stage FULL Q strip (16 rows x 64 halves) into Pw ----
    #pragma unroll
    for (int t = 0; t < 4; t++) {
        int idx = lane + t*32;
        int r = idx >> 3, c = idx & 7;
        int q = m0 + r;
        uint4 v = make_uint4(0u,0u,0u,0u);
        if (q < NTOK) v = *(const uint4*)&base[(size_t)q*(3*DD) + c*8];
        *(uint4*)&Pw[r*PPITCH + c*8] = v;
    }
    __syncwarp();
    uint32_t af[4][4];
    #pragma unroll
    for (int kc = 0; kc < 4; kc++)
        LDSM_X4(af[kc][0], af[kc][1], af[kc][2], af[kc][3], aoff + kc*32);

    float acc[26][4];
    #pragma unroll
    for (int nt = 0; nt < 26; nt++) {
        acc[nt][0]=0.f; acc[nt][1]=0.f; acc[nt][2]=0.f; acc[nt][3]=0.f;
    }
    #pragma unroll
    for (int kc = 0; kc < 4; kc++) {
        #pragma unroll
        for (int g = 0; g < 13; g++) {
            uint32_t b0,b1,b2,b3;
            LDSM_X4(b0,b1,b2,b3,
                    KsB + (g*16 + browoff)*(KPITCH*2) + bcol + kc*32);
            HMMA16816(acc[2*g  ], af[kc][0],af[kc][1],af[kc][2],af[kc][3], b0, b1);
            HMMA16816(acc[2*g+1], af[kc][0],af[kc][1],af[kc][2],af[kc][3], b2, b3);
        }
    }

    float mx1 = -1e30f, mx2 = -1e30f;
    #pragma unroll
    for (int nt = 0; nt < 26; nt++) {
        #pragma unroll
        for (int e = 0; e < 2; e++) {
            int col = nt*8 + lc*2 + e;
            bool ok = col < NTOK;
            float s1 = ok ? acc[nt][e]   * 0.125f : -1e30f;
            float s2 = ok ? acc[nt][2+e] * 0.125f : -1e30f;
            acc[nt][e] = s1; acc[nt][2+e] = s2;
            mx1 = fmaxf(mx1, s1); mx2 = fmaxf(mx2, s2);
        }
    }
    #pragma unroll
    for (int o = 1; o <= 2; o <<= 1) {
        mx1 = fmaxf(mx1, __shfl_xor_sync(0xffffffffu, mx1, o));
        mx2 = fmaxf(mx2, __shfl_xor_sync(0xffffffffu, mx2, o));
    }
    float sum1 = 0.f, sum2 = 0.f;
    #pragma unroll
    for (int nt = 0; nt < 26; nt++) {
        #pragma unroll
        for (int e = 0; e < 2; e++) {
            float p1 = expf(acc[nt][e]   - mx1);
            float p2 = expf(acc[nt][2+e] - mx2);
            acc[nt][e] = p1; acc[nt][2+e] = p2;
            sum1 += p1; sum2 += p2;
        }
    }
    #pragma unroll
    for (int o = 1; o <= 2; o <<= 1) {
        sum1 += __shfl_xor_sync(0xffffffffu, sum1, o);
        sum2 += __shfl_xor_sync(0xffffffffu, sum2, o);
    }
    #pragma unroll
    for (int nt = 0; nt < 26; nt++) {
        int col = nt*8 + lc*2;
        __half2 p1 = __floats2half2_rn(acc[nt][0], acc[nt][1]);
        __half2 p2 = __floats2half2_rn(acc[nt][2], acc[nt][3]);
        *(__half2*)&Pw[ lr   *PPITCH + col] = p1;
        *(__half2*)&Pw[(lr+8)*PPITCH + col] = p2;
    }
    __syncwarp();

    float oacc[8][4];
    #pragma unroll
    for (int nt = 0; nt < 8; nt++) {
        oacc[nt][0]=0.f; oacc[nt][1]=0.f; oacc[nt][2]=0.f; oacc[nt][3]=0.f;
    }
    for (int kt = 0; kt < 13; kt++) {
        uint32_t pa0,pa1,pa2,pa3;
        LDSM_X4(pa0,pa1,pa2,pa3, aoff + kt*32);
        #pragma unroll
        for (int g = 0; g < 4; g++) {
            uint32_t b0,b1,b2,b3;
            LDSM_X4(b0,b1,b2,b3,
                    VtB + (g*16 + browoff)*(VPITCH*2) + bcol + kt*32);
            HMMA16816(oacc[2*g  ], pa0,pa1,pa2,pa3, b0, b1);
            HMMA16816(oacc[2*g+1], pa0,pa1,pa2,pa3, b2, b3);
        }
    }

    float inv1 = 1.0f / sum1, inv2 = 1.0f / sum2;
    int q1 = m0 + lr, q2 = m0 + lr + 8;
    #pragma unroll
    for (int nt = 0; nt < 8; nt++) {
        int col = nt*8 + lc*2;
        if (q1 < NTOK) {
            __half2 hv = __floats2half2_rn(oacc[nt][0]*inv1, oacc[nt][1]*inv1);
            *(__half2*)&out[((size_t)b*NTOK + q1)*DD + h*DH + col] = hv;
        }
        if (q2 < NTOK) {
            __half2 hv = __floats2half2_rn(oacc[nt][2]*inv2, oacc[nt][3]*inv2);
            *(__half2*)&out[((size_t)b*NTOK + q2)*DD + h*DH + col] = hv;
        }
    }
}

// ---------------------------------------------------------------------------
// host orchestration
// ---------------------------------------------------------------------------
extern "C" void kernel_launch(void* const* d_in, const int* in_sizes, int n_in,
                              void* d_out, int out_size) {
    const float* x_in    = (const float*)d_in[0];
    const float* conv_w  = (const float*)d_in[1];
    const float* cls_tok = (const float*)d_in[2];
    const float* pos     = (const float*)d_in[3];
    const float* lnprew  = (const float*)d_in[4];
    const float* lnpreb  = (const float*)d_in[5];
    const float* ln1w    = (const float*)d_in[6];
    const float* ln1b    = (const float*)d_in[7];
    const float* qkvw    = (const float*)d_in[8];
    const float* qkvb    = (const float*)d_in[9];
    const float* pw      = (const float*)d_in[10];
    const float* pb      = (const float*)d_in[11];
    const float* ln2w    = (const float*)d_in[12];
    const float* ln2b    = (const float*)d_in[13];
    const float* fw      = (const float*)d_in[14];
    const float* fb      = (const float*)d_in[15];
    const float* cw      = (const float*)d_in[16];
    const float* cb      = (const float*)d_in[17];
    const float* lnpostw = (const float*)d_in[18];
    const float* lnpostb = (const float*)d_in[19];
    const float* projw   = (const float*)d_in[20];
    const float* headw   = (const float*)d_in[21];
    const float* headb   = (const float*)d_in[22];

    float  *gx, *gpe, *gc, *gcr, *gcx2, *gcx3, *gz;
    __half *gq, *gh, *go, *gm, *gp, *gca;
    __half *wconv, *wqkv, *wproj, *wfc, *wcpr;
    cudaGetSymbolAddress((void**)&gx,   g_x);
    cudaGetSymbolAddress((void**)&gpe,  g_pe);
    cudaGetSymbolAddress((void**)&gc,   g_cls);
    cudaGetSymbolAddress((void**)&gcr,  g_cr);
    cudaGetSymbolAddress((void**)&gcx2, g_cx2);
    cudaGetSymbolAddress((void**)&gcx3, g_cx3);
    cudaGetSymbolAddress((void**)&gz,   g_z);
    cudaGetSymbolAddress((void**)&gq,   g_qkv);
    cudaGetSymbolAddress((void**)&gh,   g_h);
    cudaGetSymbolAddress((void**)&go,   g_o);
    cudaGetSymbolAddress((void**)&gm,   g_mlp);
    cudaGetSymbolAddress((void**)&gp,   g_pat);
    cudaGetSymbolAddress((void**)&gca,  g_ca);
    cudaGetSymbolAddress((void**)&wconv, g_wconv);
    cudaGetSymbolAddress((void**)&wqkv,  g_wqkv);
    cudaGetSymbolAddress((void**)&wproj, g_wproj);
    cudaGetSymbolAddress((void**)&wfc,   g_wfc);
    cudaGetSymbolAddress((void**)&wcpr,  g_wcpr);

    cudaFuncSetAttribute(attn_kernel, cudaFuncAttributeMaxDynamicSharedMemorySize, ATTN_SMEM);
    cudaFuncSetAttribute(gemm_h<float ,false,false>, cudaFuncAttributeMaxDynamicSharedMemorySize, GH_SMEM);
    cudaFuncSetAttribute(gemm_h<float ,false,true >, cudaFuncAttributeMaxDynamicSharedMemorySize, GH_SMEM);
    cudaFuncSetAttribute(gemm_h<__half,true ,false>, cudaFuncAttributeMaxDynamicSharedMemorySize, GH_SMEM);
    cudaFuncSetAttribute(gemm_h<__half,false,false>, cudaFuncAttributeMaxDynamicSharedMemorySize, GH_SMEM);

    // ---- weight conversion (single launch) ----
    f2h_all_kernel<<<(F2H_C4 + 255)/256, 256>>>(conv_w, wconv, qkvw, wqkv,
                                                pw, wproj, fw, wfc, cw, wcpr);

    const int GY  = MROWS/128 + 1;   // 50 (last block = 32-row tail)
    const int GYP = PROWS/128 + 1;   // 50 (last block = empty tail)

    // ---- patch embed ----
    im2col_kernel<<<(PROWS*DD + 255)/256, 256>>>(x_in);
    gemm_h<float,false,false><<<dim3(DD/128, GYP), 256, GH_SMEM>>>(
        gp, wconv, nullptr, nullptr, gpe, PROWS, DD, DD);
    assemble_ln_kernel<<<MROWS, 256>>>(gpe, cls_tok, pos, lnprew, lnpreb, gx);

    // ---- layers 0..10: full ----
    for (int l = 0; l < DEPTH - 1; l++) {
        ln_warp<__half><<<MROWS/8, 256>>>(gx, gh, ln1w + l*DD, ln1b + l*DD, DD, DD);
        gemm_h<__half,false,false><<<dim3((3*DD)/128, GY), 256, GH_SMEM>>>(
            gh, wqkv + (size_t)l*3*DD*DD, qkvb + (long)l*3*DD, nullptr, gq, MROWS, 3*DD, DD);
        attn_kernel<<<BB*NH, ATTN_T, ATTN_SMEM>>>(gq, go, 13);
        gemm_h<float,false,true><<<dim3(DD/128, GY), 256, GH_SMEM>>>(
            go, wproj + (size_t)l*DD*DD, pb + (long)l*DD, gx, gx, MROWS, DD, DD);
        ln_warp<__half><<<MROWS/8, 256>>>(gx, gh, ln2w + l*DD, ln2b + l*DD, DD, DD);
        gemm_h<__half,true,false><<<dim3(MLPD/128, GY), 256, GH_SMEM>>>(
            gh, wfc + (size_t)l*MLPD*DD, fb + (long)l*MLPD, nullptr, gm, MROWS, MLPD, DD);
        gemm_h<float,false,true><<<dim3(DD/128, GY), 256, GH_SMEM>>>(
            gm, wcpr + (size_t)l*DD*MLPD, cb + (long)l*DD, gx, gx, MROWS, DD, MLPD);
    }

    // ---- layer 11 (last): full ln1/QKV, cls-only attention + MLP ----
    {
        const int l = DEPTH - 1;
        ln_warp<__half><<<MROWS/8, 256>>>(gx, gh, ln1w + l*DD, ln1b + l*DD, DD, DD);
        gemm_h<__half,false,false><<<dim3((3*DD)/128, GY), 256, GH_SMEM>>>(
            gh, wqkv + (size_t)l*3*DD*DD, qkvb + (long)l*3*DD, nullptr, gq, MROWS, 3*DD, DD);
        attn_kernel<<<BB*NH, ATTN_T, ATTN_SMEM>>>(gq, go, 1);   // only cls strip
        gather_cls_kernel<<<(BB*DD + 255)/256, 256>>>(go, gx, gca, gcr);
        gemm_h<float,false,true><<<dim3(DD/128, 1), 256, GH_SMEM>>>(
            gca, wproj + (size_t)l*DD*DD, pb + (long)l*DD, gcr, gcx2, BB, DD, DD);
        ln_warp<__half><<<BB/8, 256>>>(gcx2, gca, ln2w + l*DD, ln2b + l*DD, DD, DD);
        gemm_h<__half,true,false><<<dim3(MLPD/128, 1), 256, GH_SMEM>>>(
            gca, wfc + (size_t)l*MLPD*DD, fb + (long)l*MLPD, nullptr, gm, BB, MLPD, DD);
        gemm_h<float,false,true><<<dim3(DD/128, 1), 256, GH_SMEM>>>(
            gm, wcpr + (size_t)l*DD*MLPD, cb + (long)l*DD, gcx2, gcx3, BB, DD, MLPD);
    }

    // ---- head ----
    ln_warp<float><<<BB/8, 256>>>(gcx3, gc, lnpostw, lnpostb, DD, DD);
    gemm_nt<<<dim3(PROJD/64, 1), 256>>>(gc, projw, nullptr, gz, BB, PROJD, DD);
    gemm_nt<<<dim3((NCLS+63)/64, 1), 256>>>(gz, headw, headb, (float*)d_out, BB, NCLS, PROJD);
}